// round 8
// baseline (speedup 1.0000x reference)
#include <cuda_runtime.h>
#include <cstdint>
#include <math.h>

// ---------------------------------------------------------------------------
// Problem constants
// ---------------------------------------------------------------------------
#define BATCH   8
#define SEQL    2048
#define D_IN    512
#define DMODEL  1024
#define NROW    (BATCH * SEQL)          // 16384
#define LN_EPS  1e-5f
#define PERSIST_GRID 296                // 2 CTAs x 148 SMs

typedef unsigned short u16;
typedef uint32_t u32;

// element counts
static const long long C_IN  = (long long)NROW * D_IN;       // 8388608
static const long long C_EW  = (long long)DMODEL * D_IN;     // 524288
static const long long C_W   = (long long)DMODEL * DMODEL;   // 1048576
static const long long C_MAT = (long long)NROW * DMODEL;     // 16777216
static const long long C_SC  = (long long)BATCH * SEQL * SEQL; // 33554432

// scratch offsets (in floats; a split hi+lo pair of N elems occupies N floats)
#define O_INS   (0LL)
#define O_EWS   (O_INS  + C_IN)
#define O_WQS   (O_EWS  + C_EW)
#define O_WKS   (O_WQS  + C_W)
#define O_WVS   (O_WKS  + C_W)
#define O_SKWS  (O_WVS  + C_W)
#define O_X     (O_SKWS + C_W)
#define O_XS    (O_X    + C_MAT)
#define O_QS    (O_XS   + C_MAT)
#define O_KS    (O_QS   + C_MAT)
#define O_VTS   (O_KS   + C_MAT)
#define O_SC    (O_VTS  + C_MAT)
#define O_SCS   (O_SC   + C_SC)
#define O_Z     (O_SCS  + C_SC)
#define O_H     (O_Z    + C_MAT)
#define O_HS    (O_H    + C_MAT)
#define O_SK    (O_HS   + C_MAT)
#define O_T     (O_SK   + C_MAT)
#define O_TOTAL (O_T    + 16384)

__device__ float g_scratch[O_TOTAL];

// ---------------------------------------------------------------------------
// PTX helpers (baseline sm_80+ features only — harness targets plain sm_103)
// ---------------------------------------------------------------------------
__device__ __forceinline__ u32 smem_u32(const void* p) {
    u32 a;
    asm("{ .reg .u64 t; cvta.to.shared.u64 t, %1; cvt.u32.u64 %0, t; }"
        : "=r"(a) : "l"(p));
    return a;
}

__device__ __forceinline__ void cp_async16(u32 dst, const void* src) {
    asm volatile("cp.async.cg.shared.global [%0], [%1], 16;" :: "r"(dst), "l"(src));
}
#define CP_COMMIT() asm volatile("cp.async.commit_group;" ::: "memory")
#define CP_WAIT1()  asm volatile("cp.async.wait_group 1;"  ::: "memory")

// split x0,x1 (fp32) into packed bf16x2 hi and lo parts: x = hi + lo
__device__ __forceinline__ void split_pack(float x0, float x1, u32& hi, u32& lo) {
    asm("cvt.rn.bf16x2.f32 %0, %1, %2;" : "=r"(hi) : "f"(x1), "f"(x0));
    const float h0 = __uint_as_float(hi << 16);
    const float h1 = __uint_as_float(hi & 0xFFFF0000u);
    const float l0 = x0 - h0;
    const float l1 = x1 - h1;
    asm("cvt.rn.bf16x2.f32 %0, %1, %2;" : "=r"(lo) : "f"(l1), "f"(l0));
}

// D += A*B  (m16n8k16 bf16, fp32 accum)
__device__ __forceinline__ void mma_bf16(float* d, const u32* a, const u32* b) {
    asm volatile(
        "mma.sync.aligned.m16n8k16.row.col.f32.bf16.bf16.f32 "
        "{%0,%1,%2,%3}, {%4,%5,%6,%7}, {%8,%9}, {%0,%1,%2,%3};"
        : "+f"(d[0]), "+f"(d[1]), "+f"(d[2]), "+f"(d[3])
        : "r"(a[0]), "r"(a[1]), "r"(a[2]), "r"(a[3]), "r"(b[0]), "r"(b[1]));
}

__device__ __forceinline__ void ldmat4(u32& r0, u32& r1, u32& r2, u32& r3, u32 addr) {
    asm volatile("ldmatrix.sync.aligned.m8n8.x4.shared.b16 {%0,%1,%2,%3}, [%4];"
                 : "=r"(r0), "=r"(r1), "=r"(r2), "=r"(r3) : "r"(addr));
}

// swizzled byte offset of (row, 16B-chunk ch) in a 128x32 bf16 plane (64B rows)
__device__ __forceinline__ u32 sw_off(u32 row, u32 ch) {
    return row * 64u + ((ch ^ ((row >> 1) & 3u)) << 4);
}

// ---------------------------------------------------------------------------
// Persistent bf16x3 split GEMM on pre-split hi/lo planes:
//   C[m,n] = alpha * sum_k A[m,k]*B[n,k]  (+bias +posenc)
// Grid = PERSIST_GRID CTAs; each loops over linear tile ids (GX*GY*GZ tiles)
// to eliminate wave quantization. Tile 128x128x32, 256 thr, 8 warps (2x4),
// warp tile 64x32. ldmatrix fragments, 3-buffer cp.async pipeline with ONE
// __syncthreads per k-chunk; cp.async for chunk c+2 issued BEFORE compute of
// chunk c (overlap LSU with MMA).
//   F32OUT:  write fp32 C
//   SPLITOUT: write bf16 hi/lo planes of C
//   TRANSOUT: (V only) split planes written transposed per batch:
//             out[b][n][s] with m = b*SEQL + s
// ---------------------------------------------------------------------------
#define PLANE_B  (128 * 64)             // 8192
#define STAGE_B  (4 * PLANE_B)          // 32768
#define DYN_SMEM_G (3 * STAGE_B)        // 98304

template <bool F32OUT, bool SPLITOUT, bool TRANSOUT>
__global__ __launch_bounds__(256, 2)
void tc_gemm(const u16* __restrict__ Ahi, const u16* __restrict__ Alo,
             const u16* __restrict__ Bhi, const u16* __restrict__ Blo,
             float* __restrict__ Cf, u16* __restrict__ Chi, u16* __restrict__ Clo,
             int N, int K, int GX, int GY, int GZ,
             long long sA, long long sB, long long sC,
             float alpha, const float* __restrict__ bias,
             const float* __restrict__ posenc)
{
    extern __shared__ char smem[];

    const int tid  = threadIdx.x;
    const int wid  = tid >> 5;
    const int lane = tid & 31;
    const int wm   = wid >> 2;       // 0..1 (M)
    const int wn   = wid & 3;        // 0..3 (N)
    const int g    = lane >> 2;      // groupID 0..7
    const int t    = lane & 3;       // threadID_in_group
    const int lrow = lane & 15;
    const int lch  = lane >> 4;

    const u32 smem_base = smem_u32(smem);
    const int NC = K >> 5;           // k-chunks of 32
    const int n_tiles = GX * GY * GZ;

    // per-thread loader geometry
    const u32 ld_row = (u32)(tid >> 2);        // 0..63 (+64 on second pass)
    const u32 ld_ch  = (u32)(tid & 3);

    for (int tile = blockIdx.x; tile < n_tiles; tile += gridDim.x) {
        const int bz = tile / (GX * GY);
        const int r  = tile - bz * (GX * GY);
        const int m0 = (r / GX) * 128;
        const int n0 = (r - (r / GX) * GX) * 128;

        const u16* Ah = Ahi + bz * sA;
        const u16* Al = Alo + bz * sA;
        const u16* Bh = Bhi + bz * sB;
        const u16* Bl = Blo + bz * sB;

        float acc[4][4][4];
#pragma unroll
        for (int mi = 0; mi < 4; mi++)
#pragma unroll
            for (int ni = 0; ni < 4; ni++)
#pragma unroll
                for (int c = 0; c < 4; c++) acc[mi][ni][c] = 0.0f;

        // protect smem reuse across tiles (some warps may still read old data)
        __syncthreads();

        // ---- stage loader: 4 planes (Ah, Al, Bh, Bl), each 128x32 bf16 ----
        auto issue_stage = [&](int c, int buf) {
            const int k0 = c * 32;
            const u32 st = smem_base + buf * STAGE_B;
            const u16* srcs[4] = { Ah, Al, Bh, Bl };
#pragma unroll
            for (int p = 0; p < 4; p++) {
                const u16* src = srcs[p];
                const int rbase = (p < 2) ? m0 : n0;
#pragma unroll
                for (int i = 0; i < 2; i++) {
                    const u32 row = ld_row + i * 64;
                    cp_async16(st + p * PLANE_B + sw_off(row, ld_ch),
                               src + (long long)(rbase + row) * K + k0 + ld_ch * 8);
                }
            }
            CP_COMMIT();
        };

        issue_stage(0, 0);
        issue_stage(1, 1);

        int buf = 0;          // buffer holding chunk c
        int nbuf = 2;         // buffer that issue_stage(c+2) writes
        for (int c = 0; c < NC; ++c) {
            CP_WAIT1();
            __syncthreads();

            // 3-buffer rotation: nbuf was last read at iter c-1; every warp
            // has passed this iter's barrier, so it is safe to overwrite.
            // Issue BEFORE compute so the copy overlaps this chunk's MMAs.
            if (c + 2 < NC) issue_stage(c + 2, nbuf);
            else            CP_COMMIT();   // keep group accounting uniform

            const u32 st = smem_base + buf * STAGE_B;

#pragma unroll
            for (int half = 0; half < 2; half++) {
                const u32 ch = (u32)(half * 2 + lch);

                // ---- B fragments: 2 x ldmatrix.x4 per plane -> all 4 ni ----
                u32 bh[4][2], bl[4][2];
#pragma unroll
                for (int nj = 0; nj < 2; nj++) {
                    const u32 rb = sw_off((u32)(wn * 32 + nj * 16 + lrow), ch);
                    u32 r0, r1, r2, r3;
                    ldmat4(r0, r1, r2, r3, st + 2 * PLANE_B + rb);
                    bh[2*nj][0] = r0; bh[2*nj+1][0] = r1;
                    bh[2*nj][1] = r2; bh[2*nj+1][1] = r3;
                    ldmat4(r0, r1, r2, r3, st + 3 * PLANE_B + rb);
                    bl[2*nj][0] = r0; bl[2*nj+1][0] = r1;
                    bl[2*nj][1] = r2; bl[2*nj+1][1] = r3;
                }

                // ---- A fragments for an mi-pair, term-major MMA blocks ----
#pragma unroll
                for (int mp = 0; mp < 2; mp++) {
                    u32 ah[2][4], al[2][4];
#pragma unroll
                    for (int q = 0; q < 2; q++) {
                        const int mi = mp * 2 + q;
                        const u32 ra = sw_off((u32)(wm * 64 + mi * 16 + lrow), ch);
                        ldmat4(ah[q][0], ah[q][1], ah[q][2], ah[q][3], st + ra);
                        ldmat4(al[q][0], al[q][1], al[q][2], al[q][3], st + PLANE_B + ra);
                    }
                    // term 1: hi*hi — 8 independent MMAs
#pragma unroll
                    for (int q = 0; q < 2; q++)
#pragma unroll
                        for (int ni = 0; ni < 4; ni++)
                            mma_bf16(acc[mp*2+q][ni], ah[q], bh[ni]);
                    // term 2: hi*lo
#pragma unroll
                    for (int q = 0; q < 2; q++)
#pragma unroll
                        for (int ni = 0; ni < 4; ni++)
                            mma_bf16(acc[mp*2+q][ni], ah[q], bl[ni]);
                    // term 3: lo*hi
#pragma unroll
                    for (int q = 0; q < 2; q++)
#pragma unroll
                        for (int ni = 0; ni < 4; ni++)
                            mma_bf16(acc[mp*2+q][ni], al[q], bh[ni]);
                }
            }

            buf  = (buf  == 2) ? 0 : buf  + 1;
            nbuf = (nbuf == 2) ? 0 : nbuf + 1;
        }

        // ---- epilogue ----
        float* Cfp = F32OUT ? (Cf + bz * sC) : (float*)0;
#pragma unroll
        for (int mi = 0; mi < 4; mi++) {
            const int m_lo = m0 + wm * 64 + mi * 16 + g;
            const int m_hi = m_lo + 8;
            const float* pe_lo = posenc ? posenc + (long long)(m_lo & (SEQL - 1)) * N : 0;
            const float* pe_hi = posenc ? posenc + (long long)(m_hi & (SEQL - 1)) * N : 0;
#pragma unroll
            for (int ni = 0; ni < 4; ni++) {
                const int n = n0 + wn * 32 + ni * 8 + 2 * t;
                float2 v0, v1;
                v0.x = acc[mi][ni][0] * alpha;
                v0.y = acc[mi][ni][1] * alpha;
                v1.x = acc[mi][ni][2] * alpha;
                v1.y = acc[mi][ni][3] * alpha;
                if (bias) {
                    const float b0 = bias[n], b1 = bias[n + 1];
                    v0.x += b0; v0.y += b1;
                    v1.x += b0; v1.y += b1;
                }
                if (posenc) {
                    v0.x += pe_lo[n]; v0.y += pe_lo[n + 1];
                    v1.x += pe_hi[n]; v1.y += pe_hi[n + 1];
                }
                if (F32OUT) {
                    *(float2*)(Cfp + (long long)m_lo * N + n) = v0;
                    *(float2*)(Cfp + (long long)m_hi * N + n) = v1;
                }
                if (SPLITOUT) {
                    u32 h, l;
                    if (!TRANSOUT) {
                        split_pack(v0.x, v0.y, h, l);
                        *(u32*)(Chi + (long long)m_lo * N + n) = h;
                        *(u32*)(Clo + (long long)m_lo * N + n) = l;
                        split_pack(v1.x, v1.y, h, l);
                        *(u32*)(Chi + (long long)m_hi * N + n) = h;
                        *(u32*)(Clo + (long long)m_hi * N + n) = l;
                    } else {
                        // V^T: out[b][n][s], m = b*SEQL + s; DMODEL*SEQL = 1<<21
                        const long long base_lo =
                            ((long long)(m_lo >> 11) << 21) + (m_lo & 2047);
                        const long long base_hi =
                            ((long long)(m_hi >> 11) << 21) + (m_hi & 2047);
                        split_pack(v0.x, v0.y, h, l);
                        Chi[base_lo + (long long)n * SEQL]       = (u16)h;
                        Chi[base_lo + (long long)(n + 1) * SEQL] = (u16)(h >> 16);
                        Clo[base_lo + (long long)n * SEQL]       = (u16)l;
                        Clo[base_lo + (long long)(n + 1) * SEQL] = (u16)(l >> 16);
                        split_pack(v1.x, v1.y, h, l);
                        Chi[base_hi + (long long)n * SEQL]       = (u16)h;
                        Chi[base_hi + (long long)(n + 1) * SEQL] = (u16)(h >> 16);
                        Clo[base_hi + (long long)n * SEQL]       = (u16)l;
                        Clo[base_hi + (long long)(n + 1) * SEQL] = (u16)(l >> 16);
                    }
                }
            }
        }
    }
}

// ---------------------------------------------------------------------------
// fp32 -> split bf16 hi/lo planes (4 elems per thread)
// ---------------------------------------------------------------------------
__global__ void split_fp32(const float* __restrict__ src,
                           u16* __restrict__ hi, u16* __restrict__ lo, int n4)
{
    const int i = blockIdx.x * blockDim.x + threadIdx.x;
    if (i >= n4) return;
    const float4 v = ((const float4*)src)[i];
    u32 h01, l01, h23, l23;
    split_pack(v.x, v.y, h01, l01);
    split_pack(v.z, v.w, h23, l23);
    ((uint2*)hi)[i] = make_uint2(h01, h23);
    ((uint2*)lo)[i] = make_uint2(l01, l23);
}

// ---------------------------------------------------------------------------
// Row softmax (2048 cols) reading fp32, writing split bf16 planes.
// ---------------------------------------------------------------------------
__global__ void softmax_split(const float* __restrict__ S,
                              u16* __restrict__ hi, u16* __restrict__ lo)
{
    const long long off = (long long)blockIdx.x * 2048;
    const float* row = S + off;
    const int tid = threadIdx.x;
    __shared__ float red[256];

    float v[8];
    *(float4*)&v[0] = *(const float4*)(row + tid * 8);
    *(float4*)&v[4] = *(const float4*)(row + tid * 8 + 4);

    float mx = -1e30f;
#pragma unroll
    for (int i = 0; i < 8; i++) mx = fmaxf(mx, v[i]);
    red[tid] = mx; __syncthreads();
    for (int s = 128; s > 0; s >>= 1) {
        if (tid < s) red[tid] = fmaxf(red[tid], red[tid + s]);
        __syncthreads();
    }
    mx = red[0]; __syncthreads();

    float sum = 0.0f;
#pragma unroll
    for (int i = 0; i < 8; i++) { v[i] = __expf(v[i] - mx); sum += v[i]; }
    red[tid] = sum; __syncthreads();
    for (int s = 128; s > 0; s >>= 1) {
        if (tid < s) red[tid] += red[tid + s];
        __syncthreads();
    }
    const float inv = 1.0f / red[0];

    u32* hp = (u32*)hi + (off >> 1) + tid * 4;
    u32* lp = (u32*)lo + (off >> 1) + tid * 4;
#pragma unroll
    for (int j = 0; j < 4; j++) {
        u32 h, l;
        split_pack(v[2*j] * inv, v[2*j+1] * inv, h, l);
        hp[j] = h; lp[j] = l;
    }
}

// ---------------------------------------------------------------------------
// Plain fp32 row softmax (for the length-2048 pooling weights, 8 rows)
// ---------------------------------------------------------------------------
__global__ void softmax_rows(float* __restrict__ S)
{
    float* row = S + (long long)blockIdx.x * 2048;
    const int tid = threadIdx.x;
    __shared__ float red[256];

    float v[8];
    *(float4*)&v[0] = *(const float4*)(row + tid * 8);
    *(float4*)&v[4] = *(const float4*)(row + tid * 8 + 4);

    float mx = -1e30f;
#pragma unroll
    for (int i = 0; i < 8; i++) mx = fmaxf(mx, v[i]);
    red[tid] = mx; __syncthreads();
    for (int s = 128; s > 0; s >>= 1) {
        if (tid < s) red[tid] = fmaxf(red[tid], red[tid + s]);
        __syncthreads();
    }
    mx = red[0]; __syncthreads();

    float sum = 0.0f;
#pragma unroll
    for (int i = 0; i < 8; i++) { v[i] = __expf(v[i] - mx); sum += v[i]; }
    red[tid] = sum; __syncthreads();
    for (int s = 128; s > 0; s >>= 1) {
        if (tid < s) red[tid] += red[tid + s];
        __syncthreads();
    }
    const float inv = 1.0f / red[0];
#pragma unroll
    for (int i = 0; i < 8; i++) v[i] *= inv;
    *(float4*)(row + tid * 8)     = *(float4*)&v[0];
    *(float4*)(row + tid * 8 + 4) = *(float4*)&v[4];
}

// ---------------------------------------------------------------------------
// h = x + z ; H = LN(h)*g + b  -> fp32 H + split planes
// ---------------------------------------------------------------------------
__global__ void add_ln_split(const float* __restrict__ X, const float* __restrict__ Z,
                             const float* __restrict__ g, const float* __restrict__ b,
                             float* __restrict__ H, u16* __restrict__ hi, u16* __restrict__ lo)
{
    const long long r = blockIdx.x;
    const int tid = threadIdx.x;
    const int c0  = tid * 4;
    const float* xr = X + r * DMODEL;
    const float* zr = Z + r * DMODEL;
    __shared__ float red[256];

    float4 x4 = *(const float4*)(xr + c0);
    float4 z4 = *(const float4*)(zr + c0);
    float h[4] = { x4.x + z4.x, x4.y + z4.y, x4.z + z4.z, x4.w + z4.w };

    float sum = h[0] + h[1] + h[2] + h[3];
    red[tid] = sum; __syncthreads();
    for (int s = 128; s > 0; s >>= 1) {
        if (tid < s) red[tid] += red[tid + s];
        __syncthreads();
    }
    const float mean = red[0] * (1.0f / DMODEL);
    __syncthreads();

    float vs = 0.0f;
#pragma unroll
    for (int i = 0; i < 4; i++) { const float d = h[i] - mean; vs += d * d; }
    red[tid] = vs; __syncthreads();
    for (int s = 128; s > 0; s >>= 1) {
        if (tid < s) red[tid] += red[tid + s];
        __syncthreads();
    }
    const float inv = rsqrtf(red[0] * (1.0f / DMODEL) + LN_EPS);

    float4 o;
    o.x = (h[0] - mean) * inv * g[c0 + 0] + b[c0 + 0];
    o.y = (h[1] - mean) * inv * g[c0 + 1] + b[c0 + 1];
    o.z = (h[2] - mean) * inv * g[c0 + 2] + b[c0 + 2];
    o.w = (h[3] - mean) * inv * g[c0 + 3] + b[c0 + 3];
    *(float4*)(H + r * DMODEL + c0) = o;

    u32 h01, l01, h23, l23;
    split_pack(o.x, o.y, h01, l01);
    split_pack(o.z, o.w, h23, l23);
    const long long pi = (r * DMODEL + c0) >> 1;
    ((u32*)hi)[pi]     = h01;
    ((u32*)hi)[pi + 1] = h23;
    ((u32*)lo)[pi]     = l01;
    ((u32*)lo)[pi + 1] = l23;
}

// ---------------------------------------------------------------------------
// t[r] = sum_o tanh(SK[r,o]) * q[o]
// ---------------------------------------------------------------------------
__global__ void softkey_reduce(const float* __restrict__ SK, const float* __restrict__ q,
                               float* __restrict__ t)
{
    const long long r = blockIdx.x;
    const int tid = threadIdx.x;
    __shared__ float red[256];

    float s = 0.0f;
#pragma unroll
    for (int i = 0; i < 4; i++) {
        const int c = tid + i * 256;
        s += tanhf(SK[r * DMODEL + c]) * q[c];
    }
    red[tid] = s; __syncthreads();
    for (int k = 128; k > 0; k >>= 1) {
        if (tid < k) red[tid] += red[tid + k];
        __syncthreads();
    }
    if (tid == 0) t[r] = red[0];
}

// ---------------------------------------------------------------------------
// out[b,o] = sum_s w[b,s] * H[b,s,o]
// ---------------------------------------------------------------------------
__global__ void final_out(const float* __restrict__ H, const float* __restrict__ w,
                          float* __restrict__ out)
{
    const int b = blockIdx.y;
    const int o = blockIdx.x * 256 + threadIdx.x;
    const float* Hb = H + (long long)b * SEQL * DMODEL;
    const float* wb = w + (long long)b * SEQL;

    float a0 = 0.0f, a1 = 0.0f, a2 = 0.0f, a3 = 0.0f;
    for (int s = 0; s < SEQL; s += 4) {
        a0 += wb[s + 0] * Hb[(long long)(s + 0) * DMODEL + o];
        a1 += wb[s + 1] * Hb[(long long)(s + 1) * DMODEL + o];
        a2 += wb[s + 2] * Hb[(long long)(s + 2) * DMODEL + o];
        a3 += wb[s + 3] * Hb[(long long)(s + 3) * DMODEL + o];
    }
    out[b * DMODEL + o] = (a0 + a1) + (a2 + a3);
}

// ---------------------------------------------------------------------------
// Launch
// ---------------------------------------------------------------------------
extern "C" void kernel_launch(void* const* d_in, const int* in_sizes, int n_in,
                              void* d_out, int out_size)
{
    const float* inputs  = (const float*)d_in[0];
    const float* embed_w = (const float*)d_in[1];
    const float* embed_b = (const float*)d_in[2];
    const float* wq_w    = (const float*)d_in[3];
    const float* wq_b    = (const float*)d_in[4];
    const float* wk_w    = (const float*)d_in[5];
    const float* wk_b    = (const float*)d_in[6];
    const float* wv_w    = (const float*)d_in[7];
    const float* wv_b    = (const float*)d_in[8];
    const float* ln_g    = (const float*)d_in[9];
    const float* ln_b    = (const float*)d_in[10];
    const float* skw     = (const float*)d_in[11];
    const float* sq      = (const float*)d_in[12];
    const float* pos     = (const float*)d_in[13];
    float* out = (float*)d_out;

    cudaFuncSetAttribute((const void*)tc_gemm<true,  true,  false>,
                         cudaFuncAttributeMaxDynamicSharedMemorySize, DYN_SMEM_G);
    cudaFuncSetAttribute((const void*)tc_gemm<false, true,  false>,
                         cudaFuncAttributeMaxDynamicSharedMemorySize, DYN_SMEM_G);
    cudaFuncSetAttribute((const void*)tc_gemm<false, true,  true>,
                         cudaFuncAttributeMaxDynamicSharedMemorySize, DYN_SMEM_G);
    cudaFuncSetAttribute((const void*)tc_gemm<true,  false, false>,
                         cudaFuncAttributeMaxDynamicSharedMemorySize, DYN_SMEM_G);

    float* base = 0;
    cudaGetSymbolAddress((void**)&base, g_scratch);

    u16* INh  = (u16*)(base + O_INS);   u16* INl  = INh  + C_IN;
    u16* EWh  = (u16*)(base + O_EWS);   u16* EWl  = EWh  + C_EW;
    u16* WQh  = (u16*)(base + O_WQS);   u16* WQl  = WQh  + C_W;
    u16* WKh  = (u16*)(base + O_WKS);   u16* WKl  = WKh  + C_W;
    u16* WVh  = (u16*)(base + O_WVS);   u16* WVl  = WVh  + C_W;
    u16* SKWh = (u16*)(base + O_SKWS);  u16* SKWl = SKWh + C_W;
    float* X  = base + O_X;
    u16* Xh   = (u16*)(base + O_XS);    u16* Xl   = Xh   + C_MAT;
    u16* Qh   = (u16*)(base + O_QS);    u16* Ql   = Qh   + C_MAT;
    u16* Kh   = (u16*)(base + O_KS);    u16* Kl   = Kh   + C_MAT;
    u16* VTh  = (u16*)(base + O_VTS);   u16* VTl  = VTh  + C_MAT;
    float* SC = base + O_SC;
    u16* SCh  = (u16*)(base + O_SCS);   u16* SCl  = SCh  + C_SC;
    float* Z  = base + O_Z;
    float* H  = base + O_H;
    u16* Hh   = (u16*)(base + O_HS);    u16* Hl   = Hh   + C_MAT;
    float* SK = base + O_SK;
    float* T  = base + O_T;

    // 0) one-time splits of raw inputs & weights
    split_fp32<<<(int)(C_IN / 4 / 256), 256>>>(inputs,  INh,  INl,  (int)(C_IN / 4));
    split_fp32<<<(int)(C_EW / 4 / 256), 256>>>(embed_w, EWh,  EWl,  (int)(C_EW / 4));
    split_fp32<<<(int)(C_W  / 4 / 256), 256>>>(wq_w,    WQh,  WQl,  (int)(C_W  / 4));
    split_fp32<<<(int)(C_W  / 4 / 256), 256>>>(wk_w,    WKh,  WKl,  (int)(C_W  / 4));
    split_fp32<<<(int)(C_W  / 4 / 256), 256>>>(wv_w,    WVh,  WVl,  (int)(C_W  / 4));
    split_fp32<<<(int)(C_W  / 4 / 256), 256>>>(skw,     SKWh, SKWl, (int)(C_W  / 4));

    // 1) embed: X = inputs @ embed_w^T + embed_b + pos_enc  (fp32 + split out)
    tc_gemm<true, true, false><<<PERSIST_GRID, 256, DYN_SMEM_G>>>(
        INh, INl, EWh, EWl, X, Xh, Xl,
        DMODEL, D_IN, DMODEL / 128, NROW / 128, 1, 0, 0, 0, 1.0f, embed_b, pos);

    // 2) Q, K (split out), V (transposed split out)
    tc_gemm<false, true, false><<<PERSIST_GRID, 256, DYN_SMEM_G>>>(
        Xh, Xl, WQh, WQl, 0, Qh, Ql,
        DMODEL, DMODEL, DMODEL / 128, NROW / 128, 1, 0, 0, 0, 1.0f, wq_b, 0);
    tc_gemm<false, true, false><<<PERSIST_GRID, 256, DYN_SMEM_G>>>(
        Xh, Xl, WKh, WKl, 0, Kh, Kl,
        DMODEL, DMODEL, DMODEL / 128, NROW / 128, 1, 0, 0, 0, 1.0f, wk_b, 0);
    tc_gemm<false, true, true><<<PERSIST_GRID, 256, DYN_SMEM_G>>>(
        Xh, Xl, WVh, WVl, 0, VTh, VTl,
        DMODEL, DMODEL, DMODEL / 128, NROW / 128, 1, 0, 0, 0, 1.0f, wv_b, 0);

    // 3) scores = Q @ K^T / 32 (batched, fp32 out)
    tc_gemm<true, false, false><<<PERSIST_GRID, 256, DYN_SMEM_G>>>(
        Qh, Ql, Kh, Kl, SC, 0, 0,
        SEQL, DMODEL, SEQL / 128, SEQL / 128, BATCH,
        (long long)SEQL * DMODEL, (long long)SEQL * DMODEL, (long long)SEQL * SEQL,
        1.0f / 32.0f, 0, 0);

    // 4) softmax -> split planes
    softmax_split<<<NROW, 256>>>(SC, SCh, SCl);

    // 5) Z = softmax(SC) @ V  (B = V^T planes, [n][k] per batch)
    tc_gemm<true, false, false><<<PERSIST_GRID, 256, DYN_SMEM_G>>>(
        SCh, SCl, VTh, VTl, Z, 0, 0,
        DMODEL, SEQL, DMODEL / 128, SEQL / 128, BATCH,
        (long long)SEQL * SEQL, (long long)DMODEL * SEQL, (long long)SEQL * DMODEL,
        1.0f, 0, 0);

    // 6) H = LN(X + Z)*g + b  (fp32 + split)
    add_ln_split<<<NROW, 256>>>(X, Z, ln_g, ln_b, H, Hh, Hl);

    // 7) SK = H @ soft_key_w^T (fp32 out)
    tc_gemm<true, false, false><<<PERSIST_GRID, 256, DYN_SMEM_G>>>(
        Hh, Hl, SKWh, SKWl, SK, 0, 0,
        DMODEL, DMODEL, DMODEL / 128, NROW / 128, 1, 0, 0, 0, 1.0f, 0, 0);

    // 8) t[b,s] = sum_o tanh(SK)*soft_query[o]; softmax over s per batch
    softkey_reduce<<<NROW, 256>>>(SK, sq, T);
    softmax_rows<<<BATCH, 256>>>(T);

    // 9) out[b,o] = sum_s w[b,s] * H[b,s,o]
    final_out<<<dim3(DMODEL / 256, BATCH), 256>>>(H, T, out);
}

// round 9
// speedup vs baseline: 1.0728x; 1.0728x over previous
#include <cuda_runtime.h>
#include <cstdint>
#include <math.h>

// ---------------------------------------------------------------------------
// Problem constants
// ---------------------------------------------------------------------------
#define BATCH   8
#define SEQL    2048
#define D_IN    512
#define DMODEL  1024
#define NROW    (BATCH * SEQL)          // 16384
#define LN_EPS  1e-5f

typedef unsigned short u16;
typedef uint32_t u32;

// element counts
static const long long C_IN  = (long long)NROW * D_IN;       // 8388608
static const long long C_EW  = (long long)DMODEL * D_IN;     // 524288
static const long long C_W   = (long long)DMODEL * DMODEL;   // 1048576
static const long long C_MAT = (long long)NROW * DMODEL;     // 16777216
static const long long C_SC  = (long long)BATCH * SEQL * SEQL; // 33554432

// scratch offsets (in floats; a split hi+lo pair of N elems occupies N floats)
// QKV weights stored as stacked planes: hi[3*C_W] then lo[3*C_W]
#define O_INS   (0LL)
#define O_EWS   (O_INS  + C_IN)
#define O_QKVW  (O_EWS  + C_EW)
#define O_SKWS  (O_QKVW + 3 * C_W)
#define O_X     (O_SKWS + C_W)
#define O_XS    (O_X    + C_MAT)
#define O_QS    (O_XS   + C_MAT)
#define O_KS    (O_QS   + C_MAT)
#define O_VTS   (O_KS   + C_MAT)
#define O_SC    (O_VTS  + C_MAT)
#define O_SCS   (O_SC   + C_SC)
#define O_Z     (O_SCS  + C_SC)
#define O_H     (O_Z    + C_MAT)
#define O_HS    (O_H    + C_MAT)
#define O_SK    (O_HS   + C_MAT)
#define O_T     (O_SK   + C_MAT)
#define O_TOTAL (O_T    + 16384)

__device__ float g_scratch[O_TOTAL];

// ---------------------------------------------------------------------------
// PTX helpers (baseline sm_80+ features only — harness targets plain sm_103)
// ---------------------------------------------------------------------------
__device__ __forceinline__ u32 smem_u32(const void* p) {
    u32 a;
    asm("{ .reg .u64 t; cvta.to.shared.u64 t, %1; cvt.u32.u64 %0, t; }"
        : "=r"(a) : "l"(p));
    return a;
}

__device__ __forceinline__ void cp_async16(u32 dst, const void* src) {
    asm volatile("cp.async.cg.shared.global [%0], [%1], 16;" :: "r"(dst), "l"(src));
}
#define CP_COMMIT() asm volatile("cp.async.commit_group;" ::: "memory")
#define CP_WAIT1()  asm volatile("cp.async.wait_group 1;"  ::: "memory")

// split x0,x1 (fp32) into packed bf16x2 hi and lo parts: x = hi + lo
__device__ __forceinline__ void split_pack(float x0, float x1, u32& hi, u32& lo) {
    asm("cvt.rn.bf16x2.f32 %0, %1, %2;" : "=r"(hi) : "f"(x1), "f"(x0));
    const float h0 = __uint_as_float(hi << 16);
    const float h1 = __uint_as_float(hi & 0xFFFF0000u);
    const float l0 = x0 - h0;
    const float l1 = x1 - h1;
    asm("cvt.rn.bf16x2.f32 %0, %1, %2;" : "=r"(lo) : "f"(l1), "f"(l0));
}

// D += A*B  (m16n8k16 bf16, fp32 accum)
__device__ __forceinline__ void mma_bf16(float* d, const u32* a, const u32* b) {
    asm volatile(
        "mma.sync.aligned.m16n8k16.row.col.f32.bf16.bf16.f32 "
        "{%0,%1,%2,%3}, {%4,%5,%6,%7}, {%8,%9}, {%0,%1,%2,%3};"
        : "+f"(d[0]), "+f"(d[1]), "+f"(d[2]), "+f"(d[3])
        : "r"(a[0]), "r"(a[1]), "r"(a[2]), "r"(a[3]), "r"(b[0]), "r"(b[1]));
}

__device__ __forceinline__ void ldmat4(u32& r0, u32& r1, u32& r2, u32& r3, u32 addr) {
    asm volatile("ldmatrix.sync.aligned.m8n8.x4.shared.b16 {%0,%1,%2,%3}, [%4];"
                 : "=r"(r0), "=r"(r1), "=r"(r2), "=r"(r3) : "r"(addr));
}

// swizzled byte offset of (row, 16B-chunk ch) in a 128x32 bf16 plane (64B rows)
__device__ __forceinline__ u32 sw_off(u32 row, u32 ch) {
    return row * 64u + ((ch ^ ((row >> 1) & 3u)) << 4);
}

// outputs for the merged QKV GEMM
struct QKVOut {
    u16 *qh, *ql, *kh, *kl, *vh, *vl;
    const float *bq, *bk, *bv;
};

// ---------------------------------------------------------------------------
// bf16x3 split GEMM on pre-split hi/lo planes:
//   C[m,n] = alpha * sum_k A[m,k]*B[n,k]  (+bias +posenc)
// A planes [M][K] bf16, B planes [N][K] bf16. Tile 128x128x32, 256 thr,
// 8 warps (2x4), warp tile 64x32. ldmatrix fragments.
// 3-buffer cp.async pipeline, ONE __syncthreads per k-chunk; stage c+2 is
// issued BEFORE the compute of chunk c so the copy overlaps the MMA block.
//   F32OUT:  write fp32 C
//   SPLITOUT: write bf16 hi/lo planes of C
//   QKV:     merged Q/K/V epilogue (N=3072): bucket n>>10 selects
//            Q split / K split / V transposed split + per-bucket bias
// ---------------------------------------------------------------------------
#define PLANE_B  (128 * 64)             // 8192
#define STAGE_B  (4 * PLANE_B)          // 32768
#define DYN_SMEM_G (3 * STAGE_B)        // 98304

template <bool F32OUT, bool SPLITOUT, bool QKV>
__global__ __launch_bounds__(256, 2)
void tc_gemm(const u16* __restrict__ Ahi, const u16* __restrict__ Alo,
             const u16* __restrict__ Bhi, const u16* __restrict__ Blo,
             float* __restrict__ Cf, u16* __restrict__ Chi, u16* __restrict__ Clo,
             QKVOut qkv,
             int N, int K,
             long long sA, long long sB, long long sC,
             float alpha, const float* __restrict__ bias,
             const float* __restrict__ posenc)
{
    extern __shared__ char smem[];

    const int tid  = threadIdx.x;
    const int wid  = tid >> 5;
    const int lane = tid & 31;
    const int wm   = wid >> 2;       // 0..1 (M)
    const int wn   = wid & 3;        // 0..3 (N)
    const int g    = lane >> 2;      // groupID 0..7
    const int t    = lane & 3;       // threadID_in_group
    const int lrow = lane & 15;
    const int lch  = lane >> 4;

    const int bz = blockIdx.z;
    Ahi += bz * sA; Alo += bz * sA;
    Bhi += bz * sB; Blo += bz * sB;
    if (F32OUT) Cf += bz * sC;
    const int m0 = blockIdx.y * 128;
    const int n0 = blockIdx.x * 128;

    const u32 smem_base = smem_u32(smem);

    float acc[4][4][4];
#pragma unroll
    for (int mi = 0; mi < 4; mi++)
#pragma unroll
        for (int ni = 0; ni < 4; ni++)
#pragma unroll
            for (int c = 0; c < 4; c++) acc[mi][ni][c] = 0.0f;

    const int NC = K >> 5;   // k-chunks of 32

    // per-thread loader geometry
    const u32 ld_row = (u32)(tid >> 2);        // 0..63 (+64 on second pass)
    const u32 ld_ch  = (u32)(tid & 3);

    // ---- async stage loader: 4 planes (Ahi, Alo, Bhi, Blo), each 128x32 bf16
    auto issue_stage = [&](int c, int buf) {
        const int k0 = c * 32;
        const u32 st = smem_base + buf * STAGE_B;
        const u16* srcs[4] = { Ahi, Alo, Bhi, Blo };
#pragma unroll
        for (int p = 0; p < 4; p++) {
            const u16* src = srcs[p];
            const int rbase = (p < 2) ? m0 : n0;
#pragma unroll
            for (int i = 0; i < 2; i++) {
                const u32 row = ld_row + i * 64;
                cp_async16(st + p * PLANE_B + sw_off(row, ld_ch),
                           src + (long long)(rbase + row) * K + k0 + ld_ch * 8);
            }
        }
        CP_COMMIT();
    };

    issue_stage(0, 0);
    issue_stage(1, 1);

    int buf = 0;          // buffer holding chunk c
    int nbuf = 2;         // buffer that issue_stage(c+2) writes
    for (int c = 0; c < NC; ++c) {
        CP_WAIT1();
        __syncthreads();

        // 3-buffer rotation: nbuf was last read at iter c-1; every warp has
        // passed this iter's barrier, so it is safe to overwrite. Issue
        // BEFORE compute so the copy overlaps this chunk's MMAs.
        if (c + 2 < NC) issue_stage(c + 2, nbuf);
        else            CP_COMMIT();   // keep group accounting uniform

        const u32 st = smem_base + buf * STAGE_B;

#pragma unroll
        for (int half = 0; half < 2; half++) {
            const u32 ch = (u32)(half * 2 + lch);

            // ---- B fragments: 2 x ldmatrix.x4 per plane cover all 4 ni ----
            u32 bh[4][2], bl[4][2];
#pragma unroll
            for (int nj = 0; nj < 2; nj++) {
                const u32 rb = sw_off((u32)(wn * 32 + nj * 16 + lrow), ch);
                u32 r0, r1, r2, r3;
                ldmat4(r0, r1, r2, r3, st + 2 * PLANE_B + rb);
                bh[2*nj][0] = r0; bh[2*nj+1][0] = r1;
                bh[2*nj][1] = r2; bh[2*nj+1][1] = r3;
                ldmat4(r0, r1, r2, r3, st + 3 * PLANE_B + rb);
                bl[2*nj][0] = r0; bl[2*nj+1][0] = r1;
                bl[2*nj][1] = r2; bl[2*nj+1][1] = r3;
            }

            // ---- A fragments for an mi-pair, then term-major MMA blocks ----
#pragma unroll
            for (int mp = 0; mp < 2; mp++) {
                u32 ah[2][4], al[2][4];
#pragma unroll
                for (int q = 0; q < 2; q++) {
                    const int mi = mp * 2 + q;
                    const u32 ra = sw_off((u32)(wm * 64 + mi * 16 + lrow), ch);
                    ldmat4(ah[q][0], ah[q][1], ah[q][2], ah[q][3], st + ra);
                    ldmat4(al[q][0], al[q][1], al[q][2], al[q][3], st + PLANE_B + ra);
                }
                // term 1: hi*hi — 8 independent MMAs
#pragma unroll
                for (int q = 0; q < 2; q++)
#pragma unroll
                    for (int ni = 0; ni < 4; ni++)
                        mma_bf16(acc[mp*2+q][ni], ah[q], bh[ni]);
                // term 2: hi*lo
#pragma unroll
                for (int q = 0; q < 2; q++)
#pragma unroll
                    for (int ni = 0; ni < 4; ni++)
                        mma_bf16(acc[mp*2+q][ni], ah[q], bl[ni]);
                // term 3: lo*hi
#pragma unroll
                for (int q = 0; q < 2; q++)
#pragma unroll
                    for (int ni = 0; ni < 4; ni++)
                        mma_bf16(acc[mp*2+q][ni], al[q], bh[ni]);
            }
        }

        buf  = (buf  == 2) ? 0 : buf  + 1;
        nbuf = (nbuf == 2) ? 0 : nbuf + 1;
    }

    // ---- epilogue ----
    const int bucket = QKV ? (n0 >> 10) : 0;   // tile lies in one 1024 block
#pragma unroll
    for (int mi = 0; mi < 4; mi++) {
        const int m_lo = m0 + wm * 64 + mi * 16 + g;
        const int m_hi = m_lo + 8;
        const float* pe_lo = posenc ? posenc + (long long)(m_lo & (SEQL - 1)) * N : 0;
        const float* pe_hi = posenc ? posenc + (long long)(m_hi & (SEQL - 1)) * N : 0;
#pragma unroll
        for (int ni = 0; ni < 4; ni++) {
            const int n = n0 + wn * 32 + ni * 8 + 2 * t;
            float2 v0, v1;
            v0.x = acc[mi][ni][0] * alpha;
            v0.y = acc[mi][ni][1] * alpha;
            v1.x = acc[mi][ni][2] * alpha;
            v1.y = acc[mi][ni][3] * alpha;

            if (QKV) {
                const int col = n & 1023;
                const float* bb = (bucket == 0) ? qkv.bq
                                : (bucket == 1) ? qkv.bk : qkv.bv;
                const float b0 = bb[col], b1 = bb[col + 1];
                v0.x += b0; v0.y += b1;
                v1.x += b0; v1.y += b1;
                u32 h, l;
                if (bucket < 2) {
                    u16* Dh = (bucket == 0) ? qkv.qh : qkv.kh;
                    u16* Dl = (bucket == 0) ? qkv.ql : qkv.kl;
                    split_pack(v0.x, v0.y, h, l);
                    *(u32*)(Dh + (long long)m_lo * DMODEL + col) = h;
                    *(u32*)(Dl + (long long)m_lo * DMODEL + col) = l;
                    split_pack(v1.x, v1.y, h, l);
                    *(u32*)(Dh + (long long)m_hi * DMODEL + col) = h;
                    *(u32*)(Dl + (long long)m_hi * DMODEL + col) = l;
                } else {
                    // V^T: out[b][col][s], m = b*SEQL + s; DMODEL*SEQL = 1<<21
                    const long long base_lo =
                        ((long long)(m_lo >> 11) << 21) + (m_lo & 2047);
                    const long long base_hi =
                        ((long long)(m_hi >> 11) << 21) + (m_hi & 2047);
                    split_pack(v0.x, v0.y, h, l);
                    qkv.vh[base_lo + (long long)col * SEQL]       = (u16)h;
                    qkv.vh[base_lo + (long long)(col + 1) * SEQL] = (u16)(h >> 16);
                    qkv.vl[base_lo + (long long)col * SEQL]       = (u16)l;
                    qkv.vl[base_lo + (long long)(col + 1) * SEQL] = (u16)(l >> 16);
                    split_pack(v1.x, v1.y, h, l);
                    qkv.vh[base_hi + (long long)col * SEQL]       = (u16)h;
                    qkv.vh[base_hi + (long long)(col + 1) * SEQL] = (u16)(h >> 16);
                    qkv.vl[base_hi + (long long)col * SEQL]       = (u16)l;
                    qkv.vl[base_hi + (long long)(col + 1) * SEQL] = (u16)(l >> 16);
                }
                continue;
            }

            if (bias) {
                const float b0 = bias[n], b1 = bias[n + 1];
                v0.x += b0; v0.y += b1;
                v1.x += b0; v1.y += b1;
            }
            if (posenc) {
                v0.x += pe_lo[n]; v0.y += pe_lo[n + 1];
                v1.x += pe_hi[n]; v1.y += pe_hi[n + 1];
            }
            if (F32OUT) {
                *(float2*)(Cf + (long long)m_lo * N + n) = v0;
                *(float2*)(Cf + (long long)m_hi * N + n) = v1;
            }
            if (SPLITOUT) {
                u32 h, l;
                split_pack(v0.x, v0.y, h, l);
                *(u32*)(Chi + (long long)m_lo * N + n) = h;
                *(u32*)(Clo + (long long)m_lo * N + n) = l;
                split_pack(v1.x, v1.y, h, l);
                *(u32*)(Chi + (long long)m_hi * N + n) = h;
                *(u32*)(Clo + (long long)m_hi * N + n) = l;
            }
        }
    }
}

// ---------------------------------------------------------------------------
// fp32 -> split bf16 hi/lo planes (4 elems per thread)
// ---------------------------------------------------------------------------
__global__ void split_fp32(const float* __restrict__ src,
                           u16* __restrict__ hi, u16* __restrict__ lo, int n4)
{
    const int i = blockIdx.x * blockDim.x + threadIdx.x;
    if (i >= n4) return;
    const float4 v = ((const float4*)src)[i];
    u32 h01, l01, h23, l23;
    split_pack(v.x, v.y, h01, l01);
    split_pack(v.z, v.w, h23, l23);
    ((uint2*)hi)[i] = make_uint2(h01, h23);
    ((uint2*)lo)[i] = make_uint2(l01, l23);
}

// ---------------------------------------------------------------------------
// Row softmax (2048 cols) reading fp32, writing split bf16 planes.
// ---------------------------------------------------------------------------
__global__ void softmax_split(const float* __restrict__ S,
                              u16* __restrict__ hi, u16* __restrict__ lo)
{
    const long long off = (long long)blockIdx.x * 2048;
    const float* row = S + off;
    const int tid = threadIdx.x;
    __shared__ float red[256];

    float v[8];
    *(float4*)&v[0] = *(const float4*)(row + tid * 8);
    *(float4*)&v[4] = *(const float4*)(row + tid * 8 + 4);

    float mx = -1e30f;
#pragma unroll
    for (int i = 0; i < 8; i++) mx = fmaxf(mx, v[i]);
    red[tid] = mx; __syncthreads();
    for (int s = 128; s > 0; s >>= 1) {
        if (tid < s) red[tid] = fmaxf(red[tid], red[tid + s]);
        __syncthreads();
    }
    mx = red[0]; __syncthreads();

    float sum = 0.0f;
#pragma unroll
    for (int i = 0; i < 8; i++) { v[i] = __expf(v[i] - mx); sum += v[i]; }
    red[tid] = sum; __syncthreads();
    for (int s = 128; s > 0; s >>= 1) {
        if (tid < s) red[tid] += red[tid + s];
        __syncthreads();
    }
    const float inv = 1.0f / red[0];

    u32* hp = (u32*)hi + (off >> 1) + tid * 4;
    u32* lp = (u32*)lo + (off >> 1) + tid * 4;
#pragma unroll
    for (int j = 0; j < 4; j++) {
        u32 h, l;
        split_pack(v[2*j] * inv, v[2*j+1] * inv, h, l);
        hp[j] = h; lp[j] = l;
    }
}

// ---------------------------------------------------------------------------
// Plain fp32 row softmax (for the length-2048 pooling weights, 8 rows)
// ---------------------------------------------------------------------------
__global__ void softmax_rows(float* __restrict__ S)
{
    float* row = S + (long long)blockIdx.x * 2048;
    const int tid = threadIdx.x;
    __shared__ float red[256];

    float v[8];
    *(float4*)&v[0] = *(const float4*)(row + tid * 8);
    *(float4*)&v[4] = *(const float4*)(row + tid * 8 + 4);

    float mx = -1e30f;
#pragma unroll
    for (int i = 0; i < 8; i++) mx = fmaxf(mx, v[i]);
    red[tid] = mx; __syncthreads();
    for (int s = 128; s > 0; s >>= 1) {
        if (tid < s) red[tid] = fmaxf(red[tid], red[tid + s]);
        __syncthreads();
    }
    mx = red[0]; __syncthreads();

    float sum = 0.0f;
#pragma unroll
    for (int i = 0; i < 8; i++) { v[i] = __expf(v[i] - mx); sum += v[i]; }
    red[tid] = sum; __syncthreads();
    for (int s = 128; s > 0; s >>= 1) {
        if (tid < s) red[tid] += red[tid + s];
        __syncthreads();
    }
    const float inv = 1.0f / red[0];
#pragma unroll
    for (int i = 0; i < 8; i++) v[i] *= inv;
    *(float4*)(row + tid * 8)     = *(float4*)&v[0];
    *(float4*)(row + tid * 8 + 4) = *(float4*)&v[4];
}

// ---------------------------------------------------------------------------
// h = x + z ; H = LN(h)*g + b  -> fp32 H + split planes
// ---------------------------------------------------------------------------
__global__ void add_ln_split(const float* __restrict__ X, const float* __restrict__ Z,
                             const float* __restrict__ g, const float* __restrict__ b,
                             float* __restrict__ H, u16* __restrict__ hi, u16* __restrict__ lo)
{
    const long long r = blockIdx.x;
    const int tid = threadIdx.x;
    const int c0  = tid * 4;
    const float* xr = X + r * DMODEL;
    const float* zr = Z + r * DMODEL;
    __shared__ float red[256];

    float4 x4 = *(const float4*)(xr + c0);
    float4 z4 = *(const float4*)(zr + c0);
    float h[4] = { x4.x + z4.x, x4.y + z4.y, x4.z + z4.z, x4.w + z4.w };

    float sum = h[0] + h[1] + h[2] + h[3];
    red[tid] = sum; __syncthreads();
    for (int s = 128; s > 0; s >>= 1) {
        if (tid < s) red[tid] += red[tid + s];
        __syncthreads();
    }
    const float mean = red[0] * (1.0f / DMODEL);
    __syncthreads();

    float vs = 0.0f;
#pragma unroll
    for (int i = 0; i < 4; i++) { const float d = h[i] - mean; vs += d * d; }
    red[tid] = vs; __syncthreads();
    for (int s = 128; s > 0; s >>= 1) {
        if (tid < s) red[tid] += red[tid + s];
        __syncthreads();
    }
    const float inv = rsqrtf(red[0] * (1.0f / DMODEL) + LN_EPS);

    float4 o;
    o.x = (h[0] - mean) * inv * g[c0 + 0] + b[c0 + 0];
    o.y = (h[1] - mean) * inv * g[c0 + 1] + b[c0 + 1];
    o.z = (h[2] - mean) * inv * g[c0 + 2] + b[c0 + 2];
    o.w = (h[3] - mean) * inv * g[c0 + 3] + b[c0 + 3];
    *(float4*)(H + r * DMODEL + c0) = o;

    u32 h01, l01, h23, l23;
    split_pack(o.x, o.y, h01, l01);
    split_pack(o.z, o.w, h23, l23);
    const long long pi = (r * DMODEL + c0) >> 1;
    ((u32*)hi)[pi]     = h01;
    ((u32*)hi)[pi + 1] = h23;
    ((u32*)lo)[pi]     = l01;
    ((u32*)lo)[pi + 1] = l23;
}

// ---------------------------------------------------------------------------
// t[r] = sum_o tanh(SK[r,o]) * q[o]
// ---------------------------------------------------------------------------
__global__ void softkey_reduce(const float* __restrict__ SK, const float* __restrict__ q,
                               float* __restrict__ t)
{
    const long long r = blockIdx.x;
    const int tid = threadIdx.x;
    __shared__ float red[256];

    float s = 0.0f;
#pragma unroll
    for (int i = 0; i < 4; i++) {
        const int c = tid + i * 256;
        s += tanhf(SK[r * DMODEL + c]) * q[c];
    }
    red[tid] = s; __syncthreads();
    for (int k = 128; k > 0; k >>= 1) {
        if (tid < k) red[tid] += red[tid + k];
        __syncthreads();
    }
    if (tid == 0) t[r] = red[0];
}

// ---------------------------------------------------------------------------
// out[b,o] = sum_s w[b,s] * H[b,s,o]
// ---------------------------------------------------------------------------
__global__ void final_out(const float* __restrict__ H, const float* __restrict__ w,
                          float* __restrict__ out)
{
    const int b = blockIdx.y;
    const int o = blockIdx.x * 256 + threadIdx.x;
    const float* Hb = H + (long long)b * SEQL * DMODEL;
    const float* wb = w + (long long)b * SEQL;

    float a0 = 0.0f, a1 = 0.0f, a2 = 0.0f, a3 = 0.0f;
    for (int s = 0; s < SEQL; s += 4) {
        a0 += wb[s + 0] * Hb[(long long)(s + 0) * DMODEL + o];
        a1 += wb[s + 1] * Hb[(long long)(s + 1) * DMODEL + o];
        a2 += wb[s + 2] * Hb[(long long)(s + 2) * DMODEL + o];
        a3 += wb[s + 3] * Hb[(long long)(s + 3) * DMODEL + o];
    }
    out[b * DMODEL + o] = (a0 + a1) + (a2 + a3);
}

// ---------------------------------------------------------------------------
// Launch
// ---------------------------------------------------------------------------
extern "C" void kernel_launch(void* const* d_in, const int* in_sizes, int n_in,
                              void* d_out, int out_size)
{
    const float* inputs  = (const float*)d_in[0];
    const float* embed_w = (const float*)d_in[1];
    const float* embed_b = (const float*)d_in[2];
    const float* wq_w    = (const float*)d_in[3];
    const float* wq_b    = (const float*)d_in[4];
    const float* wk_w    = (const float*)d_in[5];
    const float* wk_b    = (const float*)d_in[6];
    const float* wv_w    = (const float*)d_in[7];
    const float* wv_b    = (const float*)d_in[8];
    const float* ln_g    = (const float*)d_in[9];
    const float* ln_b    = (const float*)d_in[10];
    const float* skw     = (const float*)d_in[11];
    const float* sq      = (const float*)d_in[12];
    const float* pos     = (const float*)d_in[13];
    float* out = (float*)d_out;

    cudaFuncSetAttribute((const void*)tc_gemm<true,  true,  false>,
                         cudaFuncAttributeMaxDynamicSharedMemorySize, DYN_SMEM_G);
    cudaFuncSetAttribute((const void*)tc_gemm<false, false, true>,
                         cudaFuncAttributeMaxDynamicSharedMemorySize, DYN_SMEM_G);
    cudaFuncSetAttribute((const void*)tc_gemm<true,  false, false>,
                         cudaFuncAttributeMaxDynamicSharedMemorySize, DYN_SMEM_G);

    float* base = 0;
    cudaGetSymbolAddress((void**)&base, g_scratch);

    u16* INh   = (u16*)(base + O_INS);   u16* INl   = INh   + C_IN;
    u16* EWh   = (u16*)(base + O_EWS);   u16* EWl   = EWh   + C_EW;
    u16* QKVWh = (u16*)(base + O_QKVW);  u16* QKVWl = QKVWh + 3 * C_W;
    u16* SKWh  = (u16*)(base + O_SKWS);  u16* SKWl  = SKWh  + C_W;
    float* X  = base + O_X;
    u16* Xh   = (u16*)(base + O_XS);    u16* Xl   = Xh   + C_MAT;
    u16* Qh   = (u16*)(base + O_QS);    u16* Ql   = Qh   + C_MAT;
    u16* Kh   = (u16*)(base + O_KS);    u16* Kl   = Kh   + C_MAT;
    u16* VTh  = (u16*)(base + O_VTS);   u16* VTl  = VTh  + C_MAT;
    float* SC = base + O_SC;
    u16* SCh  = (u16*)(base + O_SCS);   u16* SCl  = SCh  + C_SC;
    float* Z  = base + O_Z;
    float* H  = base + O_H;
    u16* Hh   = (u16*)(base + O_HS);    u16* Hl   = Hh   + C_MAT;
    float* SK = base + O_SK;
    float* T  = base + O_T;

    const QKVOut qkv = { Qh, Ql, Kh, Kl, VTh, VTl, wq_b, wk_b, wv_b };
    const QKVOut qnone = { 0, 0, 0, 0, 0, 0, 0, 0, 0 };

    // 0) one-time splits of raw inputs & weights (QKV weights stacked)
    split_fp32<<<(int)(C_IN / 4 / 256), 256>>>(inputs,  INh,  INl,  (int)(C_IN / 4));
    split_fp32<<<(int)(C_EW / 4 / 256), 256>>>(embed_w, EWh,  EWl,  (int)(C_EW / 4));
    split_fp32<<<(int)(C_W  / 4 / 256), 256>>>(wq_w, QKVWh,           QKVWl,           (int)(C_W / 4));
    split_fp32<<<(int)(C_W  / 4 / 256), 256>>>(wk_w, QKVWh + C_W,     QKVWl + C_W,     (int)(C_W / 4));
    split_fp32<<<(int)(C_W  / 4 / 256), 256>>>(wv_w, QKVWh + 2 * C_W, QKVWl + 2 * C_W, (int)(C_W / 4));
    split_fp32<<<(int)(C_W  / 4 / 256), 256>>>(skw,  SKWh,            SKWl,            (int)(C_W / 4));

    // 1) embed: X = inputs @ embed_w^T + embed_b + pos_enc  (fp32 + split out)
    tc_gemm<true, true, false><<<dim3(DMODEL / 128, NROW / 128, 1), 256, DYN_SMEM_G>>>(
        INh, INl, EWh, EWl, X, Xh, Xl, qnone,
        DMODEL, D_IN, 0, 0, 0, 1.0f, embed_b, pos);

    // 2) merged QKV: one N=3072 GEMM; epilogue routes per 1024-bucket
    tc_gemm<false, false, true><<<dim3(3 * DMODEL / 128, NROW / 128, 1), 256, DYN_SMEM_G>>>(
        Xh, Xl, QKVWh, QKVWl, 0, 0, 0, qkv,
        3 * DMODEL, DMODEL, 0, 0, 0, 1.0f, 0, 0);

    // 3) scores = Q @ K^T / 32 (batched, fp32 out)
    tc_gemm<true, false, false><<<dim3(SEQL / 128, SEQL / 128, BATCH), 256, DYN_SMEM_G>>>(
        Qh, Ql, Kh, Kl, SC, 0, 0, qnone,
        SEQL, DMODEL,
        (long long)SEQL * DMODEL, (long long)SEQL * DMODEL, (long long)SEQL * SEQL,
        1.0f / 32.0f, 0, 0);

    // 4) softmax -> split planes
    softmax_split<<<NROW, 256>>>(SC, SCh, SCl);

    // 5) Z = softmax(SC) @ V  (B = V^T planes, [n][k] per batch)
    tc_gemm<true, false, false><<<dim3(DMODEL / 128, SEQL / 128, BATCH), 256, DYN_SMEM_G>>>(
        SCh, SCl, VTh, VTl, Z, 0, 0, qnone,
        DMODEL, SEQL,
        (long long)SEQL * SEQL, (long long)DMODEL * SEQL, (long long)SEQL * DMODEL,
        1.0f, 0, 0);

    // 6) H = LN(X + Z)*g + b  (fp32 + split)
    add_ln_split<<<NROW, 256>>>(X, Z, ln_g, ln_b, H, Hh, Hl);

    // 7) SK = H @ soft_key_w^T (fp32 out)
    tc_gemm<true, false, false><<<dim3(DMODEL / 128, NROW / 128, 1), 256, DYN_SMEM_G>>>(
        Hh, Hl, SKWh, SKWl, SK, 0, 0, qnone,
        DMODEL, DMODEL, 0, 0, 0, 1.0f, 0, 0);

    // 8) t[b,s] = sum_o tanh(SK)*soft_query[o]; softmax over s per batch
    softkey_reduce<<<NROW, 256>>>(SK, sq, T);
    softmax_rows<<<BATCH, 256>>>(T);

    // 9) out[b,o] = sum_s w[b,s] * H[b,s,o]
    final_out<<<dim3(DMODEL / 256, BATCH), 256>>>(H, T, out);
}

// round 10
// speedup vs baseline: 1.1495x; 1.0715x over previous
#include <cuda_runtime.h>
#include <cstdint>
#include <math.h>

// ---------------------------------------------------------------------------
// Problem constants
// ---------------------------------------------------------------------------
#define BATCH   8
#define SEQL    2048
#define D_IN    512
#define DMODEL  1024
#define NROW    (BATCH * SEQL)          // 16384
#define LN_EPS  1e-5f

typedef unsigned short u16;
typedef uint32_t u32;

// element counts
static const long long C_IN  = (long long)NROW * D_IN;       // 8388608
static const long long C_EW  = (long long)DMODEL * D_IN;     // 524288
static const long long C_W   = (long long)DMODEL * DMODEL;   // 1048576
static const long long C_MAT = (long long)NROW * DMODEL;     // 16777216
static const long long C_SC  = (long long)BATCH * SEQL * SEQL; // 33554432

// scratch offsets (in floats; a split hi+lo pair of N elems occupies N floats)
#define O_INS   (0LL)
#define O_EWS   (O_INS  + C_IN)
#define O_WQS   (O_EWS  + C_EW)
#define O_WKS   (O_WQS  + C_W)
#define O_WVS   (O_WKS  + C_W)
#define O_SKWS  (O_WVS  + C_W)
#define O_X     (O_SKWS + C_W)
#define O_XS    (O_X    + C_MAT)
#define O_QS    (O_XS   + C_MAT)
#define O_KS    (O_QS   + C_MAT)
#define O_VTS   (O_KS   + C_MAT)
#define O_SC    (O_VTS  + C_MAT)
#define O_SCS   (O_SC   + C_SC)
#define O_Z     (O_SCS  + C_SC)
#define O_H     (O_Z    + C_MAT)
#define O_HS    (O_H    + C_MAT)
#define O_TP    (O_HS   + C_MAT)                 // soft-key partials [16384][32]
#define O_OP    (O_TP   + 16384LL * 32)          // final_out partials [64][1024]
#define O_T     (O_OP   + 65536)
#define O_TOTAL (O_T    + 16384)

__device__ float g_scratch[O_TOTAL];

// ---------------------------------------------------------------------------
// PTX helpers (baseline sm_80+ features only — harness targets plain sm_103)
// ---------------------------------------------------------------------------
__device__ __forceinline__ u32 smem_u32(const void* p) {
    u32 a;
    asm("{ .reg .u64 t; cvta.to.shared.u64 t, %1; cvt.u32.u64 %0, t; }"
        : "=r"(a) : "l"(p));
    return a;
}

__device__ __forceinline__ void cp_async16(u32 dst, const void* src) {
    asm volatile("cp.async.cg.shared.global [%0], [%1], 16;" :: "r"(dst), "l"(src));
}
#define CP_COMMIT() asm volatile("cp.async.commit_group;" ::: "memory")
#define CP_WAIT1()  asm volatile("cp.async.wait_group 1;"  ::: "memory")

// split x0,x1 (fp32) into packed bf16x2 hi and lo parts: x = hi + lo
__device__ __forceinline__ void split_pack(float x0, float x1, u32& hi, u32& lo) {
    asm("cvt.rn.bf16x2.f32 %0, %1, %2;" : "=r"(hi) : "f"(x1), "f"(x0));
    const float h0 = __uint_as_float(hi << 16);
    const float h1 = __uint_as_float(hi & 0xFFFF0000u);
    const float l0 = x0 - h0;
    const float l1 = x1 - h1;
    asm("cvt.rn.bf16x2.f32 %0, %1, %2;" : "=r"(lo) : "f"(l1), "f"(l0));
}

// D += A*B  (m16n8k16 bf16, fp32 accum)
__device__ __forceinline__ void mma_bf16(float* d, const u32* a, const u32* b) {
    asm volatile(
        "mma.sync.aligned.m16n8k16.row.col.f32.bf16.bf16.f32 "
        "{%0,%1,%2,%3}, {%4,%5,%6,%7}, {%8,%9}, {%0,%1,%2,%3};"
        : "+f"(d[0]), "+f"(d[1]), "+f"(d[2]), "+f"(d[3])
        : "r"(a[0]), "r"(a[1]), "r"(a[2]), "r"(a[3]), "r"(b[0]), "r"(b[1]));
}

__device__ __forceinline__ void ldmat4(u32& r0, u32& r1, u32& r2, u32& r3, u32 addr) {
    asm volatile("ldmatrix.sync.aligned.m8n8.x4.shared.b16 {%0,%1,%2,%3}, [%4];"
                 : "=r"(r0), "=r"(r1), "=r"(r2), "=r"(r3) : "r"(addr));
}

// swizzled byte offset of (row, 16B-chunk ch) in a 128x32 bf16 plane (64B rows)
__device__ __forceinline__ u32 sw_off(u32 row, u32 ch) {
    return row * 64u + ((ch ^ ((row >> 1) & 3u)) << 4);
}

// ---------------------------------------------------------------------------
// bf16x3 split GEMM on pre-split hi/lo planes:
//   C[m,n] = alpha * sum_k A[m,k]*B[n,k]  (+bias +posenc)
// A planes [M][K] bf16, B planes [N][K] bf16. Tile 128x128x32, 256 thr,
// 8 warps (2x4), warp tile 64x32. ldmatrix fragments.
// 3-buffer cp.async pipeline, ONE __syncthreads per k-chunk; stage c+2 is
// issued AFTER the compute of chunk c (proven fastest cadence).
//   F32OUT:  write fp32 C
//   SPLITOUT: write bf16 hi/lo planes of C
//   TRANSOUT: (V only) split planes written transposed per batch:
//             out[b][n][s] with m = b*SEQL + s
//   SKRED:   soft-key fused epilogue: per-row partials of sum tanh(C)*q[n]
//            written to TP[row*32 + blockIdx.x*4 + wn] (no C output)
// ---------------------------------------------------------------------------
#define PLANE_B  (128 * 64)             // 8192
#define STAGE_B  (4 * PLANE_B)          // 32768
#define DYN_SMEM_G (3 * STAGE_B)        // 98304

template <bool F32OUT, bool SPLITOUT, bool TRANSOUT, bool SKRED>
__global__ __launch_bounds__(256, 2)
void tc_gemm(const u16* __restrict__ Ahi, const u16* __restrict__ Alo,
             const u16* __restrict__ Bhi, const u16* __restrict__ Blo,
             float* __restrict__ Cf, u16* __restrict__ Chi, u16* __restrict__ Clo,
             float* __restrict__ TP, const float* __restrict__ qvec,
             int N, int K,
             long long sA, long long sB, long long sC,
             float alpha, const float* __restrict__ bias,
             const float* __restrict__ posenc)
{
    extern __shared__ char smem[];

    const int tid  = threadIdx.x;
    const int wid  = tid >> 5;
    const int lane = tid & 31;
    const int wm   = wid >> 2;       // 0..1 (M)
    const int wn   = wid & 3;        // 0..3 (N)
    const int g    = lane >> 2;      // groupID 0..7
    const int t    = lane & 3;       // threadID_in_group
    const int lrow = lane & 15;
    const int lch  = lane >> 4;

    const int bz = blockIdx.z;
    Ahi += bz * sA; Alo += bz * sA;
    Bhi += bz * sB; Blo += bz * sB;
    if (F32OUT) Cf += bz * sC;
    const int m0 = blockIdx.y * 128;
    const int n0 = blockIdx.x * 128;

    const u32 smem_base = smem_u32(smem);

    float acc[4][4][4];
#pragma unroll
    for (int mi = 0; mi < 4; mi++)
#pragma unroll
        for (int ni = 0; ni < 4; ni++)
#pragma unroll
            for (int c = 0; c < 4; c++) acc[mi][ni][c] = 0.0f;

    const int NC = K >> 5;   // k-chunks of 32

    // per-thread loader geometry
    const u32 ld_row = (u32)(tid >> 2);        // 0..63 (+64 on second pass)
    const u32 ld_ch  = (u32)(tid & 3);

    // ---- async stage loader: 4 planes (Ahi, Alo, Bhi, Blo), each 128x32 bf16
    auto issue_stage = [&](int c, int buf) {
        const int k0 = c * 32;
        const u32 st = smem_base + buf * STAGE_B;
        const u16* srcs[4] = { Ahi, Alo, Bhi, Blo };
#pragma unroll
        for (int p = 0; p < 4; p++) {
            const u16* src = srcs[p];
            const int rbase = (p < 2) ? m0 : n0;
#pragma unroll
            for (int i = 0; i < 2; i++) {
                const u32 row = ld_row + i * 64;
                cp_async16(st + p * PLANE_B + sw_off(row, ld_ch),
                           src + (long long)(rbase + row) * K + k0 + ld_ch * 8);
            }
        }
        CP_COMMIT();
    };

    issue_stage(0, 0);
    issue_stage(1, 1);

    int buf = 0;          // buffer holding chunk c
    int nbuf = 2;         // buffer that issue_stage(c+2) writes
    for (int c = 0; c < NC; ++c) {
        CP_WAIT1();
        __syncthreads();

        const u32 st = smem_base + buf * STAGE_B;

#pragma unroll
        for (int half = 0; half < 2; half++) {
            const u32 ch = (u32)(half * 2 + lch);

            // ---- B fragments: 2 x ldmatrix.x4 per plane cover all 4 ni ----
            u32 bh[4][2], bl[4][2];
#pragma unroll
            for (int nj = 0; nj < 2; nj++) {
                const u32 rb = sw_off((u32)(wn * 32 + nj * 16 + lrow), ch);
                u32 r0, r1, r2, r3;
                ldmat4(r0, r1, r2, r3, st + 2 * PLANE_B + rb);
                bh[2*nj][0] = r0; bh[2*nj+1][0] = r1;
                bh[2*nj][1] = r2; bh[2*nj+1][1] = r3;
                ldmat4(r0, r1, r2, r3, st + 3 * PLANE_B + rb);
                bl[2*nj][0] = r0; bl[2*nj+1][0] = r1;
                bl[2*nj][1] = r2; bl[2*nj+1][1] = r3;
            }

            // ---- A fragments for an mi-pair, then term-major MMA blocks ----
#pragma unroll
            for (int mp = 0; mp < 2; mp++) {
                u32 ah[2][4], al[2][4];
#pragma unroll
                for (int q = 0; q < 2; q++) {
                    const int mi = mp * 2 + q;
                    const u32 ra = sw_off((u32)(wm * 64 + mi * 16 + lrow), ch);
                    ldmat4(ah[q][0], ah[q][1], ah[q][2], ah[q][3], st + ra);
                    ldmat4(al[q][0], al[q][1], al[q][2], al[q][3], st + PLANE_B + ra);
                }
                // term 1: hi*hi — 8 independent MMAs
#pragma unroll
                for (int q = 0; q < 2; q++)
#pragma unroll
                    for (int ni = 0; ni < 4; ni++)
                        mma_bf16(acc[mp*2+q][ni], ah[q], bh[ni]);
                // term 2: hi*lo
#pragma unroll
                for (int q = 0; q < 2; q++)
#pragma unroll
                    for (int ni = 0; ni < 4; ni++)
                        mma_bf16(acc[mp*2+q][ni], ah[q], bl[ni]);
                // term 3: lo*hi
#pragma unroll
                for (int q = 0; q < 2; q++)
#pragma unroll
                    for (int ni = 0; ni < 4; ni++)
                        mma_bf16(acc[mp*2+q][ni], al[q], bh[ni]);
            }
        }

        // 3-buffer rotation: nbuf was last read at iter c-1; every warp has
        // passed this iter's barrier, so it is safe to overwrite. No second
        // __syncthreads needed. (Issue AFTER compute — proven cadence.)
        if (c + 2 < NC) issue_stage(c + 2, nbuf);
        else            CP_COMMIT();   // keep group accounting uniform

        buf  = (buf  == 2) ? 0 : buf  + 1;
        nbuf = (nbuf == 2) ? 0 : nbuf + 1;
    }

    // ---- epilogue ----
    if (SKRED) {
        // fused soft-key: p[row] = sum_n tanh(C[row,n]) * q[n] over this
        // CTA's 128-col slice; reduce across t-lanes, one slot per warp.
#pragma unroll
        for (int mi = 0; mi < 4; mi++) {
            float p0 = 0.0f, p1 = 0.0f;
#pragma unroll
            for (int ni = 0; ni < 4; ni++) {
                const int n = n0 + wn * 32 + ni * 8 + 2 * t;
                const float q0 = qvec[n], q1 = qvec[n + 1];
                p0 += tanhf(acc[mi][ni][0]) * q0 + tanhf(acc[mi][ni][1]) * q1;
                p1 += tanhf(acc[mi][ni][2]) * q0 + tanhf(acc[mi][ni][3]) * q1;
            }
            p0 += __shfl_xor_sync(0xffffffffu, p0, 1);
            p0 += __shfl_xor_sync(0xffffffffu, p0, 2);
            p1 += __shfl_xor_sync(0xffffffffu, p1, 1);
            p1 += __shfl_xor_sync(0xffffffffu, p1, 2);
            if (t == 0) {
                const int m_lo = m0 + wm * 64 + mi * 16 + g;
                const int slot = blockIdx.x * 4 + wn;
                TP[(long long)m_lo * 32 + slot]       = p0;
                TP[(long long)(m_lo + 8) * 32 + slot] = p1;
            }
        }
        return;
    }

#pragma unroll
    for (int mi = 0; mi < 4; mi++) {
        const int m_lo = m0 + wm * 64 + mi * 16 + g;
        const int m_hi = m_lo + 8;
        const float* pe_lo = posenc ? posenc + (long long)(m_lo & (SEQL - 1)) * N : 0;
        const float* pe_hi = posenc ? posenc + (long long)(m_hi & (SEQL - 1)) * N : 0;
#pragma unroll
        for (int ni = 0; ni < 4; ni++) {
            const int n = n0 + wn * 32 + ni * 8 + 2 * t;
            float2 v0, v1;
            v0.x = acc[mi][ni][0] * alpha;
            v0.y = acc[mi][ni][1] * alpha;
            v1.x = acc[mi][ni][2] * alpha;
            v1.y = acc[mi][ni][3] * alpha;
            if (bias) {
                const float b0 = bias[n], b1 = bias[n + 1];
                v0.x += b0; v0.y += b1;
                v1.x += b0; v1.y += b1;
            }
            if (posenc) {
                v0.x += pe_lo[n]; v0.y += pe_lo[n + 1];
                v1.x += pe_hi[n]; v1.y += pe_hi[n + 1];
            }
            if (F32OUT) {
                *(float2*)(Cf + (long long)m_lo * N + n) = v0;
                *(float2*)(Cf + (long long)m_hi * N + n) = v1;
            }
            if (SPLITOUT) {
                u32 h, l;
                if (!TRANSOUT) {
                    split_pack(v0.x, v0.y, h, l);
                    *(u32*)(Chi + (long long)m_lo * N + n) = h;
                    *(u32*)(Clo + (long long)m_lo * N + n) = l;
                    split_pack(v1.x, v1.y, h, l);
                    *(u32*)(Chi + (long long)m_hi * N + n) = h;
                    *(u32*)(Clo + (long long)m_hi * N + n) = l;
                } else {
                    // V^T: out[b][n][s], m = b*SEQL + s; DMODEL*SEQL = 1<<21
                    const long long base_lo =
                        ((long long)(m_lo >> 11) << 21) + (m_lo & 2047);
                    const long long base_hi =
                        ((long long)(m_hi >> 11) << 21) + (m_hi & 2047);
                    split_pack(v0.x, v0.y, h, l);
                    Chi[base_lo + (long long)n * SEQL]       = (u16)h;
                    Chi[base_lo + (long long)(n + 1) * SEQL] = (u16)(h >> 16);
                    Clo[base_lo + (long long)n * SEQL]       = (u16)l;
                    Clo[base_lo + (long long)(n + 1) * SEQL] = (u16)(l >> 16);
                    split_pack(v1.x, v1.y, h, l);
                    Chi[base_hi + (long long)n * SEQL]       = (u16)h;
                    Chi[base_hi + (long long)(n + 1) * SEQL] = (u16)(h >> 16);
                    Clo[base_hi + (long long)n * SEQL]       = (u16)l;
                    Clo[base_hi + (long long)(n + 1) * SEQL] = (u16)(l >> 16);
                }
            }
        }
    }
}

// ---------------------------------------------------------------------------
// fp32 -> split bf16 hi/lo planes (4 elems per thread)
// ---------------------------------------------------------------------------
__global__ void split_fp32(const float* __restrict__ src,
                           u16* __restrict__ hi, u16* __restrict__ lo, int n4)
{
    const int i = blockIdx.x * blockDim.x + threadIdx.x;
    if (i >= n4) return;
    const float4 v = ((const float4*)src)[i];
    u32 h01, l01, h23, l23;
    split_pack(v.x, v.y, h01, l01);
    split_pack(v.z, v.w, h23, l23);
    ((uint2*)hi)[i] = make_uint2(h01, h23);
    ((uint2*)lo)[i] = make_uint2(l01, l23);
}

// ---------------------------------------------------------------------------
// Row softmax (2048 cols) reading fp32, writing split bf16 planes.
// ---------------------------------------------------------------------------
__global__ void softmax_split(const float* __restrict__ S,
                              u16* __restrict__ hi, u16* __restrict__ lo)
{
    const long long off = (long long)blockIdx.x * 2048;
    const float* row = S + off;
    const int tid = threadIdx.x;
    __shared__ float red[256];

    float v[8];
    *(float4*)&v[0] = *(const float4*)(row + tid * 8);
    *(float4*)&v[4] = *(const float4*)(row + tid * 8 + 4);

    float mx = -1e30f;
#pragma unroll
    for (int i = 0; i < 8; i++) mx = fmaxf(mx, v[i]);
    red[tid] = mx; __syncthreads();
    for (int s = 128; s > 0; s >>= 1) {
        if (tid < s) red[tid] = fmaxf(red[tid], red[tid + s]);
        __syncthreads();
    }
    mx = red[0]; __syncthreads();

    float sum = 0.0f;
#pragma unroll
    for (int i = 0; i < 8; i++) { v[i] = __expf(v[i] - mx); sum += v[i]; }
    red[tid] = sum; __syncthreads();
    for (int s = 128; s > 0; s >>= 1) {
        if (tid < s) red[tid] += red[tid + s];
        __syncthreads();
    }
    const float inv = 1.0f / red[0];

    u32* hp = (u32*)hi + (off >> 1) + tid * 4;
    u32* lp = (u32*)lo + (off >> 1) + tid * 4;
#pragma unroll
    for (int j = 0; j < 4; j++) {
        u32 h, l;
        split_pack(v[2*j] * inv, v[2*j+1] * inv, h, l);
        hp[j] = h; lp[j] = l;
    }
}

// ---------------------------------------------------------------------------
// Plain fp32 row softmax (for the length-2048 pooling weights, 8 rows)
// ---------------------------------------------------------------------------
__global__ void softmax_rows(float* __restrict__ S)
{
    float* row = S + (long long)blockIdx.x * 2048;
    const int tid = threadIdx.x;
    __shared__ float red[256];

    float v[8];
    *(float4*)&v[0] = *(const float4*)(row + tid * 8);
    *(float4*)&v[4] = *(const float4*)(row + tid * 8 + 4);

    float mx = -1e30f;
#pragma unroll
    for (int i = 0; i < 8; i++) mx = fmaxf(mx, v[i]);
    red[tid] = mx; __syncthreads();
    for (int s = 128; s > 0; s >>= 1) {
        if (tid < s) red[tid] = fmaxf(red[tid], red[tid + s]);
        __syncthreads();
    }
    mx = red[0]; __syncthreads();

    float sum = 0.0f;
#pragma unroll
    for (int i = 0; i < 8; i++) { v[i] = __expf(v[i] - mx); sum += v[i]; }
    red[tid] = sum; __syncthreads();
    for (int s = 128; s > 0; s >>= 1) {
        if (tid < s) red[tid] += red[tid + s];
        __syncthreads();
    }
    const float inv = 1.0f / red[0];
#pragma unroll
    for (int i = 0; i < 8; i++) v[i] *= inv;
    *(float4*)(row + tid * 8)     = *(float4*)&v[0];
    *(float4*)(row + tid * 8 + 4) = *(float4*)&v[4];
}

// ---------------------------------------------------------------------------
// h = x + z ; H = LN(h)*g + b  -> fp32 H + split planes
// ---------------------------------------------------------------------------
__global__ void add_ln_split(const float* __restrict__ X, const float* __restrict__ Z,
                             const float* __restrict__ g, const float* __restrict__ b,
                             float* __restrict__ H, u16* __restrict__ hi, u16* __restrict__ lo)
{
    const long long r = blockIdx.x;
    const int tid = threadIdx.x;
    const int c0  = tid * 4;
    const float* xr = X + r * DMODEL;
    const float* zr = Z + r * DMODEL;
    __shared__ float red[256];

    float4 x4 = *(const float4*)(xr + c0);
    float4 z4 = *(const float4*)(zr + c0);
    float h[4] = { x4.x + z4.x, x4.y + z4.y, x4.z + z4.z, x4.w + z4.w };

    float sum = h[0] + h[1] + h[2] + h[3];
    red[tid] = sum; __syncthreads();
    for (int s = 128; s > 0; s >>= 1) {
        if (tid < s) red[tid] += red[tid + s];
        __syncthreads();
    }
    const float mean = red[0] * (1.0f / DMODEL);
    __syncthreads();

    float vs = 0.0f;
#pragma unroll
    for (int i = 0; i < 4; i++) { const float d = h[i] - mean; vs += d * d; }
    red[tid] = vs; __syncthreads();
    for (int s = 128; s > 0; s >>= 1) {
        if (tid < s) red[tid] += red[tid + s];
        __syncthreads();
    }
    const float inv = rsqrtf(red[0] * (1.0f / DMODEL) + LN_EPS);

    float4 o;
    o.x = (h[0] - mean) * inv * g[c0 + 0] + b[c0 + 0];
    o.y = (h[1] - mean) * inv * g[c0 + 1] + b[c0 + 1];
    o.z = (h[2] - mean) * inv * g[c0 + 2] + b[c0 + 2];
    o.w = (h[3] - mean) * inv * g[c0 + 3] + b[c0 + 3];
    *(float4*)(H + r * DMODEL + c0) = o;

    u32 h01, l01, h23, l23;
    split_pack(o.x, o.y, h01, l01);
    split_pack(o.z, o.w, h23, l23);
    const long long pi = (r * DMODEL + c0) >> 1;
    ((u32*)hi)[pi]     = h01;
    ((u32*)hi)[pi + 1] = h23;
    ((u32*)lo)[pi]     = l01;
    ((u32*)lo)[pi + 1] = l23;
}

// ---------------------------------------------------------------------------
// T[r] = sum of 32 soft-key partials (deterministic fixed-order reduce)
// ---------------------------------------------------------------------------
__global__ void skt_reduce(const float* __restrict__ TP, float* __restrict__ T)
{
    const int r = blockIdx.x * 256 + threadIdx.x;
    const float* p = TP + (long long)r * 32;
    float s = 0.0f;
#pragma unroll
    for (int j = 0; j < 32; j++) s += p[j];
    T[r] = s;
}

// ---------------------------------------------------------------------------
// final_out stage 1: partial over 256-row s-chunk
//   OP[(b*8+zc)*DMODEL + o] = sum_{s in chunk} w[b,s] * H[b,s,o]
// ---------------------------------------------------------------------------
__global__ void final_partial(const float* __restrict__ H, const float* __restrict__ w,
                              float* __restrict__ OP)
{
    const int b  = blockIdx.y;
    const int zc = blockIdx.z;
    const int o  = blockIdx.x * 256 + threadIdx.x;
    const float* Hp = H + (long long)b * SEQL * DMODEL
                        + (long long)(zc * 256) * DMODEL + o;
    const float* wb = w + (long long)b * SEQL + zc * 256;

    float a0 = 0.0f, a1 = 0.0f, a2 = 0.0f, a3 = 0.0f;
    for (int s = 0; s < 256; s += 4) {
        a0 += wb[s + 0] * Hp[(long long)(s + 0) * DMODEL];
        a1 += wb[s + 1] * Hp[(long long)(s + 1) * DMODEL];
        a2 += wb[s + 2] * Hp[(long long)(s + 2) * DMODEL];
        a3 += wb[s + 3] * Hp[(long long)(s + 3) * DMODEL];
    }
    OP[(long long)(b * 8 + zc) * DMODEL + o] = (a0 + a1) + (a2 + a3);
}

// final_out stage 2: sum the 8 s-chunk partials (deterministic)
__global__ void final_reduce(const float* __restrict__ OP, float* __restrict__ out)
{
    const int b = blockIdx.y;
    const int o = blockIdx.x * 256 + threadIdx.x;
    float s = 0.0f;
#pragma unroll
    for (int z = 0; z < 8; z++)
        s += OP[(long long)(b * 8 + z) * DMODEL + o];
    out[b * DMODEL + o] = s;
}

// ---------------------------------------------------------------------------
// Launch
// ---------------------------------------------------------------------------
extern "C" void kernel_launch(void* const* d_in, const int* in_sizes, int n_in,
                              void* d_out, int out_size)
{
    const float* inputs  = (const float*)d_in[0];
    const float* embed_w = (const float*)d_in[1];
    const float* embed_b = (const float*)d_in[2];
    const float* wq_w    = (const float*)d_in[3];
    const float* wq_b    = (const float*)d_in[4];
    const float* wk_w    = (const float*)d_in[5];
    const float* wk_b    = (const float*)d_in[6];
    const float* wv_w    = (const float*)d_in[7];
    const float* wv_b    = (const float*)d_in[8];
    const float* ln_g    = (const float*)d_in[9];
    const float* ln_b    = (const float*)d_in[10];
    const float* skw     = (const float*)d_in[11];
    const float* sq      = (const float*)d_in[12];
    const float* pos     = (const float*)d_in[13];
    float* out = (float*)d_out;

    cudaFuncSetAttribute((const void*)tc_gemm<true,  true,  false, false>,
                         cudaFuncAttributeMaxDynamicSharedMemorySize, DYN_SMEM_G);
    cudaFuncSetAttribute((const void*)tc_gemm<false, true,  false, false>,
                         cudaFuncAttributeMaxDynamicSharedMemorySize, DYN_SMEM_G);
    cudaFuncSetAttribute((const void*)tc_gemm<false, true,  true,  false>,
                         cudaFuncAttributeMaxDynamicSharedMemorySize, DYN_SMEM_G);
    cudaFuncSetAttribute((const void*)tc_gemm<true,  false, false, false>,
                         cudaFuncAttributeMaxDynamicSharedMemorySize, DYN_SMEM_G);
    cudaFuncSetAttribute((const void*)tc_gemm<false, false, false, true>,
                         cudaFuncAttributeMaxDynamicSharedMemorySize, DYN_SMEM_G);

    float* base = 0;
    cudaGetSymbolAddress((void**)&base, g_scratch);

    u16* INh  = (u16*)(base + O_INS);   u16* INl  = INh  + C_IN;
    u16* EWh  = (u16*)(base + O_EWS);   u16* EWl  = EWh  + C_EW;
    u16* WQh  = (u16*)(base + O_WQS);   u16* WQl  = WQh  + C_W;
    u16* WKh  = (u16*)(base + O_WKS);   u16* WKl  = WKh  + C_W;
    u16* WVh  = (u16*)(base + O_WVS);   u16* WVl  = WVh  + C_W;
    u16* SKWh = (u16*)(base + O_SKWS);  u16* SKWl = SKWh + C_W;
    float* X  = base + O_X;
    u16* Xh   = (u16*)(base + O_XS);    u16* Xl   = Xh   + C_MAT;
    u16* Qh   = (u16*)(base + O_QS);    u16* Ql   = Qh   + C_MAT;
    u16* Kh   = (u16*)(base + O_KS);    u16* Kl   = Kh   + C_MAT;
    u16* VTh  = (u16*)(base + O_VTS);   u16* VTl  = VTh  + C_MAT;
    float* SC = base + O_SC;
    u16* SCh  = (u16*)(base + O_SCS);   u16* SCl  = SCh  + C_SC;
    float* Z  = base + O_Z;
    float* H  = base + O_H;
    u16* Hh   = (u16*)(base + O_HS);    u16* Hl   = Hh   + C_MAT;
    float* TP = base + O_TP;
    float* OP = base + O_OP;
    float* T  = base + O_T;

    // 0) one-time splits of raw inputs & weights
    split_fp32<<<(int)(C_IN / 4 / 256), 256>>>(inputs,  INh,  INl,  (int)(C_IN / 4));
    split_fp32<<<(int)(C_EW / 4 / 256), 256>>>(embed_w, EWh,  EWl,  (int)(C_EW / 4));
    split_fp32<<<(int)(C_W  / 4 / 256), 256>>>(wq_w,    WQh,  WQl,  (int)(C_W  / 4));
    split_fp32<<<(int)(C_W  / 4 / 256), 256>>>(wk_w,    WKh,  WKl,  (int)(C_W  / 4));
    split_fp32<<<(int)(C_W  / 4 / 256), 256>>>(wv_w,    WVh,  WVl,  (int)(C_W  / 4));
    split_fp32<<<(int)(C_W  / 4 / 256), 256>>>(skw,     SKWh, SKWl, (int)(C_W  / 4));

    // 1) embed: X = inputs @ embed_w^T + embed_b + pos_enc  (fp32 + split out)
    tc_gemm<true, true, false, false><<<dim3(DMODEL / 128, NROW / 128, 1), 256, DYN_SMEM_G>>>(
        INh, INl, EWh, EWl, X, Xh, Xl, 0, 0,
        DMODEL, D_IN, 0, 0, 0, 1.0f, embed_b, pos);

    // 2) Q, K (split out), V (transposed split out)
    tc_gemm<false, true, false, false><<<dim3(DMODEL / 128, NROW / 128, 1), 256, DYN_SMEM_G>>>(
        Xh, Xl, WQh, WQl, 0, Qh, Ql, 0, 0,
        DMODEL, DMODEL, 0, 0, 0, 1.0f, wq_b, 0);
    tc_gemm<false, true, false, false><<<dim3(DMODEL / 128, NROW / 128, 1), 256, DYN_SMEM_G>>>(
        Xh, Xl, WKh, WKl, 0, Kh, Kl, 0, 0,
        DMODEL, DMODEL, 0, 0, 0, 1.0f, wk_b, 0);
    tc_gemm<false, true, true, false><<<dim3(DMODEL / 128, NROW / 128, 1), 256, DYN_SMEM_G>>>(
        Xh, Xl, WVh, WVl, 0, VTh, VTl, 0, 0,
        DMODEL, DMODEL, 0, 0, 0, 1.0f, wv_b, 0);

    // 3) scores = Q @ K^T / 32 (batched, fp32 out)
    tc_gemm<true, false, false, false><<<dim3(SEQL / 128, SEQL / 128, BATCH), 256, DYN_SMEM_G>>>(
        Qh, Ql, Kh, Kl, SC, 0, 0, 0, 0,
        SEQL, DMODEL,
        (long long)SEQL * DMODEL, (long long)SEQL * DMODEL, (long long)SEQL * SEQL,
        1.0f / 32.0f, 0, 0);

    // 4) softmax -> split planes
    softmax_split<<<NROW, 256>>>(SC, SCh, SCl);

    // 5) Z = softmax(SC) @ V  (B = V^T planes, [n][k] per batch)
    tc_gemm<true, false, false, false><<<dim3(DMODEL / 128, SEQL / 128, BATCH), 256, DYN_SMEM_G>>>(
        SCh, SCl, VTh, VTl, Z, 0, 0, 0, 0,
        DMODEL, SEQL,
        (long long)SEQL * SEQL, (long long)DMODEL * SEQL, (long long)SEQL * DMODEL,
        1.0f, 0, 0);

    // 6) H = LN(X + Z)*g + b  (fp32 + split)
    add_ln_split<<<NROW, 256>>>(X, Z, ln_g, ln_b, H, Hh, Hl);

    // 7) fused SK GEMM + tanh·q partial reduction -> TP
    tc_gemm<false, false, false, true><<<dim3(DMODEL / 128, NROW / 128, 1), 256, DYN_SMEM_G>>>(
        Hh, Hl, SKWh, SKWl, 0, 0, 0, TP, sq,
        DMODEL, DMODEL, 0, 0, 0, 1.0f, 0, 0);

    // 8) T[r] = sum partials; softmax over s per batch
    skt_reduce<<<NROW / 256, 256>>>(TP, T);
    softmax_rows<<<BATCH, 256>>>(T);

    // 9) out[b,o] = sum_s w[b,s] * H[b,s,o]  (two-stage, deterministic)
    final_partial<<<dim3(DMODEL / 256, BATCH, 8), 256>>>(H, T, OP);
    final_reduce<<<dim3(DMODEL / 256, BATCH), 256>>>(OP, out);
}

// round 11
// speedup vs baseline: 1.2614x; 1.0973x over previous
#include <cuda_runtime.h>
#include <cstdint>
#include <math.h>

// ---------------------------------------------------------------------------
// Problem constants
// ---------------------------------------------------------------------------
#define BATCH   8
#define SEQL    2048
#define D_IN    512
#define DMODEL  1024
#define NROW    (BATCH * SEQL)          // 16384
#define LN_EPS  1e-5f

typedef unsigned short u16;
typedef uint32_t u32;

// element counts
static const long long C_IN  = (long long)NROW * D_IN;       // 8388608
static const long long C_EW  = (long long)DMODEL * D_IN;     // 524288
static const long long C_W   = (long long)DMODEL * DMODEL;   // 1048576
static const long long C_MAT = (long long)NROW * DMODEL;     // 16777216
static const long long C_SC  = (long long)BATCH * SEQL * SEQL; // 33554432

// scratch offsets (in floats)
#define O_INS   (0LL)
#define O_EWS   (O_INS  + C_IN)
#define O_WQS   (O_EWS  + C_EW)
#define O_WKS   (O_WQS  + C_W)
#define O_WVS   (O_WKS  + C_W)
#define O_SKWS  (O_WVS  + C_W)
#define O_X     (O_SKWS + C_W)
#define O_XS    (O_X    + C_MAT)
#define O_Q     (O_XS   + C_MAT)        // fp32 Q
#define O_K     (O_Q    + C_MAT)        // fp32 K
#define O_VT    (O_K    + C_MAT)        // fp32 V^T (per batch [n][s])
#define O_SC    (O_VT   + C_MAT)        // fp32 scores
#define O_Z     (O_SC   + C_SC)
#define O_H     (O_Z    + C_MAT)
#define O_HS    (O_H    + C_MAT)
#define O_TP    (O_HS   + C_MAT)                 // soft-key partials [16384][32]
#define O_OP    (O_TP   + 16384LL * 32)          // final_out partials [64][1024]
#define O_T     (O_OP   + 65536)
#define O_TOTAL (O_T    + 16384)

__device__ float g_scratch[O_TOTAL];

// ---------------------------------------------------------------------------
// PTX helpers (baseline sm_80+ features only — harness targets plain sm_103)
// ---------------------------------------------------------------------------
__device__ __forceinline__ u32 smem_u32(const void* p) {
    u32 a;
    asm("{ .reg .u64 t; cvta.to.shared.u64 t, %1; cvt.u32.u64 %0, t; }"
        : "=r"(a) : "l"(p));
    return a;
}

__device__ __forceinline__ void cp_async16(u32 dst, const void* src) {
    asm volatile("cp.async.cg.shared.global [%0], [%1], 16;" :: "r"(dst), "l"(src));
}
#define CP_COMMIT() asm volatile("cp.async.commit_group;" ::: "memory")
#define CP_WAIT1()  asm volatile("cp.async.wait_group 1;"  ::: "memory")

// split x0,x1 (fp32) into packed bf16x2 hi and lo parts: x = hi + lo
__device__ __forceinline__ void split_pack(float x0, float x1, u32& hi, u32& lo) {
    asm("cvt.rn.bf16x2.f32 %0, %1, %2;" : "=r"(hi) : "f"(x1), "f"(x0));
    const float h0 = __uint_as_float(hi << 16);
    const float h1 = __uint_as_float(hi & 0xFFFF0000u);
    const float l0 = x0 - h0;
    const float l1 = x1 - h1;
    asm("cvt.rn.bf16x2.f32 %0, %1, %2;" : "=r"(lo) : "f"(l1), "f"(l0));
}

__device__ __forceinline__ u32 f2tf32(float f) {
    u32 r;
    asm("cvt.rna.tf32.f32 %0, %1;" : "=r"(r) : "f"(f));
    return r;
}

// D += A*B  (m16n8k16 bf16, fp32 accum)
__device__ __forceinline__ void mma_bf16(float* d, const u32* a, const u32* b) {
    asm volatile(
        "mma.sync.aligned.m16n8k16.row.col.f32.bf16.bf16.f32 "
        "{%0,%1,%2,%3}, {%4,%5,%6,%7}, {%8,%9}, {%0,%1,%2,%3};"
        : "+f"(d[0]), "+f"(d[1]), "+f"(d[2]), "+f"(d[3])
        : "r"(a[0]), "r"(a[1]), "r"(a[2]), "r"(a[3]), "r"(b[0]), "r"(b[1]));
}

// D += A*B  (m16n8k8 tf32, fp32 accum)
__device__ __forceinline__ void mma_tf32(float* d, const u32* a, const u32* b) {
    asm volatile(
        "mma.sync.aligned.m16n8k8.row.col.f32.tf32.tf32.f32 "
        "{%0,%1,%2,%3}, {%4,%5,%6,%7}, {%8,%9}, {%0,%1,%2,%3};"
        : "+f"(d[0]), "+f"(d[1]), "+f"(d[2]), "+f"(d[3])
        : "r"(a[0]), "r"(a[1]), "r"(a[2]), "r"(a[3]), "r"(b[0]), "r"(b[1]));
}

__device__ __forceinline__ void ldmat4(u32& r0, u32& r1, u32& r2, u32& r3, u32 addr) {
    asm volatile("ldmatrix.sync.aligned.m8n8.x4.shared.b16 {%0,%1,%2,%3}, [%4];"
                 : "=r"(r0), "=r"(r1), "=r"(r2), "=r"(r3) : "r"(addr));
}

// swizzled byte offset of (row, 16B-chunk ch) in a 128x32 bf16 plane (64B rows)
__device__ __forceinline__ u32 sw_off(u32 row, u32 ch) {
    return row * 64u + ((ch ^ ((row >> 1) & 3u)) << 4);
}

// ---------------------------------------------------------------------------
// bf16x3 split GEMM on pre-split hi/lo planes (R7/R10 proven cadence):
//   C[m,n] = alpha * sum_k A[m,k]*B[n,k]  (+bias +posenc)
//   F32OUT:  write fp32 C
//   SPLITOUT: also write bf16 hi/lo planes of C
//   FTRANS:  write fp32 C transposed per batch: out[b][n][s], m=b*SEQL+s
//   SKRED:   fused soft-key epilogue (partials of sum tanh(C)*q)
// ---------------------------------------------------------------------------
#define PLANE_B  (128 * 64)             // 8192
#define STAGE_B  (4 * PLANE_B)          // 32768
#define DYN_SMEM_G (3 * STAGE_B)        // 98304

template <bool F32OUT, bool SPLITOUT, bool FTRANS, bool SKRED>
__global__ __launch_bounds__(256, 2)
void tc_gemm(const u16* __restrict__ Ahi, const u16* __restrict__ Alo,
             const u16* __restrict__ Bhi, const u16* __restrict__ Blo,
             float* __restrict__ Cf, u16* __restrict__ Chi, u16* __restrict__ Clo,
             float* __restrict__ TP, const float* __restrict__ qvec,
             int N, int K,
             long long sA, long long sB, long long sC,
             float alpha, const float* __restrict__ bias,
             const float* __restrict__ posenc)
{
    extern __shared__ char smem[];

    const int tid  = threadIdx.x;
    const int wid  = tid >> 5;
    const int lane = tid & 31;
    const int wm   = wid >> 2;
    const int wn   = wid & 3;
    const int g    = lane >> 2;
    const int t    = lane & 3;
    const int lrow = lane & 15;
    const int lch  = lane >> 4;

    const int bz = blockIdx.z;
    Ahi += bz * sA; Alo += bz * sA;
    Bhi += bz * sB; Blo += bz * sB;
    if (F32OUT) Cf += bz * sC;
    const int m0 = blockIdx.y * 128;
    const int n0 = blockIdx.x * 128;

    const u32 smem_base = smem_u32(smem);

    float acc[4][4][4];
#pragma unroll
    for (int mi = 0; mi < 4; mi++)
#pragma unroll
        for (int ni = 0; ni < 4; ni++)
#pragma unroll
            for (int c = 0; c < 4; c++) acc[mi][ni][c] = 0.0f;

    const int NC = K >> 5;

    const u32 ld_row = (u32)(tid >> 2);
    const u32 ld_ch  = (u32)(tid & 3);

    auto issue_stage = [&](int c, int buf) {
        const int k0 = c * 32;
        const u32 st = smem_base + buf * STAGE_B;
        const u16* srcs[4] = { Ahi, Alo, Bhi, Blo };
#pragma unroll
        for (int p = 0; p < 4; p++) {
            const u16* src = srcs[p];
            const int rbase = (p < 2) ? m0 : n0;
#pragma unroll
            for (int i = 0; i < 2; i++) {
                const u32 row = ld_row + i * 64;
                cp_async16(st + p * PLANE_B + sw_off(row, ld_ch),
                           src + (long long)(rbase + row) * K + k0 + ld_ch * 8);
            }
        }
        CP_COMMIT();
    };

    issue_stage(0, 0);
    issue_stage(1, 1);

    int buf = 0;
    int nbuf = 2;
    for (int c = 0; c < NC; ++c) {
        CP_WAIT1();
        __syncthreads();

        const u32 st = smem_base + buf * STAGE_B;

#pragma unroll
        for (int half = 0; half < 2; half++) {
            const u32 ch = (u32)(half * 2 + lch);

            u32 bh[4][2], bl[4][2];
#pragma unroll
            for (int nj = 0; nj < 2; nj++) {
                const u32 rb = sw_off((u32)(wn * 32 + nj * 16 + lrow), ch);
                u32 r0, r1, r2, r3;
                ldmat4(r0, r1, r2, r3, st + 2 * PLANE_B + rb);
                bh[2*nj][0] = r0; bh[2*nj+1][0] = r1;
                bh[2*nj][1] = r2; bh[2*nj+1][1] = r3;
                ldmat4(r0, r1, r2, r3, st + 3 * PLANE_B + rb);
                bl[2*nj][0] = r0; bl[2*nj+1][0] = r1;
                bl[2*nj][1] = r2; bl[2*nj+1][1] = r3;
            }

#pragma unroll
            for (int mp = 0; mp < 2; mp++) {
                u32 ah[2][4], al[2][4];
#pragma unroll
                for (int q = 0; q < 2; q++) {
                    const int mi = mp * 2 + q;
                    const u32 ra = sw_off((u32)(wm * 64 + mi * 16 + lrow), ch);
                    ldmat4(ah[q][0], ah[q][1], ah[q][2], ah[q][3], st + ra);
                    ldmat4(al[q][0], al[q][1], al[q][2], al[q][3], st + PLANE_B + ra);
                }
#pragma unroll
                for (int q = 0; q < 2; q++)
#pragma unroll
                    for (int ni = 0; ni < 4; ni++)
                        mma_bf16(acc[mp*2+q][ni], ah[q], bh[ni]);
#pragma unroll
                for (int q = 0; q < 2; q++)
#pragma unroll
                    for (int ni = 0; ni < 4; ni++)
                        mma_bf16(acc[mp*2+q][ni], ah[q], bl[ni]);
#pragma unroll
                for (int q = 0; q < 2; q++)
#pragma unroll
                    for (int ni = 0; ni < 4; ni++)
                        mma_bf16(acc[mp*2+q][ni], al[q], bh[ni]);
            }
        }

        if (c + 2 < NC) issue_stage(c + 2, nbuf);
        else            CP_COMMIT();

        buf  = (buf  == 2) ? 0 : buf  + 1;
        nbuf = (nbuf == 2) ? 0 : nbuf + 1;
    }

    // ---- epilogue ----
    if (SKRED) {
#pragma unroll
        for (int mi = 0; mi < 4; mi++) {
            float p0 = 0.0f, p1 = 0.0f;
#pragma unroll
            for (int ni = 0; ni < 4; ni++) {
                const int n = n0 + wn * 32 + ni * 8 + 2 * t;
                const float q0 = qvec[n], q1 = qvec[n + 1];
                p0 += tanhf(acc[mi][ni][0]) * q0 + tanhf(acc[mi][ni][1]) * q1;
                p1 += tanhf(acc[mi][ni][2]) * q0 + tanhf(acc[mi][ni][3]) * q1;
            }
            p0 += __shfl_xor_sync(0xffffffffu, p0, 1);
            p0 += __shfl_xor_sync(0xffffffffu, p0, 2);
            p1 += __shfl_xor_sync(0xffffffffu, p1, 1);
            p1 += __shfl_xor_sync(0xffffffffu, p1, 2);
            if (t == 0) {
                const int m_lo = m0 + wm * 64 + mi * 16 + g;
                const int slot = blockIdx.x * 4 + wn;
                TP[(long long)m_lo * 32 + slot]       = p0;
                TP[(long long)(m_lo + 8) * 32 + slot] = p1;
            }
        }
        return;
    }

#pragma unroll
    for (int mi = 0; mi < 4; mi++) {
        const int m_lo = m0 + wm * 64 + mi * 16 + g;
        const int m_hi = m_lo + 8;
        const float* pe_lo = posenc ? posenc + (long long)(m_lo & (SEQL - 1)) * N : 0;
        const float* pe_hi = posenc ? posenc + (long long)(m_hi & (SEQL - 1)) * N : 0;
#pragma unroll
        for (int ni = 0; ni < 4; ni++) {
            const int n = n0 + wn * 32 + ni * 8 + 2 * t;
            float2 v0, v1;
            v0.x = acc[mi][ni][0] * alpha;
            v0.y = acc[mi][ni][1] * alpha;
            v1.x = acc[mi][ni][2] * alpha;
            v1.y = acc[mi][ni][3] * alpha;
            if (bias) {
                const float b0 = bias[n], b1 = bias[n + 1];
                v0.x += b0; v0.y += b1;
                v1.x += b0; v1.y += b1;
            }
            if (posenc) {
                v0.x += pe_lo[n]; v0.y += pe_lo[n + 1];
                v1.x += pe_hi[n]; v1.y += pe_hi[n + 1];
            }
            if (FTRANS) {
                // V^T fp32: out[b][n][s], m = b*SEQL + s; DMODEL*SEQL = 1<<21
                const long long base_lo = ((long long)(m_lo >> 11) << 21) + (m_lo & 2047);
                const long long base_hi = ((long long)(m_hi >> 11) << 21) + (m_hi & 2047);
                Cf[base_lo + (long long)n * SEQL]       = v0.x;
                Cf[base_lo + (long long)(n + 1) * SEQL] = v0.y;
                Cf[base_hi + (long long)n * SEQL]       = v1.x;
                Cf[base_hi + (long long)(n + 1) * SEQL] = v1.y;
                continue;
            }
            if (F32OUT) {
                *(float2*)(Cf + (long long)m_lo * N + n) = v0;
                *(float2*)(Cf + (long long)m_hi * N + n) = v1;
            }
            if (SPLITOUT) {
                u32 h, l;
                split_pack(v0.x, v0.y, h, l);
                *(u32*)(Chi + (long long)m_lo * N + n) = h;
                *(u32*)(Clo + (long long)m_lo * N + n) = l;
                split_pack(v1.x, v1.y, h, l);
                *(u32*)(Chi + (long long)m_hi * N + n) = h;
                *(u32*)(Clo + (long long)m_hi * N + n) = l;
            }
        }
    }
}

// ---------------------------------------------------------------------------
// tf32 GEMM (single-term) on fp32 operands:
//   C[m,n] = alpha * sum_k A[m,k]*B[n,k]
// A [M][K] fp32, B [N][K] fp32. Tile 128x128x32, 256 thr, 8 warps (2x4),
// warp tile 64x32. Padded-stride fp32 smem tiles (36 floats/row, conflict-
// free scalar fragment loads), cvt.rna.tf32 in-register, m16n8k8 MMAs.
// Same 3-buffer / one-barrier / load-after-compute cadence as tc_gemm.
// ---------------------------------------------------------------------------
#define TF_STRIDE       36
#define TF_TILE_FLOATS  (128 * TF_STRIDE)      // 4608
#define TF_STAGE_FLOATS (2 * TF_TILE_FLOATS)   // 9216
#define DYN_SMEM_T      (3 * TF_STAGE_FLOATS * 4)  // 110592

__global__ __launch_bounds__(256, 2)
void tf32_gemm(const float* __restrict__ A, const float* __restrict__ B,
               float* __restrict__ C, int N, int K,
               long long sA, long long sB, long long sC, float alpha)
{
    extern __shared__ float smf[];

    const int tid  = threadIdx.x;
    const int wid  = tid >> 5;
    const int lane = tid & 31;
    const int wm   = wid >> 2;
    const int wn   = wid & 3;
    const int g    = lane >> 2;
    const int t    = lane & 3;

    const int bz = blockIdx.z;
    A += bz * sA; B += bz * sB; C += bz * sC;
    const int m0 = blockIdx.y * 128;
    const int n0 = blockIdx.x * 128;

    const u32 smem_base = smem_u32(smf);

    float acc[4][4][4];
#pragma unroll
    for (int mi = 0; mi < 4; mi++)
#pragma unroll
        for (int ni = 0; ni < 4; ni++)
#pragma unroll
            for (int c = 0; c < 4; c++) acc[mi][ni][c] = 0.0f;

    const int NC = K >> 5;

    auto issue_stage = [&](int c, int buf) {
        const int k0 = c * 32;
        const u32 st = smem_base + (buf * TF_STAGE_FLOATS) * 4;
#pragma unroll
        for (int i = 0; i < 4; i++) {
            const int e   = tid + i * 256;
            const int row = e >> 3;
            const int q   = e & 7;
            cp_async16(st + (row * TF_STRIDE + q * 4) * 4,
                       A + (long long)(m0 + row) * K + k0 + q * 4);
        }
#pragma unroll
        for (int i = 0; i < 4; i++) {
            const int e   = tid + i * 256;
            const int row = e >> 3;
            const int q   = e & 7;
            cp_async16(st + (TF_TILE_FLOATS + row * TF_STRIDE + q * 4) * 4,
                       B + (long long)(n0 + row) * K + k0 + q * 4);
        }
        CP_COMMIT();
    };

    issue_stage(0, 0);
    issue_stage(1, 1);

    int buf = 0;
    int nbuf = 2;
    for (int c = 0; c < NC; ++c) {
        CP_WAIT1();
        __syncthreads();

        const float* As = smf + buf * TF_STAGE_FLOATS;
        const float* Bs = As + TF_TILE_FLOATS;

#pragma unroll
        for (int ks = 0; ks < 4; ks++) {
            const int kk = ks * 8;
            u32 bf[4][2];
#pragma unroll
            for (int ni = 0; ni < 4; ni++) {
                const float* b = Bs + (wn * 32 + ni * 8 + g) * TF_STRIDE + kk;
                bf[ni][0] = f2tf32(b[t]);
                bf[ni][1] = f2tf32(b[t + 4]);
            }
#pragma unroll
            for (int mp = 0; mp < 2; mp++) {
                u32 af[2][4];
#pragma unroll
                for (int q = 0; q < 2; q++) {
                    const int mi = mp * 2 + q;
                    const float* a = As + (wm * 64 + mi * 16 + g) * TF_STRIDE + kk;
                    af[q][0] = f2tf32(a[t]);
                    af[q][1] = f2tf32(a[8 * TF_STRIDE + t]);
                    af[q][2] = f2tf32(a[t + 4]);
                    af[q][3] = f2tf32(a[8 * TF_STRIDE + t + 4]);
                }
#pragma unroll
                for (int q = 0; q < 2; q++)
#pragma unroll
                    for (int ni = 0; ni < 4; ni++)
                        mma_tf32(acc[mp*2+q][ni], af[q], bf[ni]);
            }
        }

        if (c + 2 < NC) issue_stage(c + 2, nbuf);
        else            CP_COMMIT();

        buf  = (buf  == 2) ? 0 : buf  + 1;
        nbuf = (nbuf == 2) ? 0 : nbuf + 1;
    }

    // fp32 epilogue
#pragma unroll
    for (int mi = 0; mi < 4; mi++) {
        const int m_lo = m0 + wm * 64 + mi * 16 + g;
        const int m_hi = m_lo + 8;
#pragma unroll
        for (int ni = 0; ni < 4; ni++) {
            const int n = n0 + wn * 32 + ni * 8 + 2 * t;
            float2 v0, v1;
            v0.x = acc[mi][ni][0] * alpha;
            v0.y = acc[mi][ni][1] * alpha;
            v1.x = acc[mi][ni][2] * alpha;
            v1.y = acc[mi][ni][3] * alpha;
            *(float2*)(C + (long long)m_lo * N + n) = v0;
            *(float2*)(C + (long long)m_hi * N + n) = v1;
        }
    }
}

// ---------------------------------------------------------------------------
// fp32 -> split bf16 hi/lo planes (4 elems per thread)
// ---------------------------------------------------------------------------
__global__ void split_fp32(const float* __restrict__ src,
                           u16* __restrict__ hi, u16* __restrict__ lo, int n4)
{
    const int i = blockIdx.x * blockDim.x + threadIdx.x;
    if (i >= n4) return;
    const float4 v = ((const float4*)src)[i];
    u32 h01, l01, h23, l23;
    split_pack(v.x, v.y, h01, l01);
    split_pack(v.z, v.w, h23, l23);
    ((uint2*)hi)[i] = make_uint2(h01, h23);
    ((uint2*)lo)[i] = make_uint2(l01, l23);
}

// ---------------------------------------------------------------------------
// Plain fp32 row softmax, in place, row length 2048
// ---------------------------------------------------------------------------
__global__ void softmax_rows(float* __restrict__ S)
{
    float* row = S + (long long)blockIdx.x * 2048;
    const int tid = threadIdx.x;
    __shared__ float red[256];

    float v[8];
    *(float4*)&v[0] = *(const float4*)(row + tid * 8);
    *(float4*)&v[4] = *(const float4*)(row + tid * 8 + 4);

    float mx = -1e30f;
#pragma unroll
    for (int i = 0; i < 8; i++) mx = fmaxf(mx, v[i]);
    red[tid] = mx; __syncthreads();
    for (int s = 128; s > 0; s >>= 1) {
        if (tid < s) red[tid] = fmaxf(red[tid], red[tid + s]);
        __syncthreads();
    }
    mx = red[0]; __syncthreads();

    float sum = 0.0f;
#pragma unroll
    for (int i = 0; i < 8; i++) { v[i] = __expf(v[i] - mx); sum += v[i]; }
    red[tid] = sum; __syncthreads();
    for (int s = 128; s > 0; s >>= 1) {
        if (tid < s) red[tid] += red[tid + s];
        __syncthreads();
    }
    const float inv = 1.0f / red[0];
#pragma unroll
    for (int i = 0; i < 8; i++) v[i] *= inv;
    *(float4*)(row + tid * 8)     = *(float4*)&v[0];
    *(float4*)(row + tid * 8 + 4) = *(float4*)&v[4];
}

// ---------------------------------------------------------------------------
// h = x + z ; H = LN(h)*g + b  -> fp32 H + split planes
// ---------------------------------------------------------------------------
__global__ void add_ln_split(const float* __restrict__ X, const float* __restrict__ Z,
                             const float* __restrict__ g, const float* __restrict__ b,
                             float* __restrict__ H, u16* __restrict__ hi, u16* __restrict__ lo)
{
    const long long r = blockIdx.x;
    const int tid = threadIdx.x;
    const int c0  = tid * 4;
    const float* xr = X + r * DMODEL;
    const float* zr = Z + r * DMODEL;
    __shared__ float red[256];

    float4 x4 = *(const float4*)(xr + c0);
    float4 z4 = *(const float4*)(zr + c0);
    float h[4] = { x4.x + z4.x, x4.y + z4.y, x4.z + z4.z, x4.w + z4.w };

    float sum = h[0] + h[1] + h[2] + h[3];
    red[tid] = sum; __syncthreads();
    for (int s = 128; s > 0; s >>= 1) {
        if (tid < s) red[tid] += red[tid + s];
        __syncthreads();
    }
    const float mean = red[0] * (1.0f / DMODEL);
    __syncthreads();

    float vs = 0.0f;
#pragma unroll
    for (int i = 0; i < 4; i++) { const float d = h[i] - mean; vs += d * d; }
    red[tid] = vs; __syncthreads();
    for (int s = 128; s > 0; s >>= 1) {
        if (tid < s) red[tid] += red[tid + s];
        __syncthreads();
    }
    const float inv = rsqrtf(red[0] * (1.0f / DMODEL) + LN_EPS);

    float4 o;
    o.x = (h[0] - mean) * inv * g[c0 + 0] + b[c0 + 0];
    o.y = (h[1] - mean) * inv * g[c0 + 1] + b[c0 + 1];
    o.z = (h[2] - mean) * inv * g[c0 + 2] + b[c0 + 2];
    o.w = (h[3] - mean) * inv * g[c0 + 3] + b[c0 + 3];
    *(float4*)(H + r * DMODEL + c0) = o;

    u32 h01, l01, h23, l23;
    split_pack(o.x, o.y, h01, l01);
    split_pack(o.z, o.w, h23, l23);
    const long long pi = (r * DMODEL + c0) >> 1;
    ((u32*)hi)[pi]     = h01;
    ((u32*)hi)[pi + 1] = h23;
    ((u32*)lo)[pi]     = l01;
    ((u32*)lo)[pi + 1] = l23;
}

// ---------------------------------------------------------------------------
// T[r] = sum of 32 soft-key partials (deterministic fixed-order reduce)
// ---------------------------------------------------------------------------
__global__ void skt_reduce(const float* __restrict__ TP, float* __restrict__ T)
{
    const int r = blockIdx.x * 256 + threadIdx.x;
    const float* p = TP + (long long)r * 32;
    float s = 0.0f;
#pragma unroll
    for (int j = 0; j < 32; j++) s += p[j];
    T[r] = s;
}

// ---------------------------------------------------------------------------
// final_out stage 1: partial over 256-row s-chunk
// ---------------------------------------------------------------------------
__global__ void final_partial(const float* __restrict__ H, const float* __restrict__ w,
                              float* __restrict__ OP)
{
    const int b  = blockIdx.y;
    const int zc = blockIdx.z;
    const int o  = blockIdx.x * 256 + threadIdx.x;
    const float* Hp = H + (long long)b * SEQL * DMODEL
                        + (long long)(zc * 256) * DMODEL + o;
    const float* wb = w + (long long)b * SEQL + zc * 256;

    float a0 = 0.0f, a1 = 0.0f, a2 = 0.0f, a3 = 0.0f;
    for (int s = 0; s < 256; s += 4) {
        a0 += wb[s + 0] * Hp[(long long)(s + 0) * DMODEL];
        a1 += wb[s + 1] * Hp[(long long)(s + 1) * DMODEL];
        a2 += wb[s + 2] * Hp[(long long)(s + 2) * DMODEL];
        a3 += wb[s + 3] * Hp[(long long)(s + 3) * DMODEL];
    }
    OP[(long long)(b * 8 + zc) * DMODEL + o] = (a0 + a1) + (a2 + a3);
}

// final_out stage 2
__global__ void final_reduce(const float* __restrict__ OP, float* __restrict__ out)
{
    const int b = blockIdx.y;
    const int o = blockIdx.x * 256 + threadIdx.x;
    float s = 0.0f;
#pragma unroll
    for (int z = 0; z < 8; z++)
        s += OP[(long long)(b * 8 + z) * DMODEL + o];
    out[b * DMODEL + o] = s;
}

// ---------------------------------------------------------------------------
// Launch
// ---------------------------------------------------------------------------
extern "C" void kernel_launch(void* const* d_in, const int* in_sizes, int n_in,
                              void* d_out, int out_size)
{
    const float* inputs  = (const float*)d_in[0];
    const float* embed_w = (const float*)d_in[1];
    const float* embed_b = (const float*)d_in[2];
    const float* wq_w    = (const float*)d_in[3];
    const float* wq_b    = (const float*)d_in[4];
    const float* wk_w    = (const float*)d_in[5];
    const float* wk_b    = (const float*)d_in[6];
    const float* wv_w    = (const float*)d_in[7];
    const float* wv_b    = (const float*)d_in[8];
    const float* ln_g    = (const float*)d_in[9];
    const float* ln_b    = (const float*)d_in[10];
    const float* skw     = (const float*)d_in[11];
    const float* sq      = (const float*)d_in[12];
    const float* pos     = (const float*)d_in[13];
    float* out = (float*)d_out;

    cudaFuncSetAttribute((const void*)tc_gemm<true,  true,  false, false>,
                         cudaFuncAttributeMaxDynamicSharedMemorySize, DYN_SMEM_G);
    cudaFuncSetAttribute((const void*)tc_gemm<true,  false, false, false>,
                         cudaFuncAttributeMaxDynamicSharedMemorySize, DYN_SMEM_G);
    cudaFuncSetAttribute((const void*)tc_gemm<false, false, true,  false>,
                         cudaFuncAttributeMaxDynamicSharedMemorySize, DYN_SMEM_G);
    cudaFuncSetAttribute((const void*)tc_gemm<false, false, false, true>,
                         cudaFuncAttributeMaxDynamicSharedMemorySize, DYN_SMEM_G);
    cudaFuncSetAttribute((const void*)tf32_gemm,
                         cudaFuncAttributeMaxDynamicSharedMemorySize, DYN_SMEM_T);

    float* base = 0;
    cudaGetSymbolAddress((void**)&base, g_scratch);

    u16* INh  = (u16*)(base + O_INS);   u16* INl  = INh  + C_IN;
    u16* EWh  = (u16*)(base + O_EWS);   u16* EWl  = EWh  + C_EW;
    u16* WQh  = (u16*)(base + O_WQS);   u16* WQl  = WQh  + C_W;
    u16* WKh  = (u16*)(base + O_WKS);   u16* WKl  = WKh  + C_W;
    u16* WVh  = (u16*)(base + O_WVS);   u16* WVl  = WVh  + C_W;
    u16* SKWh = (u16*)(base + O_SKWS);  u16* SKWl = SKWh + C_W;
    float* X  = base + O_X;
    u16* Xh   = (u16*)(base + O_XS);    u16* Xl   = Xh   + C_MAT;
    float* Q  = base + O_Q;
    float* K  = base + O_K;
    float* VT = base + O_VT;
    float* SC = base + O_SC;
    float* Z  = base + O_Z;
    float* H  = base + O_H;
    u16* Hh   = (u16*)(base + O_HS);    u16* Hl   = Hh   + C_MAT;
    float* TP = base + O_TP;
    float* OP = base + O_OP;
    float* T  = base + O_T;

    // 0) splits (5 launches here so the 6th launch — profiled by ncu — is the
    //    embed GEMM; skw split is deferred until after it)
    split_fp32<<<(int)(C_IN / 4 / 256), 256>>>(inputs,  INh,  INl,  (int)(C_IN / 4));
    split_fp32<<<(int)(C_EW / 4 / 256), 256>>>(embed_w, EWh,  EWl,  (int)(C_EW / 4));
    split_fp32<<<(int)(C_W  / 4 / 256), 256>>>(wq_w,    WQh,  WQl,  (int)(C_W  / 4));
    split_fp32<<<(int)(C_W  / 4 / 256), 256>>>(wk_w,    WKh,  WKl,  (int)(C_W  / 4));
    split_fp32<<<(int)(C_W  / 4 / 256), 256>>>(wv_w,    WVh,  WVl,  (int)(C_W  / 4));

    // 1) embed: X = inputs @ embed_w^T + embed_b + pos_enc  (fp32 + split out)
    tc_gemm<true, true, false, false><<<dim3(DMODEL / 128, NROW / 128, 1), 256, DYN_SMEM_G>>>(
        INh, INl, EWh, EWl, X, Xh, Xl, 0, 0,
        DMODEL, D_IN, 0, 0, 0, 1.0f, embed_b, pos);

    split_fp32<<<(int)(C_W / 4 / 256), 256>>>(skw, SKWh, SKWl, (int)(C_W / 4));

    // 2) Q, K (fp32 out), V (fp32 transposed out)
    tc_gemm<true, false, false, false><<<dim3(DMODEL / 128, NROW / 128, 1), 256, DYN_SMEM_G>>>(
        Xh, Xl, WQh, WQl, Q, 0, 0, 0, 0,
        DMODEL, DMODEL, 0, 0, 0, 1.0f, wq_b, 0);
    tc_gemm<true, false, false, false><<<dim3(DMODEL / 128, NROW / 128, 1), 256, DYN_SMEM_G>>>(
        Xh, Xl, WKh, WKl, K, 0, 0, 0, 0,
        DMODEL, DMODEL, 0, 0, 0, 1.0f, wk_b, 0);
    tc_gemm<false, false, true, false><<<dim3(DMODEL / 128, NROW / 128, 1), 256, DYN_SMEM_G>>>(
        Xh, Xl, WVh, WVl, VT, 0, 0, 0, 0,
        DMODEL, DMODEL, 0, 0, 0, 1.0f, wv_b, 0);

    // 3) scores = Q @ K^T / 32 (batched, tf32)
    tf32_gemm<<<dim3(SEQL / 128, SEQL / 128, BATCH), 256, DYN_SMEM_T>>>(
        Q, K, SC, SEQL, DMODEL,
        (long long)SEQL * DMODEL, (long long)SEQL * DMODEL, (long long)SEQL * SEQL,
        1.0f / 32.0f);

    // 4) softmax in place (fp32)
    softmax_rows<<<NROW, 256>>>(SC);

    // 5) Z = softmax(SC) @ V  (tf32; B = V^T fp32 [n][s] per batch)
    tf32_gemm<<<dim3(DMODEL / 128, SEQL / 128, BATCH), 256, DYN_SMEM_T>>>(
        SC, VT, Z, DMODEL, SEQL,
        (long long)SEQL * SEQL, (long long)DMODEL * SEQL, (long long)SEQL * DMODEL,
        1.0f);

    // 6) H = LN(X + Z)*g + b  (fp32 + split)
    add_ln_split<<<NROW, 256>>>(X, Z, ln_g, ln_b, H, Hh, Hl);

    // 7) fused SK GEMM + tanh·q partial reduction -> TP
    tc_gemm<false, false, false, true><<<dim3(DMODEL / 128, NROW / 128, 1), 256, DYN_SMEM_G>>>(
        Hh, Hl, SKWh, SKWl, 0, 0, 0, TP, sq,
        DMODEL, DMODEL, 0, 0, 0, 1.0f, 0, 0);

    // 8) T[r] = sum partials; softmax over s per batch
    skt_reduce<<<NROW / 256, 256>>>(TP, T);
    softmax_rows<<<BATCH, 256>>>(T);

    // 9) out[b,o] = sum_s w[b,s] * H[b,s,o]  (two-stage, deterministic)
    final_partial<<<dim3(DMODEL / 256, BATCH, 8), 256>>>(H, T, OP);
    final_reduce<<<dim3(DMODEL / 256, BATCH), 256>>>(OP, out);
}

// round 12
// speedup vs baseline: 1.3457x; 1.0668x over previous
#include <cuda_runtime.h>
#include <cstdint>
#include <math.h>

// ---------------------------------------------------------------------------
// Problem constants
// ---------------------------------------------------------------------------
#define BATCH   8
#define SEQL    2048
#define D_IN    512
#define DMODEL  1024
#define NROW    (BATCH * SEQL)          // 16384
#define LN_EPS  1e-5f

typedef unsigned short u16;
typedef uint32_t u32;

// element counts
static const long long C_IN  = (long long)NROW * D_IN;       // 8388608
static const long long C_EW  = (long long)DMODEL * D_IN;     // 524288
static const long long C_MAT = (long long)NROW * DMODEL;     // 16777216
static const long long C_SC  = (long long)BATCH * SEQL * SEQL; // 33554432

// scratch offsets (in floats)
#define O_INS   (0LL)
#define O_EWS   (O_INS  + C_IN)
#define O_X     (O_EWS  + C_EW)
#define O_Q     (O_X    + C_MAT)
#define O_K     (O_Q    + C_MAT)
#define O_VT    (O_K    + C_MAT)        // fp32 V^T (per batch [n][s])
#define O_SC    (O_VT   + C_MAT)
#define O_Z     (O_SC   + C_SC)
#define O_H     (O_Z    + C_MAT)
#define O_TP    (O_H    + C_MAT)                 // soft-key partials [16384][32]
#define O_OP    (O_TP   + 16384LL * 32)          // final_out partials [64][1024]
#define O_T     (O_OP   + 65536)
#define O_TOTAL (O_T    + 16384)

__device__ float g_scratch[O_TOTAL];

// ---------------------------------------------------------------------------
// PTX helpers (baseline sm_80+ features only — harness targets plain sm_103)
// ---------------------------------------------------------------------------
__device__ __forceinline__ u32 smem_u32(const void* p) {
    u32 a;
    asm("{ .reg .u64 t; cvta.to.shared.u64 t, %1; cvt.u32.u64 %0, t; }"
        : "=r"(a) : "l"(p));
    return a;
}

__device__ __forceinline__ void cp_async16(u32 dst, const void* src) {
    asm volatile("cp.async.cg.shared.global [%0], [%1], 16;" :: "r"(dst), "l"(src));
}
#define CP_COMMIT() asm volatile("cp.async.commit_group;" ::: "memory")
#define CP_WAIT1()  asm volatile("cp.async.wait_group 1;"  ::: "memory")

// split x0,x1 (fp32) into packed bf16x2 hi and lo parts: x = hi + lo
__device__ __forceinline__ void split_pack(float x0, float x1, u32& hi, u32& lo) {
    asm("cvt.rn.bf16x2.f32 %0, %1, %2;" : "=r"(hi) : "f"(x1), "f"(x0));
    const float h0 = __uint_as_float(hi << 16);
    const float h1 = __uint_as_float(hi & 0xFFFF0000u);
    const float l0 = x0 - h0;
    const float l1 = x1 - h1;
    asm("cvt.rn.bf16x2.f32 %0, %1, %2;" : "=r"(lo) : "f"(l1), "f"(l0));
}

__device__ __forceinline__ u32 f2tf32(float f) {
    u32 r;
    asm("cvt.rna.tf32.f32 %0, %1;" : "=r"(r) : "f"(f));
    return r;
}

// D += A*B  (m16n8k16 bf16, fp32 accum)
__device__ __forceinline__ void mma_bf16(float* d, const u32* a, const u32* b) {
    asm volatile(
        "mma.sync.aligned.m16n8k16.row.col.f32.bf16.bf16.f32 "
        "{%0,%1,%2,%3}, {%4,%5,%6,%7}, {%8,%9}, {%0,%1,%2,%3};"
        : "+f"(d[0]), "+f"(d[1]), "+f"(d[2]), "+f"(d[3])
        : "r"(a[0]), "r"(a[1]), "r"(a[2]), "r"(a[3]), "r"(b[0]), "r"(b[1]));
}

// D += A*B  (m16n8k8 tf32, fp32 accum)
__device__ __forceinline__ void mma_tf32(float* d, const u32* a, const u32* b) {
    asm volatile(
        "mma.sync.aligned.m16n8k8.row.col.f32.tf32.tf32.f32 "
        "{%0,%1,%2,%3}, {%4,%5,%6,%7}, {%8,%9}, {%0,%1,%2,%3};"
        : "+f"(d[0]), "+f"(d[1]), "+f"(d[2]), "+f"(d[3])
        : "r"(a[0]), "r"(a[1]), "r"(a[2]), "r"(a[3]), "r"(b[0]), "r"(b[1]));
}

__device__ __forceinline__ void ldmat4(u32& r0, u32& r1, u32& r2, u32& r3, u32 addr) {
    asm volatile("ldmatrix.sync.aligned.m8n8.x4.shared.b16 {%0,%1,%2,%3}, [%4];"
                 : "=r"(r0), "=r"(r1), "=r"(r2), "=r"(r3) : "r"(addr));
}

// swizzled byte offset of (row, 16B-chunk ch) in a 128x32 bf16 plane (64B rows)
__device__ __forceinline__ u32 sw_off(u32 row, u32 ch) {
    return row * 64u + ((ch ^ ((row >> 1) & 3u)) << 4);
}

// ---------------------------------------------------------------------------
// bf16x3 split GEMM (embed only now): C = A@B^T + bias + posenc, fp32 out.
// R7/R10 proven cadence: 3-buffer, one barrier/chunk, load-after-compute.
// ---------------------------------------------------------------------------
#define PLANE_B  (128 * 64)             // 8192
#define STAGE_B  (4 * PLANE_B)          // 32768
#define DYN_SMEM_G (3 * STAGE_B)        // 98304

__global__ __launch_bounds__(256, 2)
void bf16x3_gemm(const u16* __restrict__ Ahi, const u16* __restrict__ Alo,
                 const u16* __restrict__ Bhi, const u16* __restrict__ Blo,
                 float* __restrict__ Cf,
                 int N, int K,
                 const float* __restrict__ bias,
                 const float* __restrict__ posenc)
{
    extern __shared__ char smem[];

    const int tid  = threadIdx.x;
    const int wid  = tid >> 5;
    const int lane = tid & 31;
    const int wm   = wid >> 2;
    const int wn   = wid & 3;
    const int g    = lane >> 2;
    const int t    = lane & 3;
    const int lrow = lane & 15;
    const int lch  = lane >> 4;

    const int m0 = blockIdx.y * 128;
    const int n0 = blockIdx.x * 128;

    const u32 smem_base = smem_u32(smem);

    float acc[4][4][4];
#pragma unroll
    for (int mi = 0; mi < 4; mi++)
#pragma unroll
        for (int ni = 0; ni < 4; ni++)
#pragma unroll
            for (int c = 0; c < 4; c++) acc[mi][ni][c] = 0.0f;

    const int NC = K >> 5;

    const u32 ld_row = (u32)(tid >> 2);
    const u32 ld_ch  = (u32)(tid & 3);

    auto issue_stage = [&](int c, int buf) {
        const int k0 = c * 32;
        const u32 st = smem_base + buf * STAGE_B;
        const u16* srcs[4] = { Ahi, Alo, Bhi, Blo };
#pragma unroll
        for (int p = 0; p < 4; p++) {
            const u16* src = srcs[p];
            const int rbase = (p < 2) ? m0 : n0;
#pragma unroll
            for (int i = 0; i < 2; i++) {
                const u32 row = ld_row + i * 64;
                cp_async16(st + p * PLANE_B + sw_off(row, ld_ch),
                           src + (long long)(rbase + row) * K + k0 + ld_ch * 8);
            }
        }
        CP_COMMIT();
    };

    issue_stage(0, 0);
    issue_stage(1, 1);

    int buf = 0;
    int nbuf = 2;
    for (int c = 0; c < NC; ++c) {
        CP_WAIT1();
        __syncthreads();

        const u32 st = smem_base + buf * STAGE_B;

#pragma unroll
        for (int half = 0; half < 2; half++) {
            const u32 ch = (u32)(half * 2 + lch);

            u32 bh[4][2], bl[4][2];
#pragma unroll
            for (int nj = 0; nj < 2; nj++) {
                const u32 rb = sw_off((u32)(wn * 32 + nj * 16 + lrow), ch);
                u32 r0, r1, r2, r3;
                ldmat4(r0, r1, r2, r3, st + 2 * PLANE_B + rb);
                bh[2*nj][0] = r0; bh[2*nj+1][0] = r1;
                bh[2*nj][1] = r2; bh[2*nj+1][1] = r3;
                ldmat4(r0, r1, r2, r3, st + 3 * PLANE_B + rb);
                bl[2*nj][0] = r0; bl[2*nj+1][0] = r1;
                bl[2*nj][1] = r2; bl[2*nj+1][1] = r3;
            }

#pragma unroll
            for (int mp = 0; mp < 2; mp++) {
                u32 ah[2][4], al[2][4];
#pragma unroll
                for (int q = 0; q < 2; q++) {
                    const int mi = mp * 2 + q;
                    const u32 ra = sw_off((u32)(wm * 64 + mi * 16 + lrow), ch);
                    ldmat4(ah[q][0], ah[q][1], ah[q][2], ah[q][3], st + ra);
                    ldmat4(al[q][0], al[q][1], al[q][2], al[q][3], st + PLANE_B + ra);
                }
#pragma unroll
                for (int q = 0; q < 2; q++)
#pragma unroll
                    for (int ni = 0; ni < 4; ni++)
                        mma_bf16(acc[mp*2+q][ni], ah[q], bh[ni]);
#pragma unroll
                for (int q = 0; q < 2; q++)
#pragma unroll
                    for (int ni = 0; ni < 4; ni++)
                        mma_bf16(acc[mp*2+q][ni], ah[q], bl[ni]);
#pragma unroll
                for (int q = 0; q < 2; q++)
#pragma unroll
                    for (int ni = 0; ni < 4; ni++)
                        mma_bf16(acc[mp*2+q][ni], al[q], bh[ni]);
            }
        }

        if (c + 2 < NC) issue_stage(c + 2, nbuf);
        else            CP_COMMIT();

        buf  = (buf  == 2) ? 0 : buf  + 1;
        nbuf = (nbuf == 2) ? 0 : nbuf + 1;
    }

#pragma unroll
    for (int mi = 0; mi < 4; mi++) {
        const int m_lo = m0 + wm * 64 + mi * 16 + g;
        const int m_hi = m_lo + 8;
        const float* pe_lo = posenc + (long long)(m_lo & (SEQL - 1)) * N;
        const float* pe_hi = posenc + (long long)(m_hi & (SEQL - 1)) * N;
#pragma unroll
        for (int ni = 0; ni < 4; ni++) {
            const int n = n0 + wn * 32 + ni * 8 + 2 * t;
            const float b0 = bias[n], b1 = bias[n + 1];
            float2 v0, v1;
            v0.x = acc[mi][ni][0] + b0 + pe_lo[n];
            v0.y = acc[mi][ni][1] + b1 + pe_lo[n + 1];
            v1.x = acc[mi][ni][2] + b0 + pe_hi[n];
            v1.y = acc[mi][ni][3] + b1 + pe_hi[n + 1];
            *(float2*)(Cf + (long long)m_lo * N + n) = v0;
            *(float2*)(Cf + (long long)m_hi * N + n) = v1;
        }
    }
}

// ---------------------------------------------------------------------------
// tf32 GEMM (single-term) on fp32 operands:
//   C[m,n] = alpha * sum_k A[m,k]*B[n,k]  (+bias)
// Tile 128x128x32, 256 thr, warp tile 64x32, padded-stride fp32 smem,
// cvt.rna.tf32 in-register, m16n8k8 MMAs, proven 3-buffer cadence.
//   FTRANS: write C transposed per batch: out[b][n][s], m = b*SEQL + s
//   SKRED:  fused soft-key epilogue (partials of sum tanh(C)*q)
// ---------------------------------------------------------------------------
#define TF_STRIDE       36
#define TF_TILE_FLOATS  (128 * TF_STRIDE)      // 4608
#define TF_STAGE_FLOATS (2 * TF_TILE_FLOATS)   // 9216
#define DYN_SMEM_T      (3 * TF_STAGE_FLOATS * 4)  // 110592

template <bool FTRANS, bool SKRED>
__global__ __launch_bounds__(256, 2)
void tf32_gemm(const float* __restrict__ A, const float* __restrict__ B,
               float* __restrict__ C,
               float* __restrict__ TP, const float* __restrict__ qvec,
               int N, int K,
               long long sA, long long sB, long long sC,
               float alpha, const float* __restrict__ bias)
{
    extern __shared__ float smf[];

    const int tid  = threadIdx.x;
    const int wid  = tid >> 5;
    const int lane = tid & 31;
    const int wm   = wid >> 2;
    const int wn   = wid & 3;
    const int g    = lane >> 2;
    const int t    = lane & 3;

    const int bz = blockIdx.z;
    A += bz * sA; B += bz * sB; C += bz * sC;
    const int m0 = blockIdx.y * 128;
    const int n0 = blockIdx.x * 128;

    const u32 smem_base = smem_u32(smf);

    float acc[4][4][4];
#pragma unroll
    for (int mi = 0; mi < 4; mi++)
#pragma unroll
        for (int ni = 0; ni < 4; ni++)
#pragma unroll
            for (int c = 0; c < 4; c++) acc[mi][ni][c] = 0.0f;

    const int NC = K >> 5;

    auto issue_stage = [&](int c, int buf) {
        const int k0 = c * 32;
        const u32 st = smem_base + (buf * TF_STAGE_FLOATS) * 4;
#pragma unroll
        for (int i = 0; i < 4; i++) {
            const int e   = tid + i * 256;
            const int row = e >> 3;
            const int q   = e & 7;
            cp_async16(st + (row * TF_STRIDE + q * 4) * 4,
                       A + (long long)(m0 + row) * K + k0 + q * 4);
        }
#pragma unroll
        for (int i = 0; i < 4; i++) {
            const int e   = tid + i * 256;
            const int row = e >> 3;
            const int q   = e & 7;
            cp_async16(st + (TF_TILE_FLOATS + row * TF_STRIDE + q * 4) * 4,
                       B + (long long)(n0 + row) * K + k0 + q * 4);
        }
        CP_COMMIT();
    };

    issue_stage(0, 0);
    issue_stage(1, 1);

    int buf = 0;
    int nbuf = 2;
    for (int c = 0; c < NC; ++c) {
        CP_WAIT1();
        __syncthreads();

        const float* As = smf + buf * TF_STAGE_FLOATS;
        const float* Bs = As + TF_TILE_FLOATS;

#pragma unroll
        for (int ks = 0; ks < 4; ks++) {
            const int kk = ks * 8;
            u32 bf[4][2];
#pragma unroll
            for (int ni = 0; ni < 4; ni++) {
                const float* b = Bs + (wn * 32 + ni * 8 + g) * TF_STRIDE + kk;
                bf[ni][0] = f2tf32(b[t]);
                bf[ni][1] = f2tf32(b[t + 4]);
            }
#pragma unroll
            for (int mp = 0; mp < 2; mp++) {
                u32 af[2][4];
#pragma unroll
                for (int q = 0; q < 2; q++) {
                    const int mi = mp * 2 + q;
                    const float* a = As + (wm * 64 + mi * 16 + g) * TF_STRIDE + kk;
                    af[q][0] = f2tf32(a[t]);
                    af[q][1] = f2tf32(a[8 * TF_STRIDE + t]);
                    af[q][2] = f2tf32(a[t + 4]);
                    af[q][3] = f2tf32(a[8 * TF_STRIDE + t + 4]);
                }
#pragma unroll
                for (int q = 0; q < 2; q++)
#pragma unroll
                    for (int ni = 0; ni < 4; ni++)
                        mma_tf32(acc[mp*2+q][ni], af[q], bf[ni]);
            }
        }

        if (c + 2 < NC) issue_stage(c + 2, nbuf);
        else            CP_COMMIT();

        buf  = (buf  == 2) ? 0 : buf  + 1;
        nbuf = (nbuf == 2) ? 0 : nbuf + 1;
    }

    // ---- epilogue ----
    if (SKRED) {
#pragma unroll
        for (int mi = 0; mi < 4; mi++) {
            float p0 = 0.0f, p1 = 0.0f;
#pragma unroll
            for (int ni = 0; ni < 4; ni++) {
                const int n = n0 + wn * 32 + ni * 8 + 2 * t;
                const float q0 = qvec[n], q1 = qvec[n + 1];
                p0 += tanhf(acc[mi][ni][0]) * q0 + tanhf(acc[mi][ni][1]) * q1;
                p1 += tanhf(acc[mi][ni][2]) * q0 + tanhf(acc[mi][ni][3]) * q1;
            }
            p0 += __shfl_xor_sync(0xffffffffu, p0, 1);
            p0 += __shfl_xor_sync(0xffffffffu, p0, 2);
            p1 += __shfl_xor_sync(0xffffffffu, p1, 1);
            p1 += __shfl_xor_sync(0xffffffffu, p1, 2);
            if (t == 0) {
                const int m_lo = m0 + wm * 64 + mi * 16 + g;
                const int slot = blockIdx.x * 4 + wn;
                TP[(long long)m_lo * 32 + slot]       = p0;
                TP[(long long)(m_lo + 8) * 32 + slot] = p1;
            }
        }
        return;
    }

#pragma unroll
    for (int mi = 0; mi < 4; mi++) {
        const int m_lo = m0 + wm * 64 + mi * 16 + g;
        const int m_hi = m_lo + 8;
#pragma unroll
        for (int ni = 0; ni < 4; ni++) {
            const int n = n0 + wn * 32 + ni * 8 + 2 * t;
            float2 v0, v1;
            v0.x = acc[mi][ni][0] * alpha;
            v0.y = acc[mi][ni][1] * alpha;
            v1.x = acc[mi][ni][2] * alpha;
            v1.y = acc[mi][ni][3] * alpha;
            if (bias) {
                const float b0 = bias[n], b1 = bias[n + 1];
                v0.x += b0; v0.y += b1;
                v1.x += b0; v1.y += b1;
            }
            if (FTRANS) {
                // V^T fp32: out[b][n][s], m = b*SEQL + s; DMODEL*SEQL = 1<<21
                const long long base_lo = ((long long)(m_lo >> 11) << 21) + (m_lo & 2047);
                const long long base_hi = ((long long)(m_hi >> 11) << 21) + (m_hi & 2047);
                C[base_lo + (long long)n * SEQL]       = v0.x;
                C[base_lo + (long long)(n + 1) * SEQL] = v0.y;
                C[base_hi + (long long)n * SEQL]       = v1.x;
                C[base_hi + (long long)(n + 1) * SEQL] = v1.y;
            } else {
                *(float2*)(C + (long long)m_lo * N + n) = v0;
                *(float2*)(C + (long long)m_hi * N + n) = v1;
            }
        }
    }
}

// ---------------------------------------------------------------------------
// fp32 -> split bf16 hi/lo planes (4 elems per thread)
// ---------------------------------------------------------------------------
__global__ void split_fp32(const float* __restrict__ src,
                           u16* __restrict__ hi, u16* __restrict__ lo, int n4)
{
    const int i = blockIdx.x * blockDim.x + threadIdx.x;
    if (i >= n4) return;
    const float4 v = ((const float4*)src)[i];
    u32 h01, l01, h23, l23;
    split_pack(v.x, v.y, h01, l01);
    split_pack(v.z, v.w, h23, l23);
    ((uint2*)hi)[i] = make_uint2(h01, h23);
    ((uint2*)lo)[i] = make_uint2(l01, l23);
}

// ---------------------------------------------------------------------------
// Plain fp32 row softmax, in place, row length 2048
// ---------------------------------------------------------------------------
__global__ void softmax_rows(float* __restrict__ S)
{
    float* row = S + (long long)blockIdx.x * 2048;
    const int tid = threadIdx.x;
    __shared__ float red[256];

    float v[8];
    *(float4*)&v[0] = *(const float4*)(row + tid * 8);
    *(float4*)&v[4] = *(const float4*)(row + tid * 8 + 4);

    float mx = -1e30f;
#pragma unroll
    for (int i = 0; i < 8; i++) mx = fmaxf(mx, v[i]);
    red[tid] = mx; __syncthreads();
    for (int s = 128; s > 0; s >>= 1) {
        if (tid < s) red[tid] = fmaxf(red[tid], red[tid + s]);
        __syncthreads();
    }
    mx = red[0]; __syncthreads();

    float sum = 0.0f;
#pragma unroll
    for (int i = 0; i < 8; i++) { v[i] = __expf(v[i] - mx); sum += v[i]; }
    red[tid] = sum; __syncthreads();
    for (int s = 128; s > 0; s >>= 1) {
        if (tid < s) red[tid] += red[tid + s];
        __syncthreads();
    }
    const float inv = 1.0f / red[0];
#pragma unroll
    for (int i = 0; i < 8; i++) v[i] *= inv;
    *(float4*)(row + tid * 8)     = *(float4*)&v[0];
    *(float4*)(row + tid * 8 + 4) = *(float4*)&v[4];
}

// ---------------------------------------------------------------------------
// h = x + z ; H = LN(h)*g + b  (fp32 out only)
// ---------------------------------------------------------------------------
__global__ void add_ln(const float* __restrict__ X, const float* __restrict__ Z,
                       const float* __restrict__ g, const float* __restrict__ b,
                       float* __restrict__ H)
{
    const long long r = blockIdx.x;
    const int tid = threadIdx.x;
    const int c0  = tid * 4;
    const float* xr = X + r * DMODEL;
    const float* zr = Z + r * DMODEL;
    __shared__ float red[256];

    float4 x4 = *(const float4*)(xr + c0);
    float4 z4 = *(const float4*)(zr + c0);
    float h[4] = { x4.x + z4.x, x4.y + z4.y, x4.z + z4.z, x4.w + z4.w };

    float sum = h[0] + h[1] + h[2] + h[3];
    red[tid] = sum; __syncthreads();
    for (int s = 128; s > 0; s >>= 1) {
        if (tid < s) red[tid] += red[tid + s];
        __syncthreads();
    }
    const float mean = red[0] * (1.0f / DMODEL);
    __syncthreads();

    float vs = 0.0f;
#pragma unroll
    for (int i = 0; i < 4; i++) { const float d = h[i] - mean; vs += d * d; }
    red[tid] = vs; __syncthreads();
    for (int s = 128; s > 0; s >>= 1) {
        if (tid < s) red[tid] += red[tid + s];
        __syncthreads();
    }
    const float inv = rsqrtf(red[0] * (1.0f / DMODEL) + LN_EPS);

    float4 o;
    o.x = (h[0] - mean) * inv * g[c0 + 0] + b[c0 + 0];
    o.y = (h[1] - mean) * inv * g[c0 + 1] + b[c0 + 1];
    o.z = (h[2] - mean) * inv * g[c0 + 2] + b[c0 + 2];
    o.w = (h[3] - mean) * inv * g[c0 + 3] + b[c0 + 3];
    *(float4*)(H + r * DMODEL + c0) = o;
}

// ---------------------------------------------------------------------------
// T[r] = sum of 32 soft-key partials (deterministic fixed-order reduce)
// ---------------------------------------------------------------------------
__global__ void skt_reduce(const float* __restrict__ TP, float* __restrict__ T)
{
    const int r = blockIdx.x * 256 + threadIdx.x;
    const float* p = TP + (long long)r * 32;
    float s = 0.0f;
#pragma unroll
    for (int j = 0; j < 32; j++) s += p[j];
    T[r] = s;
}

// ---------------------------------------------------------------------------
// final_out stage 1: partial over 256-row s-chunk
// ---------------------------------------------------------------------------
__global__ void final_partial(const float* __restrict__ H, const float* __restrict__ w,
                              float* __restrict__ OP)
{
    const int b  = blockIdx.y;
    const int zc = blockIdx.z;
    const int o  = blockIdx.x * 256 + threadIdx.x;
    const float* Hp = H + (long long)b * SEQL * DMODEL
                        + (long long)(zc * 256) * DMODEL + o;
    const float* wb = w + (long long)b * SEQL + zc * 256;

    float a0 = 0.0f, a1 = 0.0f, a2 = 0.0f, a3 = 0.0f;
    for (int s = 0; s < 256; s += 4) {
        a0 += wb[s + 0] * Hp[(long long)(s + 0) * DMODEL];
        a1 += wb[s + 1] * Hp[(long long)(s + 1) * DMODEL];
        a2 += wb[s + 2] * Hp[(long long)(s + 2) * DMODEL];
        a3 += wb[s + 3] * Hp[(long long)(s + 3) * DMODEL];
    }
    OP[(long long)(b * 8 + zc) * DMODEL + o] = (a0 + a1) + (a2 + a3);
}

// final_out stage 2
__global__ void final_reduce(const float* __restrict__ OP, float* __restrict__ out)
{
    const int b = blockIdx.y;
    const int o = blockIdx.x * 256 + threadIdx.x;
    float s = 0.0f;
#pragma unroll
    for (int z = 0; z < 8; z++)
        s += OP[(long long)(b * 8 + z) * DMODEL + o];
    out[b * DMODEL + o] = s;
}

// ---------------------------------------------------------------------------
// Launch
// ---------------------------------------------------------------------------
extern "C" void kernel_launch(void* const* d_in, const int* in_sizes, int n_in,
                              void* d_out, int out_size)
{
    const float* inputs  = (const float*)d_in[0];
    const float* embed_w = (const float*)d_in[1];
    const float* embed_b = (const float*)d_in[2];
    const float* wq_w    = (const float*)d_in[3];
    const float* wq_b    = (const float*)d_in[4];
    const float* wk_w    = (const float*)d_in[5];
    const float* wk_b    = (const float*)d_in[6];
    const float* wv_w    = (const float*)d_in[7];
    const float* wv_b    = (const float*)d_in[8];
    const float* ln_g    = (const float*)d_in[9];
    const float* ln_b    = (const float*)d_in[10];
    const float* skw     = (const float*)d_in[11];
    const float* sq      = (const float*)d_in[12];
    const float* pos     = (const float*)d_in[13];
    float* out = (float*)d_out;

    cudaFuncSetAttribute((const void*)bf16x3_gemm,
                         cudaFuncAttributeMaxDynamicSharedMemorySize, DYN_SMEM_G);
    cudaFuncSetAttribute((const void*)tf32_gemm<false, false>,
                         cudaFuncAttributeMaxDynamicSharedMemorySize, DYN_SMEM_T);
    cudaFuncSetAttribute((const void*)tf32_gemm<true,  false>,
                         cudaFuncAttributeMaxDynamicSharedMemorySize, DYN_SMEM_T);
    cudaFuncSetAttribute((const void*)tf32_gemm<false, true>,
                         cudaFuncAttributeMaxDynamicSharedMemorySize, DYN_SMEM_T);

    float* base = 0;
    cudaGetSymbolAddress((void**)&base, g_scratch);

    u16* INh  = (u16*)(base + O_INS);   u16* INl  = INh  + C_IN;
    u16* EWh  = (u16*)(base + O_EWS);   u16* EWl  = EWh  + C_EW;
    float* X  = base + O_X;
    float* Q  = base + O_Q;
    float* K  = base + O_K;
    float* VT = base + O_VT;
    float* SC = base + O_SC;
    float* Z  = base + O_Z;
    float* H  = base + O_H;
    float* TP = base + O_TP;
    float* OP = base + O_OP;
    float* T  = base + O_T;

    // 0) splits for the embed GEMM only
    split_fp32<<<(int)(C_IN / 4 / 256), 256>>>(inputs,  INh, INl, (int)(C_IN / 4));
    split_fp32<<<(int)(C_EW / 4 / 256), 256>>>(embed_w, EWh, EWl, (int)(C_EW / 4));

    // 1) embed (bf16x3): X = inputs @ embed_w^T + embed_b + pos_enc
    bf16x3_gemm<<<dim3(DMODEL / 128, NROW / 128, 1), 256, DYN_SMEM_G>>>(
        INh, INl, EWh, EWl, X, DMODEL, D_IN, embed_b, pos);

    // 2) Q, K (tf32, raw fp32 weights), V (tf32, transposed out)
    tf32_gemm<false, false><<<dim3(DMODEL / 128, NROW / 128, 1), 256, DYN_SMEM_T>>>(
        X, wq_w, Q, 0, 0, DMODEL, DMODEL, 0, 0, 0, 1.0f, wq_b);
    tf32_gemm<false, false><<<dim3(DMODEL / 128, NROW / 128, 1), 256, DYN_SMEM_T>>>(
        X, wk_w, K, 0, 0, DMODEL, DMODEL, 0, 0, 0, 1.0f, wk_b);
    tf32_gemm<true, false><<<dim3(DMODEL / 128, NROW / 128, 1), 256, DYN_SMEM_T>>>(
        X, wv_w, VT, 0, 0, DMODEL, DMODEL, 0, 0, 0, 1.0f, wv_b);

    // 3) scores = Q @ K^T / 32 (batched, tf32)
    tf32_gemm<false, false><<<dim3(SEQL / 128, SEQL / 128, BATCH), 256, DYN_SMEM_T>>>(
        Q, K, SC, 0, 0, SEQL, DMODEL,
        (long long)SEQL * DMODEL, (long long)SEQL * DMODEL, (long long)SEQL * SEQL,
        1.0f / 32.0f, 0);

    // 4) softmax in place (fp32)
    softmax_rows<<<NROW, 256>>>(SC);

    // 5) Z = softmax(SC) @ V  (tf32; B = V^T fp32 [n][s] per batch)
    tf32_gemm<false, false><<<dim3(DMODEL / 128, SEQL / 128, BATCH), 256, DYN_SMEM_T>>>(
        SC, VT, Z, 0, 0, DMODEL, SEQL,
        (long long)SEQL * SEQL, (long long)DMODEL * SEQL, (long long)SEQL * DMODEL,
        1.0f, 0);

    // 6) H = LN(X + Z)*g + b  (fp32)
    add_ln<<<NROW, 256>>>(X, Z, ln_g, ln_b, H);

    // 7) fused SK GEMM (tf32) + tanh·q partial reduction -> TP
    tf32_gemm<false, true><<<dim3(DMODEL / 128, NROW / 128, 1), 256, DYN_SMEM_T>>>(
        H, skw, 0, TP, sq, DMODEL, DMODEL, 0, 0, 0, 1.0f, 0);

    // 8) T[r] = sum partials; softmax over s per batch
    skt_reduce<<<NROW / 256, 256>>>(TP, T);
    softmax_rows<<<BATCH, 256>>>(T);

    // 9) out[b,o] = sum_s w[b,s] * H[b,s,o]  (two-stage, deterministic)
    final_partial<<<dim3(DMODEL / 256, BATCH, 8), 256>>>(H, T, OP);
    final_reduce<<<dim3(DMODEL / 256, BATCH), 256>>>(OP, out);
}

// round 13
// speedup vs baseline: 1.5120x; 1.1236x over previous
#include <cuda_runtime.h>
#include <cstdint>
#include <math.h>

// ---------------------------------------------------------------------------
// Problem constants
// ---------------------------------------------------------------------------
#define BATCH   8
#define SEQL    2048
#define D_IN    512
#define DMODEL  1024
#define NROW    (BATCH * SEQL)          // 16384
#define LN_EPS  1e-5f

typedef unsigned short u16;
typedef uint32_t u32;

// element counts
static const long long C_IN  = (long long)NROW * D_IN;       // 8388608
static const long long C_EW  = (long long)DMODEL * D_IN;     // 524288
static const long long C_W   = (long long)DMODEL * DMODEL;   // 1048576
static const long long C_MAT = (long long)NROW * DMODEL;     // 16777216
static const long long C_SC  = (long long)BATCH * SEQL * SEQL; // 33554432

// scratch offsets (in floats)
#define O_INS   (0LL)
#define O_EWS   (O_INS  + C_IN)
#define O_SKWS  (O_EWS  + C_EW)
#define O_WQT   (O_SKWS + C_W)
#define O_WKT   (O_WQT  + C_W)
#define O_WVT   (O_WKT  + C_W)
#define O_X     (O_WVT  + C_W)
#define O_XT    (O_X    + C_MAT)        // tf32-rounded X
#define O_Q     (O_XT   + C_MAT)        // tf32-rounded Q
#define O_K     (O_Q    + C_MAT)        // tf32-rounded K
#define O_VT    (O_K    + C_MAT)        // tf32-rounded V^T (per batch [n][s])
#define O_SC    (O_VT   + C_MAT)
#define O_Z     (O_SC   + C_SC)
#define O_H     (O_Z    + C_MAT)
#define O_HS    (O_H    + C_MAT)        // split H planes
#define O_TP    (O_HS   + C_MAT)                 // soft-key partials [16384][32]
#define O_OP    (O_TP   + 16384LL * 32)          // final_out partials [64][1024]
#define O_T     (O_OP   + 65536)
#define O_TOTAL (O_T    + 16384)

__device__ float g_scratch[O_TOTAL];

// ---------------------------------------------------------------------------
// PTX helpers (baseline sm_80+ features only — harness targets plain sm_103)
// ---------------------------------------------------------------------------
__device__ __forceinline__ u32 smem_u32(const void* p) {
    u32 a;
    asm("{ .reg .u64 t; cvta.to.shared.u64 t, %1; cvt.u32.u64 %0, t; }"
        : "=r"(a) : "l"(p));
    return a;
}

__device__ __forceinline__ void cp_async16(u32 dst, const void* src) {
    asm volatile("cp.async.cg.shared.global [%0], [%1], 16;" :: "r"(dst), "l"(src));
}
#define CP_COMMIT() asm volatile("cp.async.commit_group;" ::: "memory")
#define CP_WAIT1()  asm volatile("cp.async.wait_group 1;"  ::: "memory")

// split x0,x1 (fp32) into packed bf16x2 hi and lo parts: x = hi + lo
__device__ __forceinline__ void split_pack(float x0, float x1, u32& hi, u32& lo) {
    asm("cvt.rn.bf16x2.f32 %0, %1, %2;" : "=r"(hi) : "f"(x1), "f"(x0));
    const float h0 = __uint_as_float(hi << 16);
    const float h1 = __uint_as_float(hi & 0xFFFF0000u);
    const float l0 = x0 - h0;
    const float l1 = x1 - h1;
    asm("cvt.rn.bf16x2.f32 %0, %1, %2;" : "=r"(lo) : "f"(l1), "f"(l0));
}

__device__ __forceinline__ float f2tf32f(float f) {
    u32 r;
    asm("cvt.rna.tf32.f32 %0, %1;" : "=r"(r) : "f"(f));
    return __uint_as_float(r);
}

// D += A*B  (m16n8k16 bf16, fp32 accum)
__device__ __forceinline__ void mma_bf16(float* d, const u32* a, const u32* b) {
    asm volatile(
        "mma.sync.aligned.m16n8k16.row.col.f32.bf16.bf16.f32 "
        "{%0,%1,%2,%3}, {%4,%5,%6,%7}, {%8,%9}, {%0,%1,%2,%3};"
        : "+f"(d[0]), "+f"(d[1]), "+f"(d[2]), "+f"(d[3])
        : "r"(a[0]), "r"(a[1]), "r"(a[2]), "r"(a[3]), "r"(b[0]), "r"(b[1]));
}

// D += A*B  (m16n8k8 tf32, fp32 accum) — operands pre-rounded to tf32
__device__ __forceinline__ void mma_tf32(float* d, const u32* a, const u32* b) {
    asm volatile(
        "mma.sync.aligned.m16n8k8.row.col.f32.tf32.tf32.f32 "
        "{%0,%1,%2,%3}, {%4,%5,%6,%7}, {%8,%9}, {%0,%1,%2,%3};"
        : "+f"(d[0]), "+f"(d[1]), "+f"(d[2]), "+f"(d[3])
        : "r"(a[0]), "r"(a[1]), "r"(a[2]), "r"(a[3]), "r"(b[0]), "r"(b[1]));
}

__device__ __forceinline__ void ldmat4(u32& r0, u32& r1, u32& r2, u32& r3, u32 addr) {
    asm volatile("ldmatrix.sync.aligned.m8n8.x4.shared.b16 {%0,%1,%2,%3}, [%4];"
                 : "=r"(r0), "=r"(r1), "=r"(r2), "=r"(r3) : "r"(addr));
}

// swizzled byte offset of (row, 16B-chunk ch) in a 128x32 bf16 plane (64B rows)
__device__ __forceinline__ u32 sw_off(u32 row, u32 ch) {
    return row * 64u + ((ch ^ ((row >> 1) & 3u)) << 4);
}

// ---------------------------------------------------------------------------
// bf16x3 split GEMM (embed + SK): C = A@B^T (+bias +posenc)
// R7/R10 proven cadence: 3-buffer, one barrier/chunk, load-after-compute.
//   XTOUT: also write tf32-rounded copy of C (embed; feeds tf32 QKV GEMMs)
//   SKRED: fused soft-key epilogue (partials of sum tanh(C)*q), no C written
// ---------------------------------------------------------------------------
#define PLANE_B  (128 * 64)             // 8192
#define STAGE_B  (4 * PLANE_B)          // 32768
#define DYN_SMEM_G (3 * STAGE_B)        // 98304

template <bool XTOUT, bool SKRED>
__global__ __launch_bounds__(256, 2)
void bf16x3_gemm(const u16* __restrict__ Ahi, const u16* __restrict__ Alo,
                 const u16* __restrict__ Bhi, const u16* __restrict__ Blo,
                 float* __restrict__ Cf, float* __restrict__ Ct,
                 float* __restrict__ TP, const float* __restrict__ qvec,
                 int N, int K,
                 const float* __restrict__ bias,
                 const float* __restrict__ posenc)
{
    extern __shared__ char smem[];

    const int tid  = threadIdx.x;
    const int wid  = tid >> 5;
    const int lane = tid & 31;
    const int wm   = wid >> 2;
    const int wn   = wid & 3;
    const int g    = lane >> 2;
    const int t    = lane & 3;
    const int lrow = lane & 15;
    const int lch  = lane >> 4;

    const int m0 = blockIdx.y * 128;
    const int n0 = blockIdx.x * 128;

    const u32 smem_base = smem_u32(smem);

    float acc[4][4][4];
#pragma unroll
    for (int mi = 0; mi < 4; mi++)
#pragma unroll
        for (int ni = 0; ni < 4; ni++)
#pragma unroll
            for (int c = 0; c < 4; c++) acc[mi][ni][c] = 0.0f;

    const int NC = K >> 5;

    const u32 ld_row = (u32)(tid >> 2);
    const u32 ld_ch  = (u32)(tid & 3);

    auto issue_stage = [&](int c, int buf) {
        const int k0 = c * 32;
        const u32 st = smem_base + buf * STAGE_B;
        const u16* srcs[4] = { Ahi, Alo, Bhi, Blo };
#pragma unroll
        for (int p = 0; p < 4; p++) {
            const u16* src = srcs[p];
            const int rbase = (p < 2) ? m0 : n0;
#pragma unroll
            for (int i = 0; i < 2; i++) {
                const u32 row = ld_row + i * 64;
                cp_async16(st + p * PLANE_B + sw_off(row, ld_ch),
                           src + (long long)(rbase + row) * K + k0 + ld_ch * 8);
            }
        }
        CP_COMMIT();
    };

    issue_stage(0, 0);
    issue_stage(1, 1);

    int buf = 0;
    int nbuf = 2;
    for (int c = 0; c < NC; ++c) {
        CP_WAIT1();
        __syncthreads();

        const u32 st = smem_base + buf * STAGE_B;

#pragma unroll
        for (int half = 0; half < 2; half++) {
            const u32 ch = (u32)(half * 2 + lch);

            u32 bh[4][2], bl[4][2];
#pragma unroll
            for (int nj = 0; nj < 2; nj++) {
                const u32 rb = sw_off((u32)(wn * 32 + nj * 16 + lrow), ch);
                u32 r0, r1, r2, r3;
                ldmat4(r0, r1, r2, r3, st + 2 * PLANE_B + rb);
                bh[2*nj][0] = r0; bh[2*nj+1][0] = r1;
                bh[2*nj][1] = r2; bh[2*nj+1][1] = r3;
                ldmat4(r0, r1, r2, r3, st + 3 * PLANE_B + rb);
                bl[2*nj][0] = r0; bl[2*nj+1][0] = r1;
                bl[2*nj][1] = r2; bl[2*nj+1][1] = r3;
            }

#pragma unroll
            for (int mp = 0; mp < 2; mp++) {
                u32 ah[2][4], al[2][4];
#pragma unroll
                for (int q = 0; q < 2; q++) {
                    const int mi = mp * 2 + q;
                    const u32 ra = sw_off((u32)(wm * 64 + mi * 16 + lrow), ch);
                    ldmat4(ah[q][0], ah[q][1], ah[q][2], ah[q][3], st + ra);
                    ldmat4(al[q][0], al[q][1], al[q][2], al[q][3], st + PLANE_B + ra);
                }
#pragma unroll
                for (int q = 0; q < 2; q++)
#pragma unroll
                    for (int ni = 0; ni < 4; ni++)
                        mma_bf16(acc[mp*2+q][ni], ah[q], bh[ni]);
#pragma unroll
                for (int q = 0; q < 2; q++)
#pragma unroll
                    for (int ni = 0; ni < 4; ni++)
                        mma_bf16(acc[mp*2+q][ni], ah[q], bl[ni]);
#pragma unroll
                for (int q = 0; q < 2; q++)
#pragma unroll
                    for (int ni = 0; ni < 4; ni++)
                        mma_bf16(acc[mp*2+q][ni], al[q], bh[ni]);
            }
        }

        if (c + 2 < NC) issue_stage(c + 2, nbuf);
        else            CP_COMMIT();

        buf  = (buf  == 2) ? 0 : buf  + 1;
        nbuf = (nbuf == 2) ? 0 : nbuf + 1;
    }

    // ---- epilogue ----
    if (SKRED) {
#pragma unroll
        for (int mi = 0; mi < 4; mi++) {
            float p0 = 0.0f, p1 = 0.0f;
#pragma unroll
            for (int ni = 0; ni < 4; ni++) {
                const int n = n0 + wn * 32 + ni * 8 + 2 * t;
                const float q0 = qvec[n], q1 = qvec[n + 1];
                p0 += tanhf(acc[mi][ni][0]) * q0 + tanhf(acc[mi][ni][1]) * q1;
                p1 += tanhf(acc[mi][ni][2]) * q0 + tanhf(acc[mi][ni][3]) * q1;
            }
            p0 += __shfl_xor_sync(0xffffffffu, p0, 1);
            p0 += __shfl_xor_sync(0xffffffffu, p0, 2);
            p1 += __shfl_xor_sync(0xffffffffu, p1, 1);
            p1 += __shfl_xor_sync(0xffffffffu, p1, 2);
            if (t == 0) {
                const int m_lo = m0 + wm * 64 + mi * 16 + g;
                const int slot = blockIdx.x * 4 + wn;
                TP[(long long)m_lo * 32 + slot]       = p0;
                TP[(long long)(m_lo + 8) * 32 + slot] = p1;
            }
        }
        return;
    }

#pragma unroll
    for (int mi = 0; mi < 4; mi++) {
        const int m_lo = m0 + wm * 64 + mi * 16 + g;
        const int m_hi = m_lo + 8;
        const float* pe_lo = posenc + (long long)(m_lo & (SEQL - 1)) * N;
        const float* pe_hi = posenc + (long long)(m_hi & (SEQL - 1)) * N;
#pragma unroll
        for (int ni = 0; ni < 4; ni++) {
            const int n = n0 + wn * 32 + ni * 8 + 2 * t;
            const float b0 = bias[n], b1 = bias[n + 1];
            float2 v0, v1;
            v0.x = acc[mi][ni][0] + b0 + pe_lo[n];
            v0.y = acc[mi][ni][1] + b1 + pe_lo[n + 1];
            v1.x = acc[mi][ni][2] + b0 + pe_hi[n];
            v1.y = acc[mi][ni][3] + b1 + pe_hi[n + 1];
            *(float2*)(Cf + (long long)m_lo * N + n) = v0;
            *(float2*)(Cf + (long long)m_hi * N + n) = v1;
            if (XTOUT) {
                float2 t0, t1;
                t0.x = f2tf32f(v0.x); t0.y = f2tf32f(v0.y);
                t1.x = f2tf32f(v1.x); t1.y = f2tf32f(v1.y);
                *(float2*)(Ct + (long long)m_lo * N + n) = t0;
                *(float2*)(Ct + (long long)m_hi * N + n) = t1;
            }
        }
    }
}

// ---------------------------------------------------------------------------
// tf32 GEMM on PRE-ROUNDED tf32 operands (no in-loop cvt):
//   C[m,n] = alpha * sum_k A[m,k]*B[n,k]  (+bias)
//   ROUND:  round output to tf32 (Q, K — consumed only by scores GEMM)
//   FTRANS: write C transposed per batch, tf32-rounded (V^T)
// ---------------------------------------------------------------------------
#define TF_STRIDE       36
#define TF_TILE_FLOATS  (128 * TF_STRIDE)      // 4608
#define TF_STAGE_FLOATS (2 * TF_TILE_FLOATS)   // 9216
#define DYN_SMEM_T      (3 * TF_STAGE_FLOATS * 4)  // 110592

template <bool FTRANS, bool ROUND>
__global__ __launch_bounds__(256, 2)
void tf32_gemm(const float* __restrict__ A, const float* __restrict__ B,
               float* __restrict__ C,
               int N, int K,
               long long sA, long long sB, long long sC,
               float alpha, const float* __restrict__ bias)
{
    extern __shared__ float smf[];

    const int tid  = threadIdx.x;
    const int wid  = tid >> 5;
    const int lane = tid & 31;
    const int wm   = wid >> 2;
    const int wn   = wid & 3;
    const int g    = lane >> 2;
    const int t    = lane & 3;

    const int bz = blockIdx.z;
    A += bz * sA; B += bz * sB; C += bz * sC;
    const int m0 = blockIdx.y * 128;
    const int n0 = blockIdx.x * 128;

    const u32 smem_base = smem_u32(smf);

    float acc[4][4][4];
#pragma unroll
    for (int mi = 0; mi < 4; mi++)
#pragma unroll
        for (int ni = 0; ni < 4; ni++)
#pragma unroll
            for (int c = 0; c < 4; c++) acc[mi][ni][c] = 0.0f;

    const int NC = K >> 5;

    auto issue_stage = [&](int c, int buf) {
        const int k0 = c * 32;
        const u32 st = smem_base + (buf * TF_STAGE_FLOATS) * 4;
#pragma unroll
        for (int i = 0; i < 4; i++) {
            const int e   = tid + i * 256;
            const int row = e >> 3;
            const int q   = e & 7;
            cp_async16(st + (row * TF_STRIDE + q * 4) * 4,
                       A + (long long)(m0 + row) * K + k0 + q * 4);
        }
#pragma unroll
        for (int i = 0; i < 4; i++) {
            const int e   = tid + i * 256;
            const int row = e >> 3;
            const int q   = e & 7;
            cp_async16(st + (TF_TILE_FLOATS + row * TF_STRIDE + q * 4) * 4,
                       B + (long long)(n0 + row) * K + k0 + q * 4);
        }
        CP_COMMIT();
    };

    issue_stage(0, 0);
    issue_stage(1, 1);

    int buf = 0;
    int nbuf = 2;
    for (int c = 0; c < NC; ++c) {
        CP_WAIT1();
        __syncthreads();

        const u32* As = (const u32*)(smf + buf * TF_STAGE_FLOATS);
        const u32* Bs = As + TF_TILE_FLOATS;

#pragma unroll
        for (int ks = 0; ks < 4; ks++) {
            const int kk = ks * 8;
            u32 bf[4][2];
#pragma unroll
            for (int ni = 0; ni < 4; ni++) {
                const u32* b = Bs + (wn * 32 + ni * 8 + g) * TF_STRIDE + kk;
                bf[ni][0] = b[t];
                bf[ni][1] = b[t + 4];
            }
#pragma unroll
            for (int mp = 0; mp < 2; mp++) {
                u32 af[2][4];
#pragma unroll
                for (int q = 0; q < 2; q++) {
                    const int mi = mp * 2 + q;
                    const u32* a = As + (wm * 64 + mi * 16 + g) * TF_STRIDE + kk;
                    af[q][0] = a[t];
                    af[q][1] = a[8 * TF_STRIDE + t];
                    af[q][2] = a[t + 4];
                    af[q][3] = a[8 * TF_STRIDE + t + 4];
                }
#pragma unroll
                for (int q = 0; q < 2; q++)
#pragma unroll
                    for (int ni = 0; ni < 4; ni++)
                        mma_tf32(acc[mp*2+q][ni], af[q], bf[ni]);
            }
        }

        if (c + 2 < NC) issue_stage(c + 2, nbuf);
        else            CP_COMMIT();

        buf  = (buf  == 2) ? 0 : buf  + 1;
        nbuf = (nbuf == 2) ? 0 : nbuf + 1;
    }

#pragma unroll
    for (int mi = 0; mi < 4; mi++) {
        const int m_lo = m0 + wm * 64 + mi * 16 + g;
        const int m_hi = m_lo + 8;
#pragma unroll
        for (int ni = 0; ni < 4; ni++) {
            const int n = n0 + wn * 32 + ni * 8 + 2 * t;
            float2 v0, v1;
            v0.x = acc[mi][ni][0] * alpha;
            v0.y = acc[mi][ni][1] * alpha;
            v1.x = acc[mi][ni][2] * alpha;
            v1.y = acc[mi][ni][3] * alpha;
            if (bias) {
                const float b0 = bias[n], b1 = bias[n + 1];
                v0.x += b0; v0.y += b1;
                v1.x += b0; v1.y += b1;
            }
            if (ROUND || FTRANS) {
                v0.x = f2tf32f(v0.x); v0.y = f2tf32f(v0.y);
                v1.x = f2tf32f(v1.x); v1.y = f2tf32f(v1.y);
            }
            if (FTRANS) {
                // V^T: out[b][n][s], m = b*SEQL + s; DMODEL*SEQL = 1<<21
                const long long base_lo = ((long long)(m_lo >> 11) << 21) + (m_lo & 2047);
                const long long base_hi = ((long long)(m_hi >> 11) << 21) + (m_hi & 2047);
                C[base_lo + (long long)n * SEQL]       = v0.x;
                C[base_lo + (long long)(n + 1) * SEQL] = v0.y;
                C[base_hi + (long long)n * SEQL]       = v1.x;
                C[base_hi + (long long)(n + 1) * SEQL] = v1.y;
            } else {
                *(float2*)(C + (long long)m_lo * N + n) = v0;
                *(float2*)(C + (long long)m_hi * N + n) = v1;
            }
        }
    }
}

// ---------------------------------------------------------------------------
// fp32 -> split bf16 hi/lo planes (4 elems per thread)
// ---------------------------------------------------------------------------
__global__ void split_fp32(const float* __restrict__ src,
                           u16* __restrict__ hi, u16* __restrict__ lo, int n4)
{
    const int i = blockIdx.x * blockDim.x + threadIdx.x;
    if (i >= n4) return;
    const float4 v = ((const float4*)src)[i];
    u32 h01, l01, h23, l23;
    split_pack(v.x, v.y, h01, l01);
    split_pack(v.z, v.w, h23, l23);
    ((uint2*)hi)[i] = make_uint2(h01, h23);
    ((uint2*)lo)[i] = make_uint2(l01, l23);
}

// ---------------------------------------------------------------------------
// fp32 -> tf32-rounded fp32 (4 elems per thread)
// ---------------------------------------------------------------------------
__global__ void round_tf32(const float* __restrict__ src, float* __restrict__ dst, int n4)
{
    const int i = blockIdx.x * blockDim.x + threadIdx.x;
    if (i >= n4) return;
    float4 v = ((const float4*)src)[i];
    v.x = f2tf32f(v.x); v.y = f2tf32f(v.y);
    v.z = f2tf32f(v.z); v.w = f2tf32f(v.w);
    ((float4*)dst)[i] = v;
}

// ---------------------------------------------------------------------------
// Row softmax, in place, row length 2048.  RND: tf32-round outputs.
// ---------------------------------------------------------------------------
template <bool RND>
__global__ void softmax_rows(float* __restrict__ S)
{
    float* row = S + (long long)blockIdx.x * 2048;
    const int tid = threadIdx.x;
    __shared__ float red[256];

    float v[8];
    *(float4*)&v[0] = *(const float4*)(row + tid * 8);
    *(float4*)&v[4] = *(const float4*)(row + tid * 8 + 4);

    float mx = -1e30f;
#pragma unroll
    for (int i = 0; i < 8; i++) mx = fmaxf(mx, v[i]);
    red[tid] = mx; __syncthreads();
    for (int s = 128; s > 0; s >>= 1) {
        if (tid < s) red[tid] = fmaxf(red[tid], red[tid + s]);
        __syncthreads();
    }
    mx = red[0]; __syncthreads();

    float sum = 0.0f;
#pragma unroll
    for (int i = 0; i < 8; i++) { v[i] = __expf(v[i] - mx); sum += v[i]; }
    red[tid] = sum; __syncthreads();
    for (int s = 128; s > 0; s >>= 1) {
        if (tid < s) red[tid] += red[tid + s];
        __syncthreads();
    }
    const float inv = 1.0f / red[0];
#pragma unroll
    for (int i = 0; i < 8; i++) {
        v[i] *= inv;
        if (RND) v[i] = f2tf32f(v[i]);
    }
    *(float4*)(row + tid * 8)     = *(float4*)&v[0];
    *(float4*)(row + tid * 8 + 4) = *(float4*)&v[4];
}

// ---------------------------------------------------------------------------
// h = x + z ; H = LN(h)*g + b  -> fp32 H + split planes (for bf16x3 SK GEMM)
// ---------------------------------------------------------------------------
__global__ void add_ln_split(const float* __restrict__ X, const float* __restrict__ Z,
                             const float* __restrict__ g, const float* __restrict__ b,
                             float* __restrict__ H, u16* __restrict__ hi, u16* __restrict__ lo)
{
    const long long r = blockIdx.x;
    const int tid = threadIdx.x;
    const int c0  = tid * 4;
    const float* xr = X + r * DMODEL;
    const float* zr = Z + r * DMODEL;
    __shared__ float red[256];

    float4 x4 = *(const float4*)(xr + c0);
    float4 z4 = *(const float4*)(zr + c0);
    float h[4] = { x4.x + z4.x, x4.y + z4.y, x4.z + z4.z, x4.w + z4.w };

    float sum = h[0] + h[1] + h[2] + h[3];
    red[tid] = sum; __syncthreads();
    for (int s = 128; s > 0; s >>= 1) {
        if (tid < s) red[tid] += red[tid + s];
        __syncthreads();
    }
    const float mean = red[0] * (1.0f / DMODEL);
    __syncthreads();

    float vs = 0.0f;
#pragma unroll
    for (int i = 0; i < 4; i++) { const float d = h[i] - mean; vs += d * d; }
    red[tid] = vs; __syncthreads();
    for (int s = 128; s > 0; s >>= 1) {
        if (tid < s) red[tid] += red[tid + s];
        __syncthreads();
    }
    const float inv = rsqrtf(red[0] * (1.0f / DMODEL) + LN_EPS);

    float4 o;
    o.x = (h[0] - mean) * inv * g[c0 + 0] + b[c0 + 0];
    o.y = (h[1] - mean) * inv * g[c0 + 1] + b[c0 + 1];
    o.z = (h[2] - mean) * inv * g[c0 + 2] + b[c0 + 2];
    o.w = (h[3] - mean) * inv * g[c0 + 3] + b[c0 + 3];
    *(float4*)(H + r * DMODEL + c0) = o;

    u32 h01, l01, h23, l23;
    split_pack(o.x, o.y, h01, l01);
    split_pack(o.z, o.w, h23, l23);
    const long long pi = (r * DMODEL + c0) >> 1;
    ((u32*)hi)[pi]     = h01;
    ((u32*)hi)[pi + 1] = h23;
    ((u32*)lo)[pi]     = l01;
    ((u32*)lo)[pi + 1] = l23;
}

// ---------------------------------------------------------------------------
// T[r] = sum of 32 soft-key partials (deterministic fixed-order reduce)
// ---------------------------------------------------------------------------
__global__ void skt_reduce(const float* __restrict__ TP, float* __restrict__ T)
{
    const int r = blockIdx.x * 256 + threadIdx.x;
    const float* p = TP + (long long)r * 32;
    float s = 0.0f;
#pragma unroll
    for (int j = 0; j < 32; j++) s += p[j];
    T[r] = s;
}

// ---------------------------------------------------------------------------
// final_out stage 1: partial over 256-row s-chunk
// ---------------------------------------------------------------------------
__global__ void final_partial(const float* __restrict__ H, const float* __restrict__ w,
                              float* __restrict__ OP)
{
    const int b  = blockIdx.y;
    const int zc = blockIdx.z;
    const int o  = blockIdx.x * 256 + threadIdx.x;
    const float* Hp = H + (long long)b * SEQL * DMODEL
                        + (long long)(zc * 256) * DMODEL + o;
    const float* wb = w + (long long)b * SEQL + zc * 256;

    float a0 = 0.0f, a1 = 0.0f, a2 = 0.0f, a3 = 0.0f;
    for (int s = 0; s < 256; s += 4) {
        a0 += wb[s + 0] * Hp[(long long)(s + 0) * DMODEL];
        a1 += wb[s + 1] * Hp[(long long)(s + 1) * DMODEL];
        a2 += wb[s + 2] * Hp[(long long)(s + 2) * DMODEL];
        a3 += wb[s + 3] * Hp[(long long)(s + 3) * DMODEL];
    }
    OP[(long long)(b * 8 + zc) * DMODEL + o] = (a0 + a1) + (a2 + a3);
}

// final_out stage 2
__global__ void final_reduce(const float* __restrict__ OP, float* __restrict__ out)
{
    const int b = blockIdx.y;
    const int o = blockIdx.x * 256 + threadIdx.x;
    float s = 0.0f;
#pragma unroll
    for (int z = 0; z < 8; z++)
        s += OP[(long long)(b * 8 + z) * DMODEL + o];
    out[b * DMODEL + o] = s;
}

// ---------------------------------------------------------------------------
// Launch
// ---------------------------------------------------------------------------
extern "C" void kernel_launch(void* const* d_in, const int* in_sizes, int n_in,
                              void* d_out, int out_size)
{
    const float* inputs  = (const float*)d_in[0];
    const float* embed_w = (const float*)d_in[1];
    const float* embed_b = (const float*)d_in[2];
    const float* wq_w    = (const float*)d_in[3];
    const float* wq_b    = (const float*)d_in[4];
    const float* wk_w    = (const float*)d_in[5];
    const float* wk_b    = (const float*)d_in[6];
    const float* wv_w    = (const float*)d_in[7];
    const float* wv_b    = (const float*)d_in[8];
    const float* ln_g    = (const float*)d_in[9];
    const float* ln_b    = (const float*)d_in[10];
    const float* skw     = (const float*)d_in[11];
    const float* sq      = (const float*)d_in[12];
    const float* pos     = (const float*)d_in[13];
    float* out = (float*)d_out;

    cudaFuncSetAttribute((const void*)bf16x3_gemm<true,  false>,
                         cudaFuncAttributeMaxDynamicSharedMemorySize, DYN_SMEM_G);
    cudaFuncSetAttribute((const void*)bf16x3_gemm<false, true>,
                         cudaFuncAttributeMaxDynamicSharedMemorySize, DYN_SMEM_G);
    cudaFuncSetAttribute((const void*)tf32_gemm<false, false>,
                         cudaFuncAttributeMaxDynamicSharedMemorySize, DYN_SMEM_T);
    cudaFuncSetAttribute((const void*)tf32_gemm<false, true>,
                         cudaFuncAttributeMaxDynamicSharedMemorySize, DYN_SMEM_T);
    cudaFuncSetAttribute((const void*)tf32_gemm<true,  true>,
                         cudaFuncAttributeMaxDynamicSharedMemorySize, DYN_SMEM_T);

    float* base = 0;
    cudaGetSymbolAddress((void**)&base, g_scratch);

    u16* INh  = (u16*)(base + O_INS);   u16* INl  = INh  + C_IN;
    u16* EWh  = (u16*)(base + O_EWS);   u16* EWl  = EWh  + C_EW;
    u16* SKWh = (u16*)(base + O_SKWS);  u16* SKWl = SKWh + C_W;
    float* WQT = base + O_WQT;
    float* WKT = base + O_WKT;
    float* WVT = base + O_WVT;
    float* X  = base + O_X;
    float* XT = base + O_XT;
    float* Q  = base + O_Q;
    float* K  = base + O_K;
    float* VT = base + O_VT;
    float* SC = base + O_SC;
    float* Z  = base + O_Z;
    float* H  = base + O_H;
    u16* Hh   = (u16*)(base + O_HS);    u16* Hl   = Hh + C_MAT;
    float* TP = base + O_TP;
    float* OP = base + O_OP;
    float* T  = base + O_T;

    // 0) operand prep
    split_fp32<<<(int)(C_IN / 4 / 256), 256>>>(inputs,  INh,  INl,  (int)(C_IN / 4));
    split_fp32<<<(int)(C_EW / 4 / 256), 256>>>(embed_w, EWh,  EWl,  (int)(C_EW / 4));
    split_fp32<<<(int)(C_W  / 4 / 256), 256>>>(skw,     SKWh, SKWl, (int)(C_W / 4));
    round_tf32<<<(int)(C_W / 4 / 256), 256>>>(wq_w, WQT, (int)(C_W / 4));
    round_tf32<<<(int)(C_W / 4 / 256), 256>>>(wk_w, WKT, (int)(C_W / 4));
    round_tf32<<<(int)(C_W / 4 / 256), 256>>>(wv_w, WVT, (int)(C_W / 4));

    // 1) embed (bf16x3): X = inputs @ embed_w^T + embed_b + pos_enc; also Xt
    bf16x3_gemm<true, false><<<dim3(DMODEL / 128, NROW / 128, 1), 256, DYN_SMEM_G>>>(
        INh, INl, EWh, EWl, X, XT, 0, 0, DMODEL, D_IN, embed_b, pos);

    // 2) Q, K (tf32, rounded out), V (tf32, transposed rounded out)
    tf32_gemm<false, true><<<dim3(DMODEL / 128, NROW / 128, 1), 256, DYN_SMEM_T>>>(
        XT, WQT, Q, DMODEL, DMODEL, 0, 0, 0, 1.0f, wq_b);
    tf32_gemm<false, true><<<dim3(DMODEL / 128, NROW / 128, 1), 256, DYN_SMEM_T>>>(
        XT, WKT, K, DMODEL, DMODEL, 0, 0, 0, 1.0f, wk_b);
    tf32_gemm<true, true><<<dim3(DMODEL / 128, NROW / 128, 1), 256, DYN_SMEM_T>>>(
        XT, WVT, VT, DMODEL, DMODEL, 0, 0, 0, 1.0f, wv_b);

    // 3) scores = Q @ K^T / 32 (batched, tf32, pre-rounded inputs)
    tf32_gemm<false, false><<<dim3(SEQL / 128, SEQL / 128, BATCH), 256, DYN_SMEM_T>>>(
        Q, K, SC, SEQL, DMODEL,
        (long long)SEQL * DMODEL, (long long)SEQL * DMODEL, (long long)SEQL * SEQL,
        1.0f / 32.0f, 0);

    // 4) softmax in place, tf32-rounded output (feeds Z GEMM)
    softmax_rows<true><<<NROW, 256>>>(SC);

    // 5) Z = softmax(SC) @ V  (tf32, pre-rounded inputs)
    tf32_gemm<false, false><<<dim3(DMODEL / 128, SEQL / 128, BATCH), 256, DYN_SMEM_T>>>(
        SC, VT, Z, DMODEL, SEQL,
        (long long)SEQL * SEQL, (long long)DMODEL * SEQL, (long long)SEQL * DMODEL,
        1.0f, 0);

    // 6) H = LN(X + Z)*g + b  (fp32 + split planes for SK)
    add_ln_split<<<NROW, 256>>>(X, Z, ln_g, ln_b, H, Hh, Hl);

    // 7) fused SK GEMM (bf16x3 — unscaled logits need the precision) -> TP
    bf16x3_gemm<false, true><<<dim3(DMODEL / 128, NROW / 128, 1), 256, DYN_SMEM_G>>>(
        Hh, Hl, SKWh, SKWl, 0, 0, TP, sq, DMODEL, DMODEL, 0, 0);

    // 8) T[r] = sum partials; softmax over s per batch (no rounding)
    skt_reduce<<<NROW / 256, 256>>>(TP, T);
    softmax_rows<false><<<BATCH, 256>>>(T);

    // 9) out[b,o] = sum_s w[b,s] * H[b,s,o]  (two-stage, deterministic)
    final_partial<<<dim3(DMODEL / 256, BATCH, 8), 256>>>(H, T, OP);
    final_reduce<<<dim3(DMODEL / 256, BATCH), 256>>>(OP, out);
}

// round 14
// speedup vs baseline: 1.6288x; 1.0773x over previous
#include <cuda_runtime.h>
#include <cstdint>
#include <math.h>

// ---------------------------------------------------------------------------
// Problem constants
// ---------------------------------------------------------------------------
#define BATCH   8
#define SEQL    2048
#define D_IN    512
#define DMODEL  1024
#define NROW    (BATCH * SEQL)          // 16384
#define LN_EPS  1e-5f

typedef unsigned short u16;
typedef uint32_t u32;

// element counts
static const long long C_IN  = (long long)NROW * D_IN;       // 8388608
static const long long C_EW  = (long long)DMODEL * D_IN;     // 524288
static const long long C_W   = (long long)DMODEL * DMODEL;   // 1048576
static const long long C_MAT = (long long)NROW * DMODEL;     // 16777216
static const long long C_SC  = (long long)BATCH * SEQL * SEQL; // 33554432

// scratch offsets (in floats)
#define O_INS   (0LL)
#define O_EWS   (O_INS  + C_IN)
#define O_SKWS  (O_EWS  + C_EW)
#define O_WQT   (O_SKWS + C_W)
#define O_WKT   (O_WQT  + C_W)
#define O_WVT   (O_WKT  + C_W)
#define O_X     (O_WVT  + C_W)
#define O_XT    (O_X    + C_MAT)        // tf32-rounded X
#define O_Q     (O_XT   + C_MAT)        // tf32-rounded Q
#define O_K     (O_Q    + C_MAT)        // tf32-rounded K
#define O_VT    (O_K    + C_MAT)        // tf32-rounded V^T (per batch [n][s])
#define O_SC    (O_VT   + C_MAT)
#define O_Z     (O_SC   + C_SC)
#define O_H     (O_Z    + C_MAT)
#define O_HS    (O_H    + C_MAT)        // split H planes
#define O_TP    (O_HS   + C_MAT)                 // soft-key partials [16384][32]
#define O_OP    (O_TP   + 16384LL * 32)          // final_out partials [64][1024]
#define O_T     (O_OP   + 65536)
#define O_TOTAL (O_T    + 16384)

__device__ float g_scratch[O_TOTAL];

// ---------------------------------------------------------------------------
// PTX helpers (baseline sm_80+ features only — harness targets plain sm_103)
// ---------------------------------------------------------------------------
__device__ __forceinline__ u32 smem_u32(const void* p) {
    u32 a;
    asm("{ .reg .u64 t; cvta.to.shared.u64 t, %1; cvt.u32.u64 %0, t; }"
        : "=r"(a) : "l"(p));
    return a;
}

__device__ __forceinline__ void cp_async16(u32 dst, const void* src) {
    asm volatile("cp.async.cg.shared.global [%0], [%1], 16;" :: "r"(dst), "l"(src));
}
#define CP_COMMIT() asm volatile("cp.async.commit_group;" ::: "memory")
#define CP_WAIT1()  asm volatile("cp.async.wait_group 1;"  ::: "memory")

// split x0,x1 (fp32) into packed bf16x2 hi and lo parts: x = hi + lo
__device__ __forceinline__ void split_pack(float x0, float x1, u32& hi, u32& lo) {
    asm("cvt.rn.bf16x2.f32 %0, %1, %2;" : "=r"(hi) : "f"(x1), "f"(x0));
    const float h0 = __uint_as_float(hi << 16);
    const float h1 = __uint_as_float(hi & 0xFFFF0000u);
    const float l0 = x0 - h0;
    const float l1 = x1 - h1;
    asm("cvt.rn.bf16x2.f32 %0, %1, %2;" : "=r"(lo) : "f"(l1), "f"(l0));
}

__device__ __forceinline__ float f2tf32f(float f) {
    u32 r;
    asm("cvt.rna.tf32.f32 %0, %1;" : "=r"(r) : "f"(f));
    return __uint_as_float(r);
}

// D += A*B  (m16n8k16 bf16, fp32 accum)
__device__ __forceinline__ void mma_bf16(float* d, const u32* a, const u32* b) {
    asm volatile(
        "mma.sync.aligned.m16n8k16.row.col.f32.bf16.bf16.f32 "
        "{%0,%1,%2,%3}, {%4,%5,%6,%7}, {%8,%9}, {%0,%1,%2,%3};"
        : "+f"(d[0]), "+f"(d[1]), "+f"(d[2]), "+f"(d[3])
        : "r"(a[0]), "r"(a[1]), "r"(a[2]), "r"(a[3]), "r"(b[0]), "r"(b[1]));
}

// D += A*B  (m16n8k8 tf32, fp32 accum) — operands pre-rounded to tf32
__device__ __forceinline__ void mma_tf32(float* d, const u32* a, const u32* b) {
    asm volatile(
        "mma.sync.aligned.m16n8k8.row.col.f32.tf32.tf32.f32 "
        "{%0,%1,%2,%3}, {%4,%5,%6,%7}, {%8,%9}, {%0,%1,%2,%3};"
        : "+f"(d[0]), "+f"(d[1]), "+f"(d[2]), "+f"(d[3])
        : "r"(a[0]), "r"(a[1]), "r"(a[2]), "r"(a[3]), "r"(b[0]), "r"(b[1]));
}

__device__ __forceinline__ void ldmat4(u32& r0, u32& r1, u32& r2, u32& r3, u32 addr) {
    asm volatile("ldmatrix.sync.aligned.m8n8.x4.shared.b16 {%0,%1,%2,%3}, [%4];"
                 : "=r"(r0), "=r"(r1), "=r"(r2), "=r"(r3) : "r"(addr));
}

// swizzled byte offset of (row, 16B-chunk ch) in a 128x32 bf16 plane (64B rows)
__device__ __forceinline__ u32 sw_off(u32 row, u32 ch) {
    return row * 64u + ((ch ^ ((row >> 1) & 3u)) << 4);
}

// ---------------------------------------------------------------------------
// bf16x3 split GEMM (embed + SK): C = A@B^T (+bias +posenc)
// R7/R10 proven cadence: 3-buffer, one barrier/chunk, load-after-compute.
//   XTOUT: also write tf32-rounded copy of C (embed; feeds tf32 QKV GEMMs)
//   SKRED: fused soft-key epilogue (partials of sum tanh(C)*q), no C written
// ---------------------------------------------------------------------------
#define PLANE_B  (128 * 64)             // 8192
#define STAGE_B  (4 * PLANE_B)          // 32768
#define DYN_SMEM_G (3 * STAGE_B)        // 98304

template <bool XTOUT, bool SKRED>
__global__ __launch_bounds__(256, 2)
void bf16x3_gemm(const u16* __restrict__ Ahi, const u16* __restrict__ Alo,
                 const u16* __restrict__ Bhi, const u16* __restrict__ Blo,
                 float* __restrict__ Cf, float* __restrict__ Ct,
                 float* __restrict__ TP, const float* __restrict__ qvec,
                 int N, int K,
                 const float* __restrict__ bias,
                 const float* __restrict__ posenc)
{
    extern __shared__ char smem[];

    const int tid  = threadIdx.x;
    const int wid  = tid >> 5;
    const int lane = tid & 31;
    const int wm   = wid >> 2;
    const int wn   = wid & 3;
    const int g    = lane >> 2;
    const int t    = lane & 3;
    const int lrow = lane & 15;
    const int lch  = lane >> 4;

    const int m0 = blockIdx.y * 128;
    const int n0 = blockIdx.x * 128;

    const u32 smem_base = smem_u32(smem);

    float acc[4][4][4];
#pragma unroll
    for (int mi = 0; mi < 4; mi++)
#pragma unroll
        for (int ni = 0; ni < 4; ni++)
#pragma unroll
            for (int c = 0; c < 4; c++) acc[mi][ni][c] = 0.0f;

    const int NC = K >> 5;

    const u32 ld_row = (u32)(tid >> 2);
    const u32 ld_ch  = (u32)(tid & 3);

    auto issue_stage = [&](int c, int buf) {
        const int k0 = c * 32;
        const u32 st = smem_base + buf * STAGE_B;
        const u16* srcs[4] = { Ahi, Alo, Bhi, Blo };
#pragma unroll
        for (int p = 0; p < 4; p++) {
            const u16* src = srcs[p];
            const int rbase = (p < 2) ? m0 : n0;
#pragma unroll
            for (int i = 0; i < 2; i++) {
                const u32 row = ld_row + i * 64;
                cp_async16(st + p * PLANE_B + sw_off(row, ld_ch),
                           src + (long long)(rbase + row) * K + k0 + ld_ch * 8);
            }
        }
        CP_COMMIT();
    };

    issue_stage(0, 0);
    issue_stage(1, 1);

    int buf = 0;
    int nbuf = 2;
    for (int c = 0; c < NC; ++c) {
        CP_WAIT1();
        __syncthreads();

        const u32 st = smem_base + buf * STAGE_B;

#pragma unroll
        for (int half = 0; half < 2; half++) {
            const u32 ch = (u32)(half * 2 + lch);

            u32 bh[4][2], bl[4][2];
#pragma unroll
            for (int nj = 0; nj < 2; nj++) {
                const u32 rb = sw_off((u32)(wn * 32 + nj * 16 + lrow), ch);
                u32 r0, r1, r2, r3;
                ldmat4(r0, r1, r2, r3, st + 2 * PLANE_B + rb);
                bh[2*nj][0] = r0; bh[2*nj+1][0] = r1;
                bh[2*nj][1] = r2; bh[2*nj+1][1] = r3;
                ldmat4(r0, r1, r2, r3, st + 3 * PLANE_B + rb);
                bl[2*nj][0] = r0; bl[2*nj+1][0] = r1;
                bl[2*nj][1] = r2; bl[2*nj+1][1] = r3;
            }

#pragma unroll
            for (int mp = 0; mp < 2; mp++) {
                u32 ah[2][4], al[2][4];
#pragma unroll
                for (int q = 0; q < 2; q++) {
                    const int mi = mp * 2 + q;
                    const u32 ra = sw_off((u32)(wm * 64 + mi * 16 + lrow), ch);
                    ldmat4(ah[q][0], ah[q][1], ah[q][2], ah[q][3], st + ra);
                    ldmat4(al[q][0], al[q][1], al[q][2], al[q][3], st + PLANE_B + ra);
                }
#pragma unroll
                for (int q = 0; q < 2; q++)
#pragma unroll
                    for (int ni = 0; ni < 4; ni++)
                        mma_bf16(acc[mp*2+q][ni], ah[q], bh[ni]);
#pragma unroll
                for (int q = 0; q < 2; q++)
#pragma unroll
                    for (int ni = 0; ni < 4; ni++)
                        mma_bf16(acc[mp*2+q][ni], ah[q], bl[ni]);
#pragma unroll
                for (int q = 0; q < 2; q++)
#pragma unroll
                    for (int ni = 0; ni < 4; ni++)
                        mma_bf16(acc[mp*2+q][ni], al[q], bh[ni]);
            }
        }

        if (c + 2 < NC) issue_stage(c + 2, nbuf);
        else            CP_COMMIT();

        buf  = (buf  == 2) ? 0 : buf  + 1;
        nbuf = (nbuf == 2) ? 0 : nbuf + 1;
    }

    // ---- epilogue ----
    if (SKRED) {
#pragma unroll
        for (int mi = 0; mi < 4; mi++) {
            float p0 = 0.0f, p1 = 0.0f;
#pragma unroll
            for (int ni = 0; ni < 4; ni++) {
                const int n = n0 + wn * 32 + ni * 8 + 2 * t;
                const float q0 = qvec[n], q1 = qvec[n + 1];
                p0 += tanhf(acc[mi][ni][0]) * q0 + tanhf(acc[mi][ni][1]) * q1;
                p1 += tanhf(acc[mi][ni][2]) * q0 + tanhf(acc[mi][ni][3]) * q1;
            }
            p0 += __shfl_xor_sync(0xffffffffu, p0, 1);
            p0 += __shfl_xor_sync(0xffffffffu, p0, 2);
            p1 += __shfl_xor_sync(0xffffffffu, p1, 1);
            p1 += __shfl_xor_sync(0xffffffffu, p1, 2);
            if (t == 0) {
                const int m_lo = m0 + wm * 64 + mi * 16 + g;
                const int slot = blockIdx.x * 4 + wn;
                TP[(long long)m_lo * 32 + slot]       = p0;
                TP[(long long)(m_lo + 8) * 32 + slot] = p1;
            }
        }
        return;
    }

#pragma unroll
    for (int mi = 0; mi < 4; mi++) {
        const int m_lo = m0 + wm * 64 + mi * 16 + g;
        const int m_hi = m_lo + 8;
        const float* pe_lo = posenc + (long long)(m_lo & (SEQL - 1)) * N;
        const float* pe_hi = posenc + (long long)(m_hi & (SEQL - 1)) * N;
#pragma unroll
        for (int ni = 0; ni < 4; ni++) {
            const int n = n0 + wn * 32 + ni * 8 + 2 * t;
            const float b0 = bias[n], b1 = bias[n + 1];
            float2 v0, v1;
            v0.x = acc[mi][ni][0] + b0 + pe_lo[n];
            v0.y = acc[mi][ni][1] + b1 + pe_lo[n + 1];
            v1.x = acc[mi][ni][2] + b0 + pe_hi[n];
            v1.y = acc[mi][ni][3] + b1 + pe_hi[n + 1];
            *(float2*)(Cf + (long long)m_lo * N + n) = v0;
            *(float2*)(Cf + (long long)m_hi * N + n) = v1;
            if (XTOUT) {
                float2 t0, t1;
                t0.x = f2tf32f(v0.x); t0.y = f2tf32f(v0.y);
                t1.x = f2tf32f(v1.x); t1.y = f2tf32f(v1.y);
                *(float2*)(Ct + (long long)m_lo * N + n) = t0;
                *(float2*)(Ct + (long long)m_hi * N + n) = t1;
            }
        }
    }
}

// ---------------------------------------------------------------------------
// tf32 GEMM on PRE-ROUNDED tf32 operands, ldmatrix fragment loads:
//   C[m,n] = alpha * sum_k A[m,k]*B[n,k]  (+bias)
// An 8x8 b16 ldmatrix over fp32 data gives lane 4g+c element [g][c] of an
// 8-row x 4-float tile — exactly the tf32 m16n8k8 fragment ownership.
// One ldmatrix.x4 per A fragment (mi) / per B fragment pair (2 ni).
// 144B row stride -> the 8 rows of each phase hit distinct bank quads.
//   ROUND:  round output to tf32 (Q, K — consumed only by scores GEMM)
//   FTRANS: write C transposed per batch, tf32-rounded (V^T)
// ---------------------------------------------------------------------------
#define TF_STRIDE       36
#define TF_TILE_FLOATS  (128 * TF_STRIDE)      // 4608
#define TF_STAGE_FLOATS (2 * TF_TILE_FLOATS)   // 9216
#define TF_STAGE_BYTES  (TF_STAGE_FLOATS * 4)  // 36864
#define DYN_SMEM_T      (3 * TF_STAGE_BYTES)   // 110592

template <bool FTRANS, bool ROUND>
__global__ __launch_bounds__(256, 2)
void tf32_gemm(const float* __restrict__ A, const float* __restrict__ B,
               float* __restrict__ C,
               int N, int K,
               long long sA, long long sB, long long sC,
               float alpha, const float* __restrict__ bias)
{
    extern __shared__ float smf[];

    const int tid  = threadIdx.x;
    const int wid  = tid >> 5;
    const int lane = tid & 31;
    const int wm   = wid >> 2;
    const int wn   = wid & 3;
    const int g    = lane >> 2;
    const int t    = lane & 3;

    const int bz = blockIdx.z;
    A += bz * sA; B += bz * sB; C += bz * sC;
    const int m0 = blockIdx.y * 128;
    const int n0 = blockIdx.x * 128;

    const u32 smem_base = smem_u32(smf);

    // ldmatrix per-lane address components (j = matrix idx, r = row in matrix)
    const int lj = lane >> 3;
    const int lr = lane & 7;
    // A x4: matrices = {rows lo/hi (j&1)} x {k lo/hi (j>>1)}  -> af[0..3]
    const u32 aLane = (u32)(((wm * 64 + (lj & 1) * 8 + lr) * TF_STRIDE
                             + (lj >> 1) * 4) * 4);
    // B x4: matrices = {ni pair row-half (j>>1)} x {k lo/hi (j&1)} -> b[2nj..][0..1]
    const u32 bLane = (u32)(((wn * 32 + (lj >> 1) * 8 + lr) * TF_STRIDE
                             + (lj & 1) * 4) * 4);

    float acc[4][4][4];
#pragma unroll
    for (int mi = 0; mi < 4; mi++)
#pragma unroll
        for (int ni = 0; ni < 4; ni++)
#pragma unroll
            for (int c = 0; c < 4; c++) acc[mi][ni][c] = 0.0f;

    const int NC = K >> 5;

    auto issue_stage = [&](int c, int buf) {
        const int k0 = c * 32;
        const u32 st = smem_base + buf * TF_STAGE_BYTES;
#pragma unroll
        for (int i = 0; i < 4; i++) {
            const int e   = tid + i * 256;
            const int row = e >> 3;
            const int q   = e & 7;
            cp_async16(st + (row * TF_STRIDE + q * 4) * 4,
                       A + (long long)(m0 + row) * K + k0 + q * 4);
        }
#pragma unroll
        for (int i = 0; i < 4; i++) {
            const int e   = tid + i * 256;
            const int row = e >> 3;
            const int q   = e & 7;
            cp_async16(st + TF_TILE_FLOATS * 4 + (row * TF_STRIDE + q * 4) * 4,
                       B + (long long)(n0 + row) * K + k0 + q * 4);
        }
        CP_COMMIT();
    };

    issue_stage(0, 0);
    issue_stage(1, 1);

    int buf = 0;
    int nbuf = 2;
    for (int c = 0; c < NC; ++c) {
        CP_WAIT1();
        __syncthreads();

        const u32 stA = smem_base + buf * TF_STAGE_BYTES + aLane;
        const u32 stB = smem_base + buf * TF_STAGE_BYTES + TF_TILE_FLOATS * 4 + bLane;

#pragma unroll
        for (int ks = 0; ks < 4; ks++) {
            const u32 kkB = (u32)(ks * 8 * 4);

            // B fragments: 2 x ldmatrix.x4 cover all 4 ni
            u32 bf[4][2];
            ldmat4(bf[0][0], bf[0][1], bf[1][0], bf[1][1], stB + kkB);
            ldmat4(bf[2][0], bf[2][1], bf[3][0], bf[3][1],
                   stB + 16 * TF_STRIDE * 4 + kkB);

#pragma unroll
            for (int mp = 0; mp < 2; mp++) {
                u32 af[2][4];
#pragma unroll
                for (int q = 0; q < 2; q++) {
                    const u32 ra = stA + (u32)((mp * 2 + q) * 16 * TF_STRIDE * 4) + kkB;
                    ldmat4(af[q][0], af[q][1], af[q][2], af[q][3], ra);
                }
#pragma unroll
                for (int q = 0; q < 2; q++)
#pragma unroll
                    for (int ni = 0; ni < 4; ni++)
                        mma_tf32(acc[mp*2+q][ni], af[q], bf[ni]);
            }
        }

        if (c + 2 < NC) issue_stage(c + 2, nbuf);
        else            CP_COMMIT();

        buf  = (buf  == 2) ? 0 : buf  + 1;
        nbuf = (nbuf == 2) ? 0 : nbuf + 1;
    }

#pragma unroll
    for (int mi = 0; mi < 4; mi++) {
        const int m_lo = m0 + wm * 64 + mi * 16 + g;
        const int m_hi = m_lo + 8;
#pragma unroll
        for (int ni = 0; ni < 4; ni++) {
            const int n = n0 + wn * 32 + ni * 8 + 2 * t;
            float2 v0, v1;
            v0.x = acc[mi][ni][0] * alpha;
            v0.y = acc[mi][ni][1] * alpha;
            v1.x = acc[mi][ni][2] * alpha;
            v1.y = acc[mi][ni][3] * alpha;
            if (bias) {
                const float b0 = bias[n], b1 = bias[n + 1];
                v0.x += b0; v0.y += b1;
                v1.x += b0; v1.y += b1;
            }
            if (ROUND || FTRANS) {
                v0.x = f2tf32f(v0.x); v0.y = f2tf32f(v0.y);
                v1.x = f2tf32f(v1.x); v1.y = f2tf32f(v1.y);
            }
            if (FTRANS) {
                // V^T: out[b][n][s], m = b*SEQL + s; DMODEL*SEQL = 1<<21
                const long long base_lo = ((long long)(m_lo >> 11) << 21) + (m_lo & 2047);
                const long long base_hi = ((long long)(m_hi >> 11) << 21) + (m_hi & 2047);
                C[base_lo + (long long)n * SEQL]       = v0.x;
                C[base_lo + (long long)(n + 1) * SEQL] = v0.y;
                C[base_hi + (long long)n * SEQL]       = v1.x;
                C[base_hi + (long long)(n + 1) * SEQL] = v1.y;
            } else {
                *(float2*)(C + (long long)m_lo * N + n) = v0;
                *(float2*)(C + (long long)m_hi * N + n) = v1;
            }
        }
    }
}

// ---------------------------------------------------------------------------
// fp32 -> split bf16 hi/lo planes (4 elems per thread)
// ---------------------------------------------------------------------------
__global__ void split_fp32(const float* __restrict__ src,
                           u16* __restrict__ hi, u16* __restrict__ lo, int n4)
{
    const int i = blockIdx.x * blockDim.x + threadIdx.x;
    if (i >= n4) return;
    const float4 v = ((const float4*)src)[i];
    u32 h01, l01, h23, l23;
    split_pack(v.x, v.y, h01, l01);
    split_pack(v.z, v.w, h23, l23);
    ((uint2*)hi)[i] = make_uint2(h01, h23);
    ((uint2*)lo)[i] = make_uint2(l01, l23);
}

// ---------------------------------------------------------------------------
// three fp32 weight mats -> tf32-rounded fp32 (grid.y selects src/dst)
// ---------------------------------------------------------------------------
__global__ void round3_tf32(const float* __restrict__ s0, const float* __restrict__ s1,
                            const float* __restrict__ s2, float* __restrict__ d0,
                            float* __restrict__ d1, float* __restrict__ d2, int n4)
{
    const int i = blockIdx.x * blockDim.x + threadIdx.x;
    if (i >= n4) return;
    const float* src = (blockIdx.y == 0) ? s0 : (blockIdx.y == 1) ? s1 : s2;
    float* dst       = (blockIdx.y == 0) ? d0 : (blockIdx.y == 1) ? d1 : d2;
    float4 v = ((const float4*)src)[i];
    v.x = f2tf32f(v.x); v.y = f2tf32f(v.y);
    v.z = f2tf32f(v.z); v.w = f2tf32f(v.w);
    ((float4*)dst)[i] = v;
}

// ---------------------------------------------------------------------------
// Row softmax, in place, row length 2048.  RND: tf32-round outputs.
// ---------------------------------------------------------------------------
template <bool RND>
__global__ void softmax_rows(float* __restrict__ S)
{
    float* row = S + (long long)blockIdx.x * 2048;
    const int tid = threadIdx.x;
    __shared__ float red[256];

    float v[8];
    *(float4*)&v[0] = *(const float4*)(row + tid * 8);
    *(float4*)&v[4] = *(const float4*)(row + tid * 8 + 4);

    float mx = -1e30f;
#pragma unroll
    for (int i = 0; i < 8; i++) mx = fmaxf(mx, v[i]);
    red[tid] = mx; __syncthreads();
    for (int s = 128; s > 0; s >>= 1) {
        if (tid < s) red[tid] = fmaxf(red[tid], red[tid + s]);
        __syncthreads();
    }
    mx = red[0]; __syncthreads();

    float sum = 0.0f;
#pragma unroll
    for (int i = 0; i < 8; i++) { v[i] = __expf(v[i] - mx); sum += v[i]; }
    red[tid] = sum; __syncthreads();
    for (int s = 128; s > 0; s >>= 1) {
        if (tid < s) red[tid] += red[tid + s];
        __syncthreads();
    }
    const float inv = 1.0f / red[0];
#pragma unroll
    for (int i = 0; i < 8; i++) {
        v[i] *= inv;
        if (RND) v[i] = f2tf32f(v[i]);
    }
    *(float4*)(row + tid * 8)     = *(float4*)&v[0];
    *(float4*)(row + tid * 8 + 4) = *(float4*)&v[4];
}

// ---------------------------------------------------------------------------
// h = x + z ; H = LN(h)*g + b  -> fp32 H + split planes (for bf16x3 SK GEMM)
// ---------------------------------------------------------------------------
__global__ void add_ln_split(const float* __restrict__ X, const float* __restrict__ Z,
                             const float* __restrict__ g, const float* __restrict__ b,
                             float* __restrict__ H, u16* __restrict__ hi, u16* __restrict__ lo)
{
    const long long r = blockIdx.x;
    const int tid = threadIdx.x;
    const int c0  = tid * 4;
    const float* xr = X + r * DMODEL;
    const float* zr = Z + r * DMODEL;
    __shared__ float red[256];

    float4 x4 = *(const float4*)(xr + c0);
    float4 z4 = *(const float4*)(zr + c0);
    float h[4] = { x4.x + z4.x, x4.y + z4.y, x4.z + z4.z, x4.w + z4.w };

    float sum = h[0] + h[1] + h[2] + h[3];
    red[tid] = sum; __syncthreads();
    for (int s = 128; s > 0; s >>= 1) {
        if (tid < s) red[tid] += red[tid + s];
        __syncthreads();
    }
    const float mean = red[0] * (1.0f / DMODEL);
    __syncthreads();

    float vs = 0.0f;
#pragma unroll
    for (int i = 0; i < 4; i++) { const float d = h[i] - mean; vs += d * d; }
    red[tid] = vs; __syncthreads();
    for (int s = 128; s > 0; s >>= 1) {
        if (tid < s) red[tid] += red[tid + s];
        __syncthreads();
    }
    const float inv = rsqrtf(red[0] * (1.0f / DMODEL) + LN_EPS);

    float4 o;
    o.x = (h[0] - mean) * inv * g[c0 + 0] + b[c0 + 0];
    o.y = (h[1] - mean) * inv * g[c0 + 1] + b[c0 + 1];
    o.z = (h[2] - mean) * inv * g[c0 + 2] + b[c0 + 2];
    o.w = (h[3] - mean) * inv * g[c0 + 3] + b[c0 + 3];
    *(float4*)(H + r * DMODEL + c0) = o;

    u32 h01, l01, h23, l23;
    split_pack(o.x, o.y, h01, l01);
    split_pack(o.z, o.w, h23, l23);
    const long long pi = (r * DMODEL + c0) >> 1;
    ((u32*)hi)[pi]     = h01;
    ((u32*)hi)[pi + 1] = h23;
    ((u32*)lo)[pi]     = l01;
    ((u32*)lo)[pi + 1] = l23;
}

// ---------------------------------------------------------------------------
// T[r] = sum of 32 soft-key partials (deterministic fixed-order reduce)
// ---------------------------------------------------------------------------
__global__ void skt_reduce(const float* __restrict__ TP, float* __restrict__ T)
{
    const int r = blockIdx.x * 256 + threadIdx.x;
    const float* p = TP + (long long)r * 32;
    float s = 0.0f;
#pragma unroll
    for (int j = 0; j < 32; j++) s += p[j];
    T[r] = s;
}

// ---------------------------------------------------------------------------
// final_out stage 1: partial over 256-row s-chunk
// ---------------------------------------------------------------------------
__global__ void final_partial(const float* __restrict__ H, const float* __restrict__ w,
                              float* __restrict__ OP)
{
    const int b  = blockIdx.y;
    const int zc = blockIdx.z;
    const int o  = blockIdx.x * 256 + threadIdx.x;
    const float* Hp = H + (long long)b * SEQL * DMODEL
                        + (long long)(zc * 256) * DMODEL + o;
    const float* wb = w + (long long)b * SEQL + zc * 256;

    float a0 = 0.0f, a1 = 0.0f, a2 = 0.0f, a3 = 0.0f;
    for (int s = 0; s < 256; s += 4) {
        a0 += wb[s + 0] * Hp[(long long)(s + 0) * DMODEL];
        a1 += wb[s + 1] * Hp[(long long)(s + 1) * DMODEL];
        a2 += wb[s + 2] * Hp[(long long)(s + 2) * DMODEL];
        a3 += wb[s + 3] * Hp[(long long)(s + 3) * DMODEL];
    }
    OP[(long long)(b * 8 + zc) * DMODEL + o] = (a0 + a1) + (a2 + a3);
}

// final_out stage 2
__global__ void final_reduce(const float* __restrict__ OP, float* __restrict__ out)
{
    const int b = blockIdx.y;
    const int o = blockIdx.x * 256 + threadIdx.x;
    float s = 0.0f;
#pragma unroll
    for (int z = 0; z < 8; z++)
        s += OP[(long long)(b * 8 + z) * DMODEL + o];
    out[b * DMODEL + o] = s;
}

// ---------------------------------------------------------------------------
// Launch
// ---------------------------------------------------------------------------
extern "C" void kernel_launch(void* const* d_in, const int* in_sizes, int n_in,
                              void* d_out, int out_size)
{
    const float* inputs  = (const float*)d_in[0];
    const float* embed_w = (const float*)d_in[1];
    const float* embed_b = (const float*)d_in[2];
    const float* wq_w    = (const float*)d_in[3];
    const float* wq_b    = (const float*)d_in[4];
    const float* wk_w    = (const float*)d_in[5];
    const float* wk_b    = (const float*)d_in[6];
    const float* wv_w    = (const float*)d_in[7];
    const float* wv_b    = (const float*)d_in[8];
    const float* ln_g    = (const float*)d_in[9];
    const float* ln_b    = (const float*)d_in[10];
    const float* skw     = (const float*)d_in[11];
    const float* sq      = (const float*)d_in[12];
    const float* pos     = (const float*)d_in[13];
    float* out = (float*)d_out;

    cudaFuncSetAttribute((const void*)bf16x3_gemm<true,  false>,
                         cudaFuncAttributeMaxDynamicSharedMemorySize, DYN_SMEM_G);
    cudaFuncSetAttribute((const void*)bf16x3_gemm<false, true>,
                         cudaFuncAttributeMaxDynamicSharedMemorySize, DYN_SMEM_G);
    cudaFuncSetAttribute((const void*)tf32_gemm<false, false>,
                         cudaFuncAttributeMaxDynamicSharedMemorySize, DYN_SMEM_T);
    cudaFuncSetAttribute((const void*)tf32_gemm<false, true>,
                         cudaFuncAttributeMaxDynamicSharedMemorySize, DYN_SMEM_T);
    cudaFuncSetAttribute((const void*)tf32_gemm<true,  true>,
                         cudaFuncAttributeMaxDynamicSharedMemorySize, DYN_SMEM_T);

    float* base = 0;
    cudaGetSymbolAddress((void**)&base, g_scratch);

    u16* INh  = (u16*)(base + O_INS);   u16* INl  = INh  + C_IN;
    u16* EWh  = (u16*)(base + O_EWS);   u16* EWl  = EWh  + C_EW;
    u16* SKWh = (u16*)(base + O_SKWS);  u16* SKWl = SKWh + C_W;
    float* WQT = base + O_WQT;
    float* WKT = base + O_WKT;
    float* WVT = base + O_WVT;
    float* X  = base + O_X;
    float* XT = base + O_XT;
    float* Q  = base + O_Q;
    float* K  = base + O_K;
    float* VT = base + O_VT;
    float* SC = base + O_SC;
    float* Z  = base + O_Z;
    float* H  = base + O_H;
    u16* Hh   = (u16*)(base + O_HS);    u16* Hl   = Hh + C_MAT;
    float* TP = base + O_TP;
    float* OP = base + O_OP;
    float* T  = base + O_T;

    // 0) operand prep (4 launches; 5th = embed, 6th = Q tf32 GEMM -> ncu target)
    split_fp32<<<(int)(C_IN / 4 / 256), 256>>>(inputs,  INh,  INl,  (int)(C_IN / 4));
    split_fp32<<<(int)(C_EW / 4 / 256), 256>>>(embed_w, EWh,  EWl,  (int)(C_EW / 4));
    split_fp32<<<(int)(C_W  / 4 / 256), 256>>>(skw,     SKWh, SKWl, (int)(C_W / 4));
    round3_tf32<<<dim3((int)(C_W / 4 / 256), 3), 256>>>(
        wq_w, wk_w, wv_w, WQT, WKT, WVT, (int)(C_W / 4));

    // 1) embed (bf16x3): X = inputs @ embed_w^T + embed_b + pos_enc; also Xt
    bf16x3_gemm<true, false><<<dim3(DMODEL / 128, NROW / 128, 1), 256, DYN_SMEM_G>>>(
        INh, INl, EWh, EWl, X, XT, 0, 0, DMODEL, D_IN, embed_b, pos);

    // 2) Q, K (tf32, rounded out), V (tf32, transposed rounded out)
    tf32_gemm<false, true><<<dim3(DMODEL / 128, NROW / 128, 1), 256, DYN_SMEM_T>>>(
        XT, WQT, Q, DMODEL, DMODEL, 0, 0, 0, 1.0f, wq_b);
    tf32_gemm<false, true><<<dim3(DMODEL / 128, NROW / 128, 1), 256, DYN_SMEM_T>>>(
        XT, WKT, K, DMODEL, DMODEL, 0, 0, 0, 1.0f, wk_b);
    tf32_gemm<true, true><<<dim3(DMODEL / 128, NROW / 128, 1), 256, DYN_SMEM_T>>>(
        XT, WVT, VT, DMODEL, DMODEL, 0, 0, 0, 1.0f, wv_b);

    // 3) scores = Q @ K^T / 32 (batched, tf32, pre-rounded inputs)
    tf32_gemm<false, false><<<dim3(SEQL / 128, SEQL / 128, BATCH), 256, DYN_SMEM_T>>>(
        Q, K, SC, SEQL, DMODEL,
        (long long)SEQL * DMODEL, (long long)SEQL * DMODEL, (long long)SEQL * SEQL,
        1.0f / 32.0f, 0);

    // 4) softmax in place, tf32-rounded output (feeds Z GEMM)
    softmax_rows<true><<<NROW, 256>>>(SC);

    // 5) Z = softmax(SC) @ V  (tf32, pre-rounded inputs)
    tf32_gemm<false, false><<<dim3(DMODEL / 128, SEQL / 128, BATCH), 256, DYN_SMEM_T>>>(
        SC, VT, Z, DMODEL, SEQL,
        (long long)SEQL * SEQL, (long long)DMODEL * SEQL, (long long)SEQL * DMODEL,
        1.0f, 0);

    // 6) H = LN(X + Z)*g + b  (fp32 + split planes for SK)
    add_ln_split<<<NROW, 256>>>(X, Z, ln_g, ln_b, H, Hh, Hl);

    // 7) fused SK GEMM (bf16x3 — unscaled logits need the precision) -> TP
    bf16x3_gemm<false, true><<<dim3(DMODEL / 128, NROW / 128, 1), 256, DYN_SMEM_G>>>(
        Hh, Hl, SKWh, SKWl, 0, 0, TP, sq, DMODEL, DMODEL, 0, 0);

    // 8) T[r] = sum partials; softmax over s per batch (no rounding)
    skt_reduce<<<NROW / 256, 256>>>(TP, T);
    softmax_rows<false><<<BATCH, 256>>>(T);

    // 9) out[b,o] = sum_s w[b,s] * H[b,s,o]  (two-stage, deterministic)
    final_partial<<<dim3(DMODEL / 256, BATCH, 8), 256>>>(H, T, OP);
    final_reduce<<<dim3(DMODEL / 256, BATCH), 256>>>(OP, out);
}

// round 15
// speedup vs baseline: 1.6353x; 1.0040x over previous
#include <cuda_runtime.h>
#include <cstdint>
#include <math.h>

// ---------------------------------------------------------------------------
// Problem constants
// ---------------------------------------------------------------------------
#define BATCH   8
#define SEQL    2048
#define D_IN    512
#define DMODEL  1024
#define NROW    (BATCH * SEQL)          // 16384
#define LN_EPS  1e-5f

typedef unsigned short u16;
typedef uint32_t u32;

// element counts
static const long long C_IN  = (long long)NROW * D_IN;       // 8388608
static const long long C_EW  = (long long)DMODEL * D_IN;     // 524288
static const long long C_W   = (long long)DMODEL * DMODEL;   // 1048576
static const long long C_MAT = (long long)NROW * DMODEL;     // 16777216
static const long long C_SC  = (long long)BATCH * SEQL * SEQL; // 33554432

// scratch offsets (in floats)
#define O_INS   (0LL)
#define O_EWS   (O_INS  + C_IN)
#define O_SKWS  (O_EWS  + C_EW)
#define O_WQT   (O_SKWS + C_W)
#define O_WKT   (O_WQT  + C_W)
#define O_WVT   (O_WKT  + C_W)
#define O_X     (O_WVT  + C_W)
#define O_XT    (O_X    + C_MAT)        // tf32-rounded X
#define O_Q     (O_XT   + C_MAT)        // tf32-rounded Q
#define O_K     (O_Q    + C_MAT)        // tf32-rounded K
#define O_VT    (O_K    + C_MAT)        // tf32-rounded V^T (per batch [n][s])
#define O_SC    (O_VT   + C_MAT)
#define O_Z     (O_SC   + C_SC)
#define O_H     (O_Z    + C_MAT)
#define O_HS    (O_H    + C_MAT)        // split H planes
#define O_TP    (O_HS   + C_MAT)                 // soft-key partials [16384][32]
#define O_OP    (O_TP   + 16384LL * 32)          // final_out partials [64][1024]
#define O_T     (O_OP   + 65536)
#define O_TOTAL (O_T    + 16384)

__device__ float g_scratch[O_TOTAL];

// ---------------------------------------------------------------------------
// PTX helpers (baseline sm_80+ features only — harness targets plain sm_103)
// ---------------------------------------------------------------------------
__device__ __forceinline__ u32 smem_u32(const void* p) {
    u32 a;
    asm("{ .reg .u64 t; cvta.to.shared.u64 t, %1; cvt.u32.u64 %0, t; }"
        : "=r"(a) : "l"(p));
    return a;
}

__device__ __forceinline__ void cp_async16(u32 dst, const void* src) {
    asm volatile("cp.async.cg.shared.global [%0], [%1], 16;" :: "r"(dst), "l"(src));
}
#define CP_COMMIT() asm volatile("cp.async.commit_group;" ::: "memory")
#define CP_WAIT1()  asm volatile("cp.async.wait_group 1;"  ::: "memory")

// split x0,x1 (fp32) into packed bf16x2 hi and lo parts: x = hi + lo
__device__ __forceinline__ void split_pack(float x0, float x1, u32& hi, u32& lo) {
    asm("cvt.rn.bf16x2.f32 %0, %1, %2;" : "=r"(hi) : "f"(x1), "f"(x0));
    const float h0 = __uint_as_float(hi << 16);
    const float h1 = __uint_as_float(hi & 0xFFFF0000u);
    const float l0 = x0 - h0;
    const float l1 = x1 - h1;
    asm("cvt.rn.bf16x2.f32 %0, %1, %2;" : "=r"(lo) : "f"(l1), "f"(l0));
}

__device__ __forceinline__ float f2tf32f(float f) {
    u32 r;
    asm("cvt.rna.tf32.f32 %0, %1;" : "=r"(r) : "f"(f));
    return __uint_as_float(r);
}

// D += A*B  (m16n8k16 bf16, fp32 accum)
__device__ __forceinline__ void mma_bf16(float* d, const u32* a, const u32* b) {
    asm volatile(
        "mma.sync.aligned.m16n8k16.row.col.f32.bf16.bf16.f32 "
        "{%0,%1,%2,%3}, {%4,%5,%6,%7}, {%8,%9}, {%0,%1,%2,%3};"
        : "+f"(d[0]), "+f"(d[1]), "+f"(d[2]), "+f"(d[3])
        : "r"(a[0]), "r"(a[1]), "r"(a[2]), "r"(a[3]), "r"(b[0]), "r"(b[1]));
}

// D += A*B  (m16n8k8 tf32, fp32 accum) — operands pre-rounded to tf32
__device__ __forceinline__ void mma_tf32(float* d, const u32* a, const u32* b) {
    asm volatile(
        "mma.sync.aligned.m16n8k8.row.col.f32.tf32.tf32.f32 "
        "{%0,%1,%2,%3}, {%4,%5,%6,%7}, {%8,%9}, {%0,%1,%2,%3};"
        : "+f"(d[0]), "+f"(d[1]), "+f"(d[2]), "+f"(d[3])
        : "r"(a[0]), "r"(a[1]), "r"(a[2]), "r"(a[3]), "r"(b[0]), "r"(b[1]));
}

__device__ __forceinline__ void ldmat4(u32& r0, u32& r1, u32& r2, u32& r3, u32 addr) {
    asm volatile("ldmatrix.sync.aligned.m8n8.x4.shared.b16 {%0,%1,%2,%3}, [%4];"
                 : "=r"(r0), "=r"(r1), "=r"(r2), "=r"(r3) : "r"(addr));
}

// swizzled byte offset of (row, 16B-chunk ch) in a 128x32 bf16 plane (64B rows)
__device__ __forceinline__ u32 sw_off(u32 row, u32 ch) {
    return row * 64u + ((ch ^ ((row >> 1) & 3u)) << 4);
}

// ---------------------------------------------------------------------------
// bf16x3 split GEMM (embed + SK): C = A@B^T (+bias +posenc)
// R7/R10 proven cadence: 3-buffer, one barrier/chunk, load-after-compute.
//   XTOUT: also write tf32-rounded copy of C (embed; feeds tf32 QKV GEMMs)
//   SKRED: fused soft-key epilogue (partials of sum tanh(C)*q), no C written
// ---------------------------------------------------------------------------
#define PLANE_B  (128 * 64)             // 8192
#define STAGE_B  (4 * PLANE_B)          // 32768
#define DYN_SMEM_G (3 * STAGE_B)        // 98304

template <bool XTOUT, bool SKRED>
__global__ __launch_bounds__(256, 2)
void bf16x3_gemm(const u16* __restrict__ Ahi, const u16* __restrict__ Alo,
                 const u16* __restrict__ Bhi, const u16* __restrict__ Blo,
                 float* __restrict__ Cf, float* __restrict__ Ct,
                 float* __restrict__ TP, const float* __restrict__ qvec,
                 int N, int K,
                 const float* __restrict__ bias,
                 const float* __restrict__ posenc)
{
    extern __shared__ char smem[];

    const int tid  = threadIdx.x;
    const int wid  = tid >> 5;
    const int lane = tid & 31;
    const int wm   = wid >> 2;
    const int wn   = wid & 3;
    const int g    = lane >> 2;
    const int t    = lane & 3;
    const int lrow = lane & 15;
    const int lch  = lane >> 4;

    const int m0 = blockIdx.y * 128;
    const int n0 = blockIdx.x * 128;

    const u32 smem_base = smem_u32(smem);

    float acc[4][4][4];
#pragma unroll
    for (int mi = 0; mi < 4; mi++)
#pragma unroll
        for (int ni = 0; ni < 4; ni++)
#pragma unroll
            for (int c = 0; c < 4; c++) acc[mi][ni][c] = 0.0f;

    const int NC = K >> 5;

    const u32 ld_row = (u32)(tid >> 2);
    const u32 ld_ch  = (u32)(tid & 3);

    auto issue_stage = [&](int c, int buf) {
        const int k0 = c * 32;
        const u32 st = smem_base + buf * STAGE_B;
        const u16* srcs[4] = { Ahi, Alo, Bhi, Blo };
#pragma unroll
        for (int p = 0; p < 4; p++) {
            const u16* src = srcs[p];
            const int rbase = (p < 2) ? m0 : n0;
#pragma unroll
            for (int i = 0; i < 2; i++) {
                const u32 row = ld_row + i * 64;
                cp_async16(st + p * PLANE_B + sw_off(row, ld_ch),
                           src + (long long)(rbase + row) * K + k0 + ld_ch * 8);
            }
        }
        CP_COMMIT();
    };

    issue_stage(0, 0);
    issue_stage(1, 1);

    int buf = 0;
    int nbuf = 2;
    for (int c = 0; c < NC; ++c) {
        CP_WAIT1();
        __syncthreads();

        const u32 st = smem_base + buf * STAGE_B;

#pragma unroll
        for (int half = 0; half < 2; half++) {
            const u32 ch = (u32)(half * 2 + lch);

            u32 bh[4][2], bl[4][2];
#pragma unroll
            for (int nj = 0; nj < 2; nj++) {
                const u32 rb = sw_off((u32)(wn * 32 + nj * 16 + lrow), ch);
                u32 r0, r1, r2, r3;
                ldmat4(r0, r1, r2, r3, st + 2 * PLANE_B + rb);
                bh[2*nj][0] = r0; bh[2*nj+1][0] = r1;
                bh[2*nj][1] = r2; bh[2*nj+1][1] = r3;
                ldmat4(r0, r1, r2, r3, st + 3 * PLANE_B + rb);
                bl[2*nj][0] = r0; bl[2*nj+1][0] = r1;
                bl[2*nj][1] = r2; bl[2*nj+1][1] = r3;
            }

#pragma unroll
            for (int mp = 0; mp < 2; mp++) {
                u32 ah[2][4], al[2][4];
#pragma unroll
                for (int q = 0; q < 2; q++) {
                    const int mi = mp * 2 + q;
                    const u32 ra = sw_off((u32)(wm * 64 + mi * 16 + lrow), ch);
                    ldmat4(ah[q][0], ah[q][1], ah[q][2], ah[q][3], st + ra);
                    ldmat4(al[q][0], al[q][1], al[q][2], al[q][3], st + PLANE_B + ra);
                }
#pragma unroll
                for (int q = 0; q < 2; q++)
#pragma unroll
                    for (int ni = 0; ni < 4; ni++)
                        mma_bf16(acc[mp*2+q][ni], ah[q], bh[ni]);
#pragma unroll
                for (int q = 0; q < 2; q++)
#pragma unroll
                    for (int ni = 0; ni < 4; ni++)
                        mma_bf16(acc[mp*2+q][ni], ah[q], bl[ni]);
#pragma unroll
                for (int q = 0; q < 2; q++)
#pragma unroll
                    for (int ni = 0; ni < 4; ni++)
                        mma_bf16(acc[mp*2+q][ni], al[q], bh[ni]);
            }
        }

        if (c + 2 < NC) issue_stage(c + 2, nbuf);
        else            CP_COMMIT();

        buf  = (buf  == 2) ? 0 : buf  + 1;
        nbuf = (nbuf == 2) ? 0 : nbuf + 1;
    }

    // ---- epilogue ----
    if (SKRED) {
#pragma unroll
        for (int mi = 0; mi < 4; mi++) {
            float p0 = 0.0f, p1 = 0.0f;
#pragma unroll
            for (int ni = 0; ni < 4; ni++) {
                const int n = n0 + wn * 32 + ni * 8 + 2 * t;
                const float q0 = qvec[n], q1 = qvec[n + 1];
                p0 += tanhf(acc[mi][ni][0]) * q0 + tanhf(acc[mi][ni][1]) * q1;
                p1 += tanhf(acc[mi][ni][2]) * q0 + tanhf(acc[mi][ni][3]) * q1;
            }
            p0 += __shfl_xor_sync(0xffffffffu, p0, 1);
            p0 += __shfl_xor_sync(0xffffffffu, p0, 2);
            p1 += __shfl_xor_sync(0xffffffffu, p1, 1);
            p1 += __shfl_xor_sync(0xffffffffu, p1, 2);
            if (t == 0) {
                const int m_lo = m0 + wm * 64 + mi * 16 + g;
                const int slot = blockIdx.x * 4 + wn;
                TP[(long long)m_lo * 32 + slot]       = p0;
                TP[(long long)(m_lo + 8) * 32 + slot] = p1;
            }
        }
        return;
    }

#pragma unroll
    for (int mi = 0; mi < 4; mi++) {
        const int m_lo = m0 + wm * 64 + mi * 16 + g;
        const int m_hi = m_lo + 8;
        const float* pe_lo = posenc + (long long)(m_lo & (SEQL - 1)) * N;
        const float* pe_hi = posenc + (long long)(m_hi & (SEQL - 1)) * N;
#pragma unroll
        for (int ni = 0; ni < 4; ni++) {
            const int n = n0 + wn * 32 + ni * 8 + 2 * t;
            const float b0 = bias[n], b1 = bias[n + 1];
            float2 v0, v1;
            v0.x = acc[mi][ni][0] + b0 + pe_lo[n];
            v0.y = acc[mi][ni][1] + b1 + pe_lo[n + 1];
            v1.x = acc[mi][ni][2] + b0 + pe_hi[n];
            v1.y = acc[mi][ni][3] + b1 + pe_hi[n + 1];
            *(float2*)(Cf + (long long)m_lo * N + n) = v0;
            *(float2*)(Cf + (long long)m_hi * N + n) = v1;
            if (XTOUT) {
                float2 t0, t1;
                t0.x = f2tf32f(v0.x); t0.y = f2tf32f(v0.y);
                t1.x = f2tf32f(v1.x); t1.y = f2tf32f(v1.y);
                *(float2*)(Ct + (long long)m_lo * N + n) = t0;
                *(float2*)(Ct + (long long)m_hi * N + n) = t1;
            }
        }
    }
}

// ---------------------------------------------------------------------------
// tf32 GEMM core macros (shared by generic and QKV-merged kernels)
// ---------------------------------------------------------------------------
#define TF_STRIDE       36
#define TF_TILE_FLOATS  (128 * TF_STRIDE)      // 4608
#define TF_STAGE_FLOATS (2 * TF_TILE_FLOATS)   // 9216
#define TF_STAGE_BYTES  (TF_STAGE_FLOATS * 4)  // 36864
#define DYN_SMEM_T      (3 * TF_STAGE_BYTES)   // 110592

// ---------------------------------------------------------------------------
// generic tf32 GEMM on PRE-ROUNDED tf32 operands, ldmatrix fragment loads.
// ---------------------------------------------------------------------------
__global__ __launch_bounds__(256, 2)
void tf32_gemm(const float* __restrict__ A, const float* __restrict__ B,
               float* __restrict__ C,
               int N, int K,
               long long sA, long long sB, long long sC, float alpha)
{
    extern __shared__ float smf[];

    const int tid  = threadIdx.x;
    const int wid  = tid >> 5;
    const int lane = tid & 31;
    const int wm   = wid >> 2;
    const int wn   = wid & 3;
    const int g    = lane >> 2;
    const int t    = lane & 3;

    const int bz = blockIdx.z;
    A += bz * sA; B += bz * sB; C += bz * sC;
    const int m0 = blockIdx.y * 128;
    const int n0 = blockIdx.x * 128;

    const u32 smem_base = smem_u32(smf);

    const int lj = lane >> 3;
    const int lr = lane & 7;
    const u32 aLane = (u32)(((wm * 64 + (lj & 1) * 8 + lr) * TF_STRIDE
                             + (lj >> 1) * 4) * 4);
    const u32 bLane = (u32)(((wn * 32 + (lj >> 1) * 8 + lr) * TF_STRIDE
                             + (lj & 1) * 4) * 4);

    float acc[4][4][4];
#pragma unroll
    for (int mi = 0; mi < 4; mi++)
#pragma unroll
        for (int ni = 0; ni < 4; ni++)
#pragma unroll
            for (int c = 0; c < 4; c++) acc[mi][ni][c] = 0.0f;

    const int NC = K >> 5;

    auto issue_stage = [&](int c, int buf) {
        const int k0 = c * 32;
        const u32 st = smem_base + buf * TF_STAGE_BYTES;
#pragma unroll
        for (int i = 0; i < 4; i++) {
            const int e   = tid + i * 256;
            const int row = e >> 3;
            const int q   = e & 7;
            cp_async16(st + (row * TF_STRIDE + q * 4) * 4,
                       A + (long long)(m0 + row) * K + k0 + q * 4);
        }
#pragma unroll
        for (int i = 0; i < 4; i++) {
            const int e   = tid + i * 256;
            const int row = e >> 3;
            const int q   = e & 7;
            cp_async16(st + TF_TILE_FLOATS * 4 + (row * TF_STRIDE + q * 4) * 4,
                       B + (long long)(n0 + row) * K + k0 + q * 4);
        }
        CP_COMMIT();
    };

    issue_stage(0, 0);
    issue_stage(1, 1);

    int buf = 0;
    int nbuf = 2;
    for (int c = 0; c < NC; ++c) {
        CP_WAIT1();
        __syncthreads();

        const u32 stA = smem_base + buf * TF_STAGE_BYTES + aLane;
        const u32 stB = smem_base + buf * TF_STAGE_BYTES + TF_TILE_FLOATS * 4 + bLane;

#pragma unroll
        for (int ks = 0; ks < 4; ks++) {
            const u32 kkB = (u32)(ks * 8 * 4);

            u32 bf[4][2];
            ldmat4(bf[0][0], bf[0][1], bf[1][0], bf[1][1], stB + kkB);
            ldmat4(bf[2][0], bf[2][1], bf[3][0], bf[3][1],
                   stB + 16 * TF_STRIDE * 4 + kkB);

#pragma unroll
            for (int mp = 0; mp < 2; mp++) {
                u32 af[2][4];
#pragma unroll
                for (int q = 0; q < 2; q++) {
                    const u32 ra = stA + (u32)((mp * 2 + q) * 16 * TF_STRIDE * 4) + kkB;
                    ldmat4(af[q][0], af[q][1], af[q][2], af[q][3], ra);
                }
#pragma unroll
                for (int q = 0; q < 2; q++)
#pragma unroll
                    for (int ni = 0; ni < 4; ni++)
                        mma_tf32(acc[mp*2+q][ni], af[q], bf[ni]);
            }
        }

        if (c + 2 < NC) issue_stage(c + 2, nbuf);
        else            CP_COMMIT();

        buf  = (buf  == 2) ? 0 : buf  + 1;
        nbuf = (nbuf == 2) ? 0 : nbuf + 1;
    }

#pragma unroll
    for (int mi = 0; mi < 4; mi++) {
        const int m_lo = m0 + wm * 64 + mi * 16 + g;
        const int m_hi = m_lo + 8;
#pragma unroll
        for (int ni = 0; ni < 4; ni++) {
            const int n = n0 + wn * 32 + ni * 8 + 2 * t;
            float2 v0, v1;
            v0.x = acc[mi][ni][0] * alpha;
            v0.y = acc[mi][ni][1] * alpha;
            v1.x = acc[mi][ni][2] * alpha;
            v1.y = acc[mi][ni][3] * alpha;
            *(float2*)(C + (long long)m_lo * N + n) = v0;
            *(float2*)(C + (long long)m_hi * N + n) = v1;
        }
    }
}

// ---------------------------------------------------------------------------
// merged QKV tf32 GEMM: grid.z in {0,1,2} selects weight/bias/output.
//   z=0: Q (tf32-rounded out)   z=1: K (tf32-rounded out)
//   z=2: V (tf32-rounded, transposed per batch out[b][n][s])
// One launch (3072 CTAs) amortizes wave tails of three 1024-CTA launches.
// ---------------------------------------------------------------------------
__global__ __launch_bounds__(256, 2)
void tf32_gemm_qkv(const float* __restrict__ A,
                   const float* __restrict__ WQ, const float* __restrict__ WK,
                   const float* __restrict__ WV,
                   float* __restrict__ Q, float* __restrict__ K,
                   float* __restrict__ VT,
                   const float* __restrict__ bq, const float* __restrict__ bk,
                   const float* __restrict__ bv)
{
    extern __shared__ float smf[];

    const int tid  = threadIdx.x;
    const int wid  = tid >> 5;
    const int lane = tid & 31;
    const int wm   = wid >> 2;
    const int wn   = wid & 3;
    const int g    = lane >> 2;
    const int t    = lane & 3;

    const int z = blockIdx.z;
    const float* B    = (z == 0) ? WQ : (z == 1) ? WK : WV;
    const float* bias = (z == 0) ? bq : (z == 1) ? bk : bv;
    float* C          = (z == 0) ? Q  : (z == 1) ? K  : VT;

    const int m0 = blockIdx.y * 128;
    const int n0 = blockIdx.x * 128;

    const u32 smem_base = smem_u32(smf);

    const int lj = lane >> 3;
    const int lr = lane & 7;
    const u32 aLane = (u32)(((wm * 64 + (lj & 1) * 8 + lr) * TF_STRIDE
                             + (lj >> 1) * 4) * 4);
    const u32 bLane = (u32)(((wn * 32 + (lj >> 1) * 8 + lr) * TF_STRIDE
                             + (lj & 1) * 4) * 4);

    float acc[4][4][4];
#pragma unroll
    for (int mi = 0; mi < 4; mi++)
#pragma unroll
        for (int ni = 0; ni < 4; ni++)
#pragma unroll
            for (int c = 0; c < 4; c++) acc[mi][ni][c] = 0.0f;

    const int NC = DMODEL >> 5;   // 32

    auto issue_stage = [&](int c, int buf) {
        const int k0 = c * 32;
        const u32 st = smem_base + buf * TF_STAGE_BYTES;
#pragma unroll
        for (int i = 0; i < 4; i++) {
            const int e   = tid + i * 256;
            const int row = e >> 3;
            const int q   = e & 7;
            cp_async16(st + (row * TF_STRIDE + q * 4) * 4,
                       A + (long long)(m0 + row) * DMODEL + k0 + q * 4);
        }
#pragma unroll
        for (int i = 0; i < 4; i++) {
            const int e   = tid + i * 256;
            const int row = e >> 3;
            const int q   = e & 7;
            cp_async16(st + TF_TILE_FLOATS * 4 + (row * TF_STRIDE + q * 4) * 4,
                       B + (long long)(n0 + row) * DMODEL + k0 + q * 4);
        }
        CP_COMMIT();
    };

    issue_stage(0, 0);
    issue_stage(1, 1);

    int buf = 0;
    int nbuf = 2;
    for (int c = 0; c < NC; ++c) {
        CP_WAIT1();
        __syncthreads();

        const u32 stA = smem_base + buf * TF_STAGE_BYTES + aLane;
        const u32 stB = smem_base + buf * TF_STAGE_BYTES + TF_TILE_FLOATS * 4 + bLane;

#pragma unroll
        for (int ks = 0; ks < 4; ks++) {
            const u32 kkB = (u32)(ks * 8 * 4);

            u32 bf[4][2];
            ldmat4(bf[0][0], bf[0][1], bf[1][0], bf[1][1], stB + kkB);
            ldmat4(bf[2][0], bf[2][1], bf[3][0], bf[3][1],
                   stB + 16 * TF_STRIDE * 4 + kkB);

#pragma unroll
            for (int mp = 0; mp < 2; mp++) {
                u32 af[2][4];
#pragma unroll
                for (int q = 0; q < 2; q++) {
                    const u32 ra = stA + (u32)((mp * 2 + q) * 16 * TF_STRIDE * 4) + kkB;
                    ldmat4(af[q][0], af[q][1], af[q][2], af[q][3], ra);
                }
#pragma unroll
                for (int q = 0; q < 2; q++)
#pragma unroll
                    for (int ni = 0; ni < 4; ni++)
                        mma_tf32(acc[mp*2+q][ni], af[q], bf[ni]);
            }
        }

        if (c + 2 < NC) issue_stage(c + 2, nbuf);
        else            CP_COMMIT();

        buf  = (buf  == 2) ? 0 : buf  + 1;
        nbuf = (nbuf == 2) ? 0 : nbuf + 1;
    }

#pragma unroll
    for (int mi = 0; mi < 4; mi++) {
        const int m_lo = m0 + wm * 64 + mi * 16 + g;
        const int m_hi = m_lo + 8;
#pragma unroll
        for (int ni = 0; ni < 4; ni++) {
            const int n = n0 + wn * 32 + ni * 8 + 2 * t;
            const float b0 = bias[n], b1 = bias[n + 1];
            float2 v0, v1;
            v0.x = f2tf32f(acc[mi][ni][0] + b0);
            v0.y = f2tf32f(acc[mi][ni][1] + b1);
            v1.x = f2tf32f(acc[mi][ni][2] + b0);
            v1.y = f2tf32f(acc[mi][ni][3] + b1);
            if (z == 2) {
                // V^T: out[b][n][s], m = b*SEQL + s; DMODEL*SEQL = 1<<21
                const long long base_lo = ((long long)(m_lo >> 11) << 21) + (m_lo & 2047);
                const long long base_hi = ((long long)(m_hi >> 11) << 21) + (m_hi & 2047);
                C[base_lo + (long long)n * SEQL]       = v0.x;
                C[base_lo + (long long)(n + 1) * SEQL] = v0.y;
                C[base_hi + (long long)n * SEQL]       = v1.x;
                C[base_hi + (long long)(n + 1) * SEQL] = v1.y;
            } else {
                *(float2*)(C + (long long)m_lo * DMODEL + n) = v0;
                *(float2*)(C + (long long)m_hi * DMODEL + n) = v1;
            }
        }
    }
}

// ---------------------------------------------------------------------------
// fp32 -> split bf16 hi/lo planes (4 elems per thread)
// ---------------------------------------------------------------------------
__global__ void split_fp32(const float* __restrict__ src,
                           u16* __restrict__ hi, u16* __restrict__ lo, int n4)
{
    const int i = blockIdx.x * blockDim.x + threadIdx.x;
    if (i >= n4) return;
    const float4 v = ((const float4*)src)[i];
    u32 h01, l01, h23, l23;
    split_pack(v.x, v.y, h01, l01);
    split_pack(v.z, v.w, h23, l23);
    ((uint2*)hi)[i] = make_uint2(h01, h23);
    ((uint2*)lo)[i] = make_uint2(l01, l23);
}

// ---------------------------------------------------------------------------
// three fp32 weight mats -> tf32-rounded fp32 (grid.y selects src/dst)
// ---------------------------------------------------------------------------
__global__ void round3_tf32(const float* __restrict__ s0, const float* __restrict__ s1,
                            const float* __restrict__ s2, float* __restrict__ d0,
                            float* __restrict__ d1, float* __restrict__ d2, int n4)
{
    const int i = blockIdx.x * blockDim.x + threadIdx.x;
    if (i >= n4) return;
    const float* src = (blockIdx.y == 0) ? s0 : (blockIdx.y == 1) ? s1 : s2;
    float* dst       = (blockIdx.y == 0) ? d0 : (blockIdx.y == 1) ? d1 : d2;
    float4 v = ((const float4*)src)[i];
    v.x = f2tf32f(v.x); v.y = f2tf32f(v.y);
    v.z = f2tf32f(v.z); v.w = f2tf32f(v.w);
    ((float4*)dst)[i] = v;
}

// ---------------------------------------------------------------------------
// Row softmax, in place, row length 2048.  RND: tf32-round outputs.
// ---------------------------------------------------------------------------
template <bool RND>
__global__ void softmax_rows(float* __restrict__ S)
{
    float* row = S + (long long)blockIdx.x * 2048;
    const int tid = threadIdx.x;
    __shared__ float red[256];

    float v[8];
    *(float4*)&v[0] = *(const float4*)(row + tid * 8);
    *(float4*)&v[4] = *(const float4*)(row + tid * 8 + 4);

    float mx = -1e30f;
#pragma unroll
    for (int i = 0; i < 8; i++) mx = fmaxf(mx, v[i]);
    red[tid] = mx; __syncthreads();
    for (int s = 128; s > 0; s >>= 1) {
        if (tid < s) red[tid] = fmaxf(red[tid], red[tid + s]);
        __syncthreads();
    }
    mx = red[0]; __syncthreads();

    float sum = 0.0f;
#pragma unroll
    for (int i = 0; i < 8; i++) { v[i] = __expf(v[i] - mx); sum += v[i]; }
    red[tid] = sum; __syncthreads();
    for (int s = 128; s > 0; s >>= 1) {
        if (tid < s) red[tid] += red[tid + s];
        __syncthreads();
    }
    const float inv = 1.0f / red[0];
#pragma unroll
    for (int i = 0; i < 8; i++) {
        v[i] *= inv;
        if (RND) v[i] = f2tf32f(v[i]);
    }
    *(float4*)(row + tid * 8)     = *(float4*)&v[0];
    *(float4*)(row + tid * 8 + 4) = *(float4*)&v[4];
}

// ---------------------------------------------------------------------------
// h = x + z ; H = LN(h)*g + b  -> fp32 H + split planes (for bf16x3 SK GEMM)
// ---------------------------------------------------------------------------
__global__ void add_ln_split(const float* __restrict__ X, const float* __restrict__ Z,
                             const float* __restrict__ g, const float* __restrict__ b,
                             float* __restrict__ H, u16* __restrict__ hi, u16* __restrict__ lo)
{
    const long long r = blockIdx.x;
    const int tid = threadIdx.x;
    const int c0  = tid * 4;
    const float* xr = X + r * DMODEL;
    const float* zr = Z + r * DMODEL;
    __shared__ float red[256];

    float4 x4 = *(const float4*)(xr + c0);
    float4 z4 = *(const float4*)(zr + c0);
    float h[4] = { x4.x + z4.x, x4.y + z4.y, x4.z + z4.z, x4.w + z4.w };

    float sum = h[0] + h[1] + h[2] + h[3];
    red[tid] = sum; __syncthreads();
    for (int s = 128; s > 0; s >>= 1) {
        if (tid < s) red[tid] += red[tid + s];
        __syncthreads();
    }
    const float mean = red[0] * (1.0f / DMODEL);
    __syncthreads();

    float vs = 0.0f;
#pragma unroll
    for (int i = 0; i < 4; i++) { const float d = h[i] - mean; vs += d * d; }
    red[tid] = vs; __syncthreads();
    for (int s = 128; s > 0; s >>= 1) {
        if (tid < s) red[tid] += red[tid + s];
        __syncthreads();
    }
    const float inv = rsqrtf(red[0] * (1.0f / DMODEL) + LN_EPS);

    float4 o;
    o.x = (h[0] - mean) * inv * g[c0 + 0] + b[c0 + 0];
    o.y = (h[1] - mean) * inv * g[c0 + 1] + b[c0 + 1];
    o.z = (h[2] - mean) * inv * g[c0 + 2] + b[c0 + 2];
    o.w = (h[3] - mean) * inv * g[c0 + 3] + b[c0 + 3];
    *(float4*)(H + r * DMODEL + c0) = o;

    u32 h01, l01, h23, l23;
    split_pack(o.x, o.y, h01, l01);
    split_pack(o.z, o.w, h23, l23);
    const long long pi = (r * DMODEL + c0) >> 1;
    ((u32*)hi)[pi]     = h01;
    ((u32*)hi)[pi + 1] = h23;
    ((u32*)lo)[pi]     = l01;
    ((u32*)lo)[pi + 1] = l23;
}

// ---------------------------------------------------------------------------
// T[r] = sum of 32 soft-key partials (deterministic fixed-order reduce)
// ---------------------------------------------------------------------------
__global__ void skt_reduce(const float* __restrict__ TP, float* __restrict__ T)
{
    const int r = blockIdx.x * 256 + threadIdx.x;
    const float* p = TP + (long long)r * 32;
    float s = 0.0f;
#pragma unroll
    for (int j = 0; j < 32; j++) s += p[j];
    T[r] = s;
}

// ---------------------------------------------------------------------------
// final_out stage 1: partial over 256-row s-chunk
// ---------------------------------------------------------------------------
__global__ void final_partial(const float* __restrict__ H, const float* __restrict__ w,
                              float* __restrict__ OP)
{
    const int b  = blockIdx.y;
    const int zc = blockIdx.z;
    const int o  = blockIdx.x * 256 + threadIdx.x;
    const float* Hp = H + (long long)b * SEQL * DMODEL
                        + (long long)(zc * 256) * DMODEL + o;
    const float* wb = w + (long long)b * SEQL + zc * 256;

    float a0 = 0.0f, a1 = 0.0f, a2 = 0.0f, a3 = 0.0f;
    for (int s = 0; s < 256; s += 4) {
        a0 += wb[s + 0] * Hp[(long long)(s + 0) * DMODEL];
        a1 += wb[s + 1] * Hp[(long long)(s + 1) * DMODEL];
        a2 += wb[s + 2] * Hp[(long long)(s + 2) * DMODEL];
        a3 += wb[s + 3] * Hp[(long long)(s + 3) * DMODEL];
    }
    OP[(long long)(b * 8 + zc) * DMODEL + o] = (a0 + a1) + (a2 + a3);
}

// final_out stage 2
__global__ void final_reduce(const float* __restrict__ OP, float* __restrict__ out)
{
    const int b = blockIdx.y;
    const int o = blockIdx.x * 256 + threadIdx.x;
    float s = 0.0f;
#pragma unroll
    for (int z = 0; z < 8; z++)
        s += OP[(long long)(b * 8 + z) * DMODEL + o];
    out[b * DMODEL + o] = s;
}

// ---------------------------------------------------------------------------
// Launch
// ---------------------------------------------------------------------------
extern "C" void kernel_launch(void* const* d_in, const int* in_sizes, int n_in,
                              void* d_out, int out_size)
{
    const float* inputs  = (const float*)d_in[0];
    const float* embed_w = (const float*)d_in[1];
    const float* embed_b = (const float*)d_in[2];
    const float* wq_w    = (const float*)d_in[3];
    const float* wq_b    = (const float*)d_in[4];
    const float* wk_w    = (const float*)d_in[5];
    const float* wk_b    = (const float*)d_in[6];
    const float* wv_w    = (const float*)d_in[7];
    const float* wv_b    = (const float*)d_in[8];
    const float* ln_g    = (const float*)d_in[9];
    const float* ln_b    = (const float*)d_in[10];
    const float* skw     = (const float*)d_in[11];
    const float* sq      = (const float*)d_in[12];
    const float* pos     = (const float*)d_in[13];
    float* out = (float*)d_out;

    cudaFuncSetAttribute((const void*)bf16x3_gemm<true,  false>,
                         cudaFuncAttributeMaxDynamicSharedMemorySize, DYN_SMEM_G);
    cudaFuncSetAttribute((const void*)bf16x3_gemm<false, true>,
                         cudaFuncAttributeMaxDynamicSharedMemorySize, DYN_SMEM_G);
    cudaFuncSetAttribute((const void*)tf32_gemm,
                         cudaFuncAttributeMaxDynamicSharedMemorySize, DYN_SMEM_T);
    cudaFuncSetAttribute((const void*)tf32_gemm_qkv,
                         cudaFuncAttributeMaxDynamicSharedMemorySize, DYN_SMEM_T);

    float* base = 0;
    cudaGetSymbolAddress((void**)&base, g_scratch);

    u16* INh  = (u16*)(base + O_INS);   u16* INl  = INh  + C_IN;
    u16* EWh  = (u16*)(base + O_EWS);   u16* EWl  = EWh  + C_EW;
    u16* SKWh = (u16*)(base + O_SKWS);  u16* SKWl = SKWh + C_W;
    float* WQT = base + O_WQT;
    float* WKT = base + O_WKT;
    float* WVT = base + O_WVT;
    float* X  = base + O_X;
    float* XT = base + O_XT;
    float* Q  = base + O_Q;
    float* K  = base + O_K;
    float* VT = base + O_VT;
    float* SC = base + O_SC;
    float* Z  = base + O_Z;
    float* H  = base + O_H;
    u16* Hh   = (u16*)(base + O_HS);    u16* Hl   = Hh + C_MAT;
    float* TP = base + O_TP;
    float* OP = base + O_OP;
    float* T  = base + O_T;

    // 0) operand prep
    split_fp32<<<(int)(C_IN / 4 / 256), 256>>>(inputs,  INh,  INl,  (int)(C_IN / 4));
    split_fp32<<<(int)(C_EW / 4 / 256), 256>>>(embed_w, EWh,  EWl,  (int)(C_EW / 4));
    split_fp32<<<(int)(C_W  / 4 / 256), 256>>>(skw,     SKWh, SKWl, (int)(C_W / 4));
    round3_tf32<<<dim3((int)(C_W / 4 / 256), 3), 256>>>(
        wq_w, wk_w, wv_w, WQT, WKT, WVT, (int)(C_W / 4));

    // 1) embed (bf16x3): X = inputs @ embed_w^T + embed_b + pos_enc; also Xt
    bf16x3_gemm<true, false><<<dim3(DMODEL / 128, NROW / 128, 1), 256, DYN_SMEM_G>>>(
        INh, INl, EWh, EWl, X, XT, 0, 0, DMODEL, D_IN, embed_b, pos);

    // 2) merged QKV (tf32): one launch, grid.z selects Q / K / V(transposed)
    tf32_gemm_qkv<<<dim3(DMODEL / 128, NROW / 128, 3), 256, DYN_SMEM_T>>>(
        XT, WQT, WKT, WVT, Q, K, VT, wq_b, wk_b, wv_b);

    // 3) scores = Q @ K^T / 32 (batched, tf32, pre-rounded inputs)
    tf32_gemm<<<dim3(SEQL / 128, SEQL / 128, BATCH), 256, DYN_SMEM_T>>>(
        Q, K, SC, SEQL, DMODEL,
        (long long)SEQL * DMODEL, (long long)SEQL * DMODEL, (long long)SEQL * SEQL,
        1.0f / 32.0f);

    // 4) softmax in place, tf32-rounded output (feeds Z GEMM)
    softmax_rows<true><<<NROW, 256>>>(SC);

    // 5) Z = softmax(SC) @ V  (tf32, pre-rounded inputs)
    tf32_gemm<<<dim3(DMODEL / 128, SEQL / 128, BATCH), 256, DYN_SMEM_T>>>(
        SC, VT, Z, DMODEL, SEQL,
        (long long)SEQL * SEQL, (long long)DMODEL * SEQL, (long long)SEQL * DMODEL,
        1.0f);

    // 6) H = LN(X + Z)*g + b  (fp32 + split planes for SK)
    add_ln_split<<<NROW, 256>>>(X, Z, ln_g, ln_b, H, Hh, Hl);

    // 7) fused SK GEMM (bf16x3 — unscaled logits need the precision) -> TP
    bf16x3_gemm<false, true><<<dim3(DMODEL / 128, NROW / 128, 1), 256, DYN_SMEM_G>>>(
        Hh, Hl, SKWh, SKWl, 0, 0, TP, sq, DMODEL, DMODEL, 0, 0);

    // 8) T[r] = sum partials; softmax over s per batch (no rounding)
    skt_reduce<<<NROW / 256, 256>>>(TP, T);
    softmax_rows<false><<<BATCH, 256>>>(T);

    // 9) out[b,o] = sum_s w[b,s] * H[b,s,o]  (two-stage, deterministic)
    final_partial<<<dim3(DMODEL / 256, BATCH, 8), 256>>>(H, T, OP);
    final_reduce<<<dim3(DMODEL / 256, BATCH), 256>>>(OP, out);
}

// round 16
// speedup vs baseline: 1.7573x; 1.0746x over previous
#include <cuda_runtime.h>
#include <cstdint>
#include <math.h>

// ---------------------------------------------------------------------------
// Problem constants
// ---------------------------------------------------------------------------
#define BATCH   8
#define SEQL    2048
#define D_IN    512
#define DMODEL  1024
#define NROW    (BATCH * SEQL)          // 16384
#define LN_EPS  1e-5f

typedef unsigned short u16;
typedef uint32_t u32;

// element counts
static const long long C_IN  = (long long)NROW * D_IN;       // 8388608
static const long long C_EW  = (long long)DMODEL * D_IN;     // 524288
static const long long C_W   = (long long)DMODEL * DMODEL;   // 1048576
static const long long C_MAT = (long long)NROW * DMODEL;     // 16777216
static const long long C_SC  = (long long)BATCH * SEQL * SEQL; // 33554432

// scratch offsets (in floats)
#define O_INS   (0LL)
#define O_EWS   (O_INS  + C_IN)
#define O_SKWS  (O_EWS  + C_EW)
#define O_WQT   (O_SKWS + C_W)
#define O_WKT   (O_WQT  + C_W)
#define O_WVT   (O_WKT  + C_W)
#define O_X     (O_WVT  + C_W)
#define O_XT    (O_X    + C_MAT)        // tf32-rounded X
#define O_Q     (O_XT   + C_MAT)        // tf32-rounded Q
#define O_K     (O_Q    + C_MAT)        // tf32-rounded K
#define O_VTB   (O_K    + C_MAT)        // bf16 V^T (per batch [n][s]), C_MAT u16
#define O_SC    (O_VTB  + C_MAT / 2)    // fp32 score logits
#define O_SCB   (O_SC   + C_SC)         // bf16 softmax probs, C_SC u16
#define O_Z     (O_SCB  + C_SC / 2)
#define O_H     (O_Z    + C_MAT)
#define O_HS    (O_H    + C_MAT)        // split H planes
#define O_TP    (O_HS   + C_MAT)                 // soft-key partials [16384][32]
#define O_OP    (O_TP   + 16384LL * 32)          // final_out partials [64][1024]
#define O_T     (O_OP   + 65536)
#define O_TOTAL (O_T    + 16384)

__device__ float g_scratch[O_TOTAL];

// ---------------------------------------------------------------------------
// PTX helpers (baseline sm_80+ features only — harness targets plain sm_103)
// ---------------------------------------------------------------------------
__device__ __forceinline__ u32 smem_u32(const void* p) {
    u32 a;
    asm("{ .reg .u64 t; cvta.to.shared.u64 t, %1; cvt.u32.u64 %0, t; }"
        : "=r"(a) : "l"(p));
    return a;
}

__device__ __forceinline__ void cp_async16(u32 dst, const void* src) {
    asm volatile("cp.async.cg.shared.global [%0], [%1], 16;" :: "r"(dst), "l"(src));
}
#define CP_COMMIT() asm volatile("cp.async.commit_group;" ::: "memory")
#define CP_WAIT1()  asm volatile("cp.async.wait_group 1;"  ::: "memory")

// split x0,x1 (fp32) into packed bf16x2 hi and lo parts: x = hi + lo
__device__ __forceinline__ void split_pack(float x0, float x1, u32& hi, u32& lo) {
    asm("cvt.rn.bf16x2.f32 %0, %1, %2;" : "=r"(hi) : "f"(x1), "f"(x0));
    const float h0 = __uint_as_float(hi << 16);
    const float h1 = __uint_as_float(hi & 0xFFFF0000u);
    const float l0 = x0 - h0;
    const float l1 = x1 - h1;
    asm("cvt.rn.bf16x2.f32 %0, %1, %2;" : "=r"(lo) : "f"(l1), "f"(l0));
}

// pack two fp32 into bf16x2 (round-to-nearest); low half = x0
__device__ __forceinline__ u32 pack_bf16x2(float x0, float x1) {
    u32 r;
    asm("cvt.rn.bf16x2.f32 %0, %1, %2;" : "=r"(r) : "f"(x1), "f"(x0));
    return r;
}

__device__ __forceinline__ float f2tf32f(float f) {
    u32 r;
    asm("cvt.rna.tf32.f32 %0, %1;" : "=r"(r) : "f"(f));
    return __uint_as_float(r);
}

// D += A*B  (m16n8k16 bf16, fp32 accum)
__device__ __forceinline__ void mma_bf16(float* d, const u32* a, const u32* b) {
    asm volatile(
        "mma.sync.aligned.m16n8k16.row.col.f32.bf16.bf16.f32 "
        "{%0,%1,%2,%3}, {%4,%5,%6,%7}, {%8,%9}, {%0,%1,%2,%3};"
        : "+f"(d[0]), "+f"(d[1]), "+f"(d[2]), "+f"(d[3])
        : "r"(a[0]), "r"(a[1]), "r"(a[2]), "r"(a[3]), "r"(b[0]), "r"(b[1]));
}

// D += A*B  (m16n8k8 tf32, fp32 accum) — operands pre-rounded to tf32
__device__ __forceinline__ void mma_tf32(float* d, const u32* a, const u32* b) {
    asm volatile(
        "mma.sync.aligned.m16n8k8.row.col.f32.tf32.tf32.f32 "
        "{%0,%1,%2,%3}, {%4,%5,%6,%7}, {%8,%9}, {%0,%1,%2,%3};"
        : "+f"(d[0]), "+f"(d[1]), "+f"(d[2]), "+f"(d[3])
        : "r"(a[0]), "r"(a[1]), "r"(a[2]), "r"(a[3]), "r"(b[0]), "r"(b[1]));
}

__device__ __forceinline__ void ldmat4(u32& r0, u32& r1, u32& r2, u32& r3, u32 addr) {
    asm volatile("ldmatrix.sync.aligned.m8n8.x4.shared.b16 {%0,%1,%2,%3}, [%4];"
                 : "=r"(r0), "=r"(r1), "=r"(r2), "=r"(r3) : "r"(addr));
}

// swizzled byte offset of (row, 16B-chunk ch) in a 128x32 bf16 plane (64B rows)
__device__ __forceinline__ u32 sw_off(u32 row, u32 ch) {
    return row * 64u + ((ch ^ ((row >> 1) & 3u)) << 4);
}

// ---------------------------------------------------------------------------
// bf16x3 split GEMM (embed + SK): C = A@B^T (+bias +posenc)
// R7/R10 proven cadence: 3-buffer, one barrier/chunk, load-after-compute.
//   XTOUT: also write tf32-rounded copy of C (embed; feeds tf32 QKV GEMMs)
//   SKRED: fused soft-key epilogue (partials of sum tanh(C)*q), no C written
// ---------------------------------------------------------------------------
#define PLANE_B  (128 * 64)             // 8192
#define STAGE_B  (4 * PLANE_B)          // 32768
#define DYN_SMEM_G (3 * STAGE_B)        // 98304

template <bool XTOUT, bool SKRED>
__global__ __launch_bounds__(256, 2)
void bf16x3_gemm(const u16* __restrict__ Ahi, const u16* __restrict__ Alo,
                 const u16* __restrict__ Bhi, const u16* __restrict__ Blo,
                 float* __restrict__ Cf, float* __restrict__ Ct,
                 float* __restrict__ TP, const float* __restrict__ qvec,
                 int N, int K,
                 const float* __restrict__ bias,
                 const float* __restrict__ posenc)
{
    extern __shared__ char smem[];

    const int tid  = threadIdx.x;
    const int wid  = tid >> 5;
    const int lane = tid & 31;
    const int wm   = wid >> 2;
    const int wn   = wid & 3;
    const int g    = lane >> 2;
    const int t    = lane & 3;
    const int lrow = lane & 15;
    const int lch  = lane >> 4;

    const int m0 = blockIdx.y * 128;
    const int n0 = blockIdx.x * 128;

    const u32 smem_base = smem_u32(smem);

    float acc[4][4][4];
#pragma unroll
    for (int mi = 0; mi < 4; mi++)
#pragma unroll
        for (int ni = 0; ni < 4; ni++)
#pragma unroll
            for (int c = 0; c < 4; c++) acc[mi][ni][c] = 0.0f;

    const int NC = K >> 5;

    const u32 ld_row = (u32)(tid >> 2);
    const u32 ld_ch  = (u32)(tid & 3);

    auto issue_stage = [&](int c, int buf) {
        const int k0 = c * 32;
        const u32 st = smem_base + buf * STAGE_B;
        const u16* srcs[4] = { Ahi, Alo, Bhi, Blo };
#pragma unroll
        for (int p = 0; p < 4; p++) {
            const u16* src = srcs[p];
            const int rbase = (p < 2) ? m0 : n0;
#pragma unroll
            for (int i = 0; i < 2; i++) {
                const u32 row = ld_row + i * 64;
                cp_async16(st + p * PLANE_B + sw_off(row, ld_ch),
                           src + (long long)(rbase + row) * K + k0 + ld_ch * 8);
            }
        }
        CP_COMMIT();
    };

    issue_stage(0, 0);
    issue_stage(1, 1);

    int buf = 0;
    int nbuf = 2;
    for (int c = 0; c < NC; ++c) {
        CP_WAIT1();
        __syncthreads();

        const u32 st = smem_base + buf * STAGE_B;

#pragma unroll
        for (int half = 0; half < 2; half++) {
            const u32 ch = (u32)(half * 2 + lch);

            u32 bh[4][2], bl[4][2];
#pragma unroll
            for (int nj = 0; nj < 2; nj++) {
                const u32 rb = sw_off((u32)(wn * 32 + nj * 16 + lrow), ch);
                u32 r0, r1, r2, r3;
                ldmat4(r0, r1, r2, r3, st + 2 * PLANE_B + rb);
                bh[2*nj][0] = r0; bh[2*nj+1][0] = r1;
                bh[2*nj][1] = r2; bh[2*nj+1][1] = r3;
                ldmat4(r0, r1, r2, r3, st + 3 * PLANE_B + rb);
                bl[2*nj][0] = r0; bl[2*nj+1][0] = r1;
                bl[2*nj][1] = r2; bl[2*nj+1][1] = r3;
            }

#pragma unroll
            for (int mp = 0; mp < 2; mp++) {
                u32 ah[2][4], al[2][4];
#pragma unroll
                for (int q = 0; q < 2; q++) {
                    const int mi = mp * 2 + q;
                    const u32 ra = sw_off((u32)(wm * 64 + mi * 16 + lrow), ch);
                    ldmat4(ah[q][0], ah[q][1], ah[q][2], ah[q][3], st + ra);
                    ldmat4(al[q][0], al[q][1], al[q][2], al[q][3], st + PLANE_B + ra);
                }
#pragma unroll
                for (int q = 0; q < 2; q++)
#pragma unroll
                    for (int ni = 0; ni < 4; ni++)
                        mma_bf16(acc[mp*2+q][ni], ah[q], bh[ni]);
#pragma unroll
                for (int q = 0; q < 2; q++)
#pragma unroll
                    for (int ni = 0; ni < 4; ni++)
                        mma_bf16(acc[mp*2+q][ni], ah[q], bl[ni]);
#pragma unroll
                for (int q = 0; q < 2; q++)
#pragma unroll
                    for (int ni = 0; ni < 4; ni++)
                        mma_bf16(acc[mp*2+q][ni], al[q], bh[ni]);
            }
        }

        if (c + 2 < NC) issue_stage(c + 2, nbuf);
        else            CP_COMMIT();

        buf  = (buf  == 2) ? 0 : buf  + 1;
        nbuf = (nbuf == 2) ? 0 : nbuf + 1;
    }

    // ---- epilogue ----
    if (SKRED) {
#pragma unroll
        for (int mi = 0; mi < 4; mi++) {
            float p0 = 0.0f, p1 = 0.0f;
#pragma unroll
            for (int ni = 0; ni < 4; ni++) {
                const int n = n0 + wn * 32 + ni * 8 + 2 * t;
                const float q0 = qvec[n], q1 = qvec[n + 1];
                p0 += tanhf(acc[mi][ni][0]) * q0 + tanhf(acc[mi][ni][1]) * q1;
                p1 += tanhf(acc[mi][ni][2]) * q0 + tanhf(acc[mi][ni][3]) * q1;
            }
            p0 += __shfl_xor_sync(0xffffffffu, p0, 1);
            p0 += __shfl_xor_sync(0xffffffffu, p0, 2);
            p1 += __shfl_xor_sync(0xffffffffu, p1, 1);
            p1 += __shfl_xor_sync(0xffffffffu, p1, 2);
            if (t == 0) {
                const int m_lo = m0 + wm * 64 + mi * 16 + g;
                const int slot = blockIdx.x * 4 + wn;
                TP[(long long)m_lo * 32 + slot]       = p0;
                TP[(long long)(m_lo + 8) * 32 + slot] = p1;
            }
        }
        return;
    }

#pragma unroll
    for (int mi = 0; mi < 4; mi++) {
        const int m_lo = m0 + wm * 64 + mi * 16 + g;
        const int m_hi = m_lo + 8;
        const float* pe_lo = posenc + (long long)(m_lo & (SEQL - 1)) * N;
        const float* pe_hi = posenc + (long long)(m_hi & (SEQL - 1)) * N;
#pragma unroll
        for (int ni = 0; ni < 4; ni++) {
            const int n = n0 + wn * 32 + ni * 8 + 2 * t;
            const float b0 = bias[n], b1 = bias[n + 1];
            float2 v0, v1;
            v0.x = acc[mi][ni][0] + b0 + pe_lo[n];
            v0.y = acc[mi][ni][1] + b1 + pe_lo[n + 1];
            v1.x = acc[mi][ni][2] + b0 + pe_hi[n];
            v1.y = acc[mi][ni][3] + b1 + pe_hi[n + 1];
            *(float2*)(Cf + (long long)m_lo * N + n) = v0;
            *(float2*)(Cf + (long long)m_hi * N + n) = v1;
            if (XTOUT) {
                float2 t0, t1;
                t0.x = f2tf32f(v0.x); t0.y = f2tf32f(v0.y);
                t1.x = f2tf32f(v1.x); t1.y = f2tf32f(v1.y);
                *(float2*)(Ct + (long long)m_lo * N + n) = t0;
                *(float2*)(Ct + (long long)m_hi * N + n) = t1;
            }
        }
    }
}

// ---------------------------------------------------------------------------
// single-term bf16 GEMM (Z = P @ V): A [M][K] bf16, B [N][K] bf16, C fp32.
// Same proven cadence; 2 planes per stage (16KB), 32 MMAs per K=32 chunk.
// ---------------------------------------------------------------------------
#define STAGE_S    (2 * PLANE_B)        // 16384
#define DYN_SMEM_S (3 * STAGE_S)        // 49152

__global__ __launch_bounds__(256, 2)
void bf16s_gemm(const u16* __restrict__ A, const u16* __restrict__ B,
                float* __restrict__ C, int N, int K,
                long long sA, long long sB, long long sC)
{
    extern __shared__ char smem[];

    const int tid  = threadIdx.x;
    const int wid  = tid >> 5;
    const int lane = tid & 31;
    const int wm   = wid >> 2;
    const int wn   = wid & 3;
    const int g    = lane >> 2;
    const int t    = lane & 3;
    const int lrow = lane & 15;
    const int lch  = lane >> 4;

    const int bz = blockIdx.z;
    A += bz * sA; B += bz * sB; C += bz * sC;
    const int m0 = blockIdx.y * 128;
    const int n0 = blockIdx.x * 128;

    const u32 smem_base = smem_u32(smem);

    float acc[4][4][4];
#pragma unroll
    for (int mi = 0; mi < 4; mi++)
#pragma unroll
        for (int ni = 0; ni < 4; ni++)
#pragma unroll
            for (int c = 0; c < 4; c++) acc[mi][ni][c] = 0.0f;

    const int NC = K >> 5;

    const u32 ld_row = (u32)(tid >> 2);
    const u32 ld_ch  = (u32)(tid & 3);

    auto issue_stage = [&](int c, int buf) {
        const int k0 = c * 32;
        const u32 st = smem_base + buf * STAGE_S;
#pragma unroll
        for (int i = 0; i < 2; i++) {
            const u32 row = ld_row + i * 64;
            cp_async16(st + sw_off(row, ld_ch),
                       A + (long long)(m0 + row) * K + k0 + ld_ch * 8);
            cp_async16(st + PLANE_B + sw_off(row, ld_ch),
                       B + (long long)(n0 + row) * K + k0 + ld_ch * 8);
        }
        CP_COMMIT();
    };

    issue_stage(0, 0);
    issue_stage(1, 1);

    int buf = 0;
    int nbuf = 2;
    for (int c = 0; c < NC; ++c) {
        CP_WAIT1();
        __syncthreads();

        const u32 st = smem_base + buf * STAGE_S;

#pragma unroll
        for (int half = 0; half < 2; half++) {
            const u32 ch = (u32)(half * 2 + lch);

            u32 bh[4][2];
#pragma unroll
            for (int nj = 0; nj < 2; nj++) {
                const u32 rb = sw_off((u32)(wn * 32 + nj * 16 + lrow), ch);
                u32 r0, r1, r2, r3;
                ldmat4(r0, r1, r2, r3, st + PLANE_B + rb);
                bh[2*nj][0] = r0; bh[2*nj+1][0] = r1;
                bh[2*nj][1] = r2; bh[2*nj+1][1] = r3;
            }

#pragma unroll
            for (int mp = 0; mp < 2; mp++) {
                u32 ah[2][4];
#pragma unroll
                for (int q = 0; q < 2; q++) {
                    const int mi = mp * 2 + q;
                    const u32 ra = sw_off((u32)(wm * 64 + mi * 16 + lrow), ch);
                    ldmat4(ah[q][0], ah[q][1], ah[q][2], ah[q][3], st + ra);
                }
#pragma unroll
                for (int q = 0; q < 2; q++)
#pragma unroll
                    for (int ni = 0; ni < 4; ni++)
                        mma_bf16(acc[mp*2+q][ni], ah[q], bh[ni]);
            }
        }

        if (c + 2 < NC) issue_stage(c + 2, nbuf);
        else            CP_COMMIT();

        buf  = (buf  == 2) ? 0 : buf  + 1;
        nbuf = (nbuf == 2) ? 0 : nbuf + 1;
    }

#pragma unroll
    for (int mi = 0; mi < 4; mi++) {
        const int m_lo = m0 + wm * 64 + mi * 16 + g;
        const int m_hi = m_lo + 8;
#pragma unroll
        for (int ni = 0; ni < 4; ni++) {
            const int n = n0 + wn * 32 + ni * 8 + 2 * t;
            float2 v0, v1;
            v0.x = acc[mi][ni][0];
            v0.y = acc[mi][ni][1];
            v1.x = acc[mi][ni][2];
            v1.y = acc[mi][ni][3];
            *(float2*)(C + (long long)m_lo * N + n) = v0;
            *(float2*)(C + (long long)m_hi * N + n) = v1;
        }
    }
}

// ---------------------------------------------------------------------------
// tf32 GEMM core macros (shared by generic and QKV-merged kernels)
// ---------------------------------------------------------------------------
#define TF_STRIDE       36
#define TF_TILE_FLOATS  (128 * TF_STRIDE)      // 4608
#define TF_STAGE_FLOATS (2 * TF_TILE_FLOATS)   // 9216
#define TF_STAGE_BYTES  (TF_STAGE_FLOATS * 4)  // 36864
#define DYN_SMEM_T      (3 * TF_STAGE_BYTES)   // 110592

// ---------------------------------------------------------------------------
// generic tf32 GEMM on PRE-ROUNDED tf32 operands, ldmatrix fragment loads.
// (used for the scores GEMM)
// ---------------------------------------------------------------------------
__global__ __launch_bounds__(256, 2)
void tf32_gemm(const float* __restrict__ A, const float* __restrict__ B,
               float* __restrict__ C,
               int N, int K,
               long long sA, long long sB, long long sC, float alpha)
{
    extern __shared__ float smf[];

    const int tid  = threadIdx.x;
    const int wid  = tid >> 5;
    const int lane = tid & 31;
    const int wm   = wid >> 2;
    const int wn   = wid & 3;
    const int g    = lane >> 2;
    const int t    = lane & 3;

    const int bz = blockIdx.z;
    A += bz * sA; B += bz * sB; C += bz * sC;
    const int m0 = blockIdx.y * 128;
    const int n0 = blockIdx.x * 128;

    const u32 smem_base = smem_u32(smf);

    const int lj = lane >> 3;
    const int lr = lane & 7;
    const u32 aLane = (u32)(((wm * 64 + (lj & 1) * 8 + lr) * TF_STRIDE
                             + (lj >> 1) * 4) * 4);
    const u32 bLane = (u32)(((wn * 32 + (lj >> 1) * 8 + lr) * TF_STRIDE
                             + (lj & 1) * 4) * 4);

    float acc[4][4][4];
#pragma unroll
    for (int mi = 0; mi < 4; mi++)
#pragma unroll
        for (int ni = 0; ni < 4; ni++)
#pragma unroll
            for (int c = 0; c < 4; c++) acc[mi][ni][c] = 0.0f;

    const int NC = K >> 5;

    auto issue_stage = [&](int c, int buf) {
        const int k0 = c * 32;
        const u32 st = smem_base + buf * TF_STAGE_BYTES;
#pragma unroll
        for (int i = 0; i < 4; i++) {
            const int e   = tid + i * 256;
            const int row = e >> 3;
            const int q   = e & 7;
            cp_async16(st + (row * TF_STRIDE + q * 4) * 4,
                       A + (long long)(m0 + row) * K + k0 + q * 4);
        }
#pragma unroll
        for (int i = 0; i < 4; i++) {
            const int e   = tid + i * 256;
            const int row = e >> 3;
            const int q   = e & 7;
            cp_async16(st + TF_TILE_FLOATS * 4 + (row * TF_STRIDE + q * 4) * 4,
                       B + (long long)(n0 + row) * K + k0 + q * 4);
        }
        CP_COMMIT();
    };

    issue_stage(0, 0);
    issue_stage(1, 1);

    int buf = 0;
    int nbuf = 2;
    for (int c = 0; c < NC; ++c) {
        CP_WAIT1();
        __syncthreads();

        const u32 stA = smem_base + buf * TF_STAGE_BYTES + aLane;
        const u32 stB = smem_base + buf * TF_STAGE_BYTES + TF_TILE_FLOATS * 4 + bLane;

#pragma unroll
        for (int ks = 0; ks < 4; ks++) {
            const u32 kkB = (u32)(ks * 8 * 4);

            u32 bf[4][2];
            ldmat4(bf[0][0], bf[0][1], bf[1][0], bf[1][1], stB + kkB);
            ldmat4(bf[2][0], bf[2][1], bf[3][0], bf[3][1],
                   stB + 16 * TF_STRIDE * 4 + kkB);

#pragma unroll
            for (int mp = 0; mp < 2; mp++) {
                u32 af[2][4];
#pragma unroll
                for (int q = 0; q < 2; q++) {
                    const u32 ra = stA + (u32)((mp * 2 + q) * 16 * TF_STRIDE * 4) + kkB;
                    ldmat4(af[q][0], af[q][1], af[q][2], af[q][3], ra);
                }
#pragma unroll
                for (int q = 0; q < 2; q++)
#pragma unroll
                    for (int ni = 0; ni < 4; ni++)
                        mma_tf32(acc[mp*2+q][ni], af[q], bf[ni]);
            }
        }

        if (c + 2 < NC) issue_stage(c + 2, nbuf);
        else            CP_COMMIT();

        buf  = (buf  == 2) ? 0 : buf  + 1;
        nbuf = (nbuf == 2) ? 0 : nbuf + 1;
    }

#pragma unroll
    for (int mi = 0; mi < 4; mi++) {
        const int m_lo = m0 + wm * 64 + mi * 16 + g;
        const int m_hi = m_lo + 8;
#pragma unroll
        for (int ni = 0; ni < 4; ni++) {
            const int n = n0 + wn * 32 + ni * 8 + 2 * t;
            float2 v0, v1;
            v0.x = acc[mi][ni][0] * alpha;
            v0.y = acc[mi][ni][1] * alpha;
            v1.x = acc[mi][ni][2] * alpha;
            v1.y = acc[mi][ni][3] * alpha;
            *(float2*)(C + (long long)m_lo * N + n) = v0;
            *(float2*)(C + (long long)m_hi * N + n) = v1;
        }
    }
}

// ---------------------------------------------------------------------------
// merged QKV tf32 GEMM: grid.z in {0,1,2} selects weight/bias/output.
//   z=0: Q (tf32-rounded fp32 out)   z=1: K (tf32-rounded fp32 out)
//   z=2: V (bf16, transposed per batch out[b][n][s])
// ---------------------------------------------------------------------------
__global__ __launch_bounds__(256, 2)
void tf32_gemm_qkv(const float* __restrict__ A,
                   const float* __restrict__ WQ, const float* __restrict__ WK,
                   const float* __restrict__ WV,
                   float* __restrict__ Q, float* __restrict__ K,
                   u16* __restrict__ VTB,
                   const float* __restrict__ bq, const float* __restrict__ bk,
                   const float* __restrict__ bv)
{
    extern __shared__ float smf[];

    const int tid  = threadIdx.x;
    const int wid  = tid >> 5;
    const int lane = tid & 31;
    const int wm   = wid >> 2;
    const int wn   = wid & 3;
    const int g    = lane >> 2;
    const int t    = lane & 3;

    const int z = blockIdx.z;
    const float* B    = (z == 0) ? WQ : (z == 1) ? WK : WV;
    const float* bias = (z == 0) ? bq : (z == 1) ? bk : bv;

    const int m0 = blockIdx.y * 128;
    const int n0 = blockIdx.x * 128;

    const u32 smem_base = smem_u32(smf);

    const int lj = lane >> 3;
    const int lr = lane & 7;
    const u32 aLane = (u32)(((wm * 64 + (lj & 1) * 8 + lr) * TF_STRIDE
                             + (lj >> 1) * 4) * 4);
    const u32 bLane = (u32)(((wn * 32 + (lj >> 1) * 8 + lr) * TF_STRIDE
                             + (lj & 1) * 4) * 4);

    float acc[4][4][4];
#pragma unroll
    for (int mi = 0; mi < 4; mi++)
#pragma unroll
        for (int ni = 0; ni < 4; ni++)
#pragma unroll
            for (int c = 0; c < 4; c++) acc[mi][ni][c] = 0.0f;

    const int NC = DMODEL >> 5;   // 32

    auto issue_stage = [&](int c, int buf) {
        const int k0 = c * 32;
        const u32 st = smem_base + buf * TF_STAGE_BYTES;
#pragma unroll
        for (int i = 0; i < 4; i++) {
            const int e   = tid + i * 256;
            const int row = e >> 3;
            const int q   = e & 7;
            cp_async16(st + (row * TF_STRIDE + q * 4) * 4,
                       A + (long long)(m0 + row) * DMODEL + k0 + q * 4);
        }
#pragma unroll
        for (int i = 0; i < 4; i++) {
            const int e   = tid + i * 256;
            const int row = e >> 3;
            const int q   = e & 7;
            cp_async16(st + TF_TILE_FLOATS * 4 + (row * TF_STRIDE + q * 4) * 4,
                       B + (long long)(n0 + row) * DMODEL + k0 + q * 4);
        }
        CP_COMMIT();
    };

    issue_stage(0, 0);
    issue_stage(1, 1);

    int buf = 0;
    int nbuf = 2;
    for (int c = 0; c < NC; ++c) {
        CP_WAIT1();
        __syncthreads();

        const u32 stA = smem_base + buf * TF_STAGE_BYTES + aLane;
        const u32 stB = smem_base + buf * TF_STAGE_BYTES + TF_TILE_FLOATS * 4 + bLane;

#pragma unroll
        for (int ks = 0; ks < 4; ks++) {
            const u32 kkB = (u32)(ks * 8 * 4);

            u32 bf[4][2];
            ldmat4(bf[0][0], bf[0][1], bf[1][0], bf[1][1], stB + kkB);
            ldmat4(bf[2][0], bf[2][1], bf[3][0], bf[3][1],
                   stB + 16 * TF_STRIDE * 4 + kkB);

#pragma unroll
            for (int mp = 0; mp < 2; mp++) {
                u32 af[2][4];
#pragma unroll
                for (int q = 0; q < 2; q++) {
                    const u32 ra = stA + (u32)((mp * 2 + q) * 16 * TF_STRIDE * 4) + kkB;
                    ldmat4(af[q][0], af[q][1], af[q][2], af[q][3], ra);
                }
#pragma unroll
                for (int q = 0; q < 2; q++)
#pragma unroll
                    for (int ni = 0; ni < 4; ni++)
                        mma_tf32(acc[mp*2+q][ni], af[q], bf[ni]);
            }
        }

        if (c + 2 < NC) issue_stage(c + 2, nbuf);
        else            CP_COMMIT();

        buf  = (buf  == 2) ? 0 : buf  + 1;
        nbuf = (nbuf == 2) ? 0 : nbuf + 1;
    }

#pragma unroll
    for (int mi = 0; mi < 4; mi++) {
        const int m_lo = m0 + wm * 64 + mi * 16 + g;
        const int m_hi = m_lo + 8;
#pragma unroll
        for (int ni = 0; ni < 4; ni++) {
            const int n = n0 + wn * 32 + ni * 8 + 2 * t;
            const float b0 = bias[n], b1 = bias[n + 1];
            const float a0 = acc[mi][ni][0] + b0;
            const float a1 = acc[mi][ni][1] + b1;
            const float a2 = acc[mi][ni][2] + b0;
            const float a3 = acc[mi][ni][3] + b1;
            if (z == 2) {
                // bf16 V^T: out[b][n][s], m = b*SEQL + s; DMODEL*SEQL = 1<<21
                const long long base_lo = ((long long)(m_lo >> 11) << 21) + (m_lo & 2047);
                const long long base_hi = ((long long)(m_hi >> 11) << 21) + (m_hi & 2047);
                const u32 h0 = pack_bf16x2(a0, a1);
                const u32 h1 = pack_bf16x2(a2, a3);
                VTB[base_lo + (long long)n * SEQL]       = (u16)h0;
                VTB[base_lo + (long long)(n + 1) * SEQL] = (u16)(h0 >> 16);
                VTB[base_hi + (long long)n * SEQL]       = (u16)h1;
                VTB[base_hi + (long long)(n + 1) * SEQL] = (u16)(h1 >> 16);
            } else {
                float* C = (z == 0) ? Q : K;
                float2 v0, v1;
                v0.x = f2tf32f(a0); v0.y = f2tf32f(a1);
                v1.x = f2tf32f(a2); v1.y = f2tf32f(a3);
                *(float2*)(C + (long long)m_lo * DMODEL + n) = v0;
                *(float2*)(C + (long long)m_hi * DMODEL + n) = v1;
            }
        }
    }
}

// ---------------------------------------------------------------------------
// fp32 -> split bf16 hi/lo planes (4 elems per thread)
// ---------------------------------------------------------------------------
__global__ void split_fp32(const float* __restrict__ src,
                           u16* __restrict__ hi, u16* __restrict__ lo, int n4)
{
    const int i = blockIdx.x * blockDim.x + threadIdx.x;
    if (i >= n4) return;
    const float4 v = ((const float4*)src)[i];
    u32 h01, l01, h23, l23;
    split_pack(v.x, v.y, h01, l01);
    split_pack(v.z, v.w, h23, l23);
    ((uint2*)hi)[i] = make_uint2(h01, h23);
    ((uint2*)lo)[i] = make_uint2(l01, l23);
}

// ---------------------------------------------------------------------------
// three fp32 weight mats -> tf32-rounded fp32 (grid.y selects src/dst)
// ---------------------------------------------------------------------------
__global__ void round3_tf32(const float* __restrict__ s0, const float* __restrict__ s1,
                            const float* __restrict__ s2, float* __restrict__ d0,
                            float* __restrict__ d1, float* __restrict__ d2, int n4)
{
    const int i = blockIdx.x * blockDim.x + threadIdx.x;
    if (i >= n4) return;
    const float* src = (blockIdx.y == 0) ? s0 : (blockIdx.y == 1) ? s1 : s2;
    float* dst       = (blockIdx.y == 0) ? d0 : (blockIdx.y == 1) ? d1 : d2;
    float4 v = ((const float4*)src)[i];
    v.x = f2tf32f(v.x); v.y = f2tf32f(v.y);
    v.z = f2tf32f(v.z); v.w = f2tf32f(v.w);
    ((float4*)dst)[i] = v;
}

// ---------------------------------------------------------------------------
// Row softmax over fp32 logits (2048 cols), writing PACKED bf16 prob plane.
// ---------------------------------------------------------------------------
__global__ void softmax_bf16(const float* __restrict__ S, u16* __restrict__ P)
{
    const long long off = (long long)blockIdx.x * 2048;
    const float* row = S + off;
    const int tid = threadIdx.x;
    __shared__ float red[256];

    float v[8];
    *(float4*)&v[0] = *(const float4*)(row + tid * 8);
    *(float4*)&v[4] = *(const float4*)(row + tid * 8 + 4);

    float mx = -1e30f;
#pragma unroll
    for (int i = 0; i < 8; i++) mx = fmaxf(mx, v[i]);
    red[tid] = mx; __syncthreads();
    for (int s = 128; s > 0; s >>= 1) {
        if (tid < s) red[tid] = fmaxf(red[tid], red[tid + s]);
        __syncthreads();
    }
    mx = red[0]; __syncthreads();

    float sum = 0.0f;
#pragma unroll
    for (int i = 0; i < 8; i++) { v[i] = __expf(v[i] - mx); sum += v[i]; }
    red[tid] = sum; __syncthreads();
    for (int s = 128; s > 0; s >>= 1) {
        if (tid < s) red[tid] += red[tid + s];
        __syncthreads();
    }
    const float inv = 1.0f / red[0];

    u32* pp = (u32*)P + (off >> 1) + tid * 4;
#pragma unroll
    for (int j = 0; j < 4; j++)
        pp[j] = pack_bf16x2(v[2*j] * inv, v[2*j+1] * inv);
}

// ---------------------------------------------------------------------------
// Plain fp32 row softmax, in place (pooling weights, 8 rows)
// ---------------------------------------------------------------------------
__global__ void softmax_rows(float* __restrict__ S)
{
    float* row = S + (long long)blockIdx.x * 2048;
    const int tid = threadIdx.x;
    __shared__ float red[256];

    float v[8];
    *(float4*)&v[0] = *(const float4*)(row + tid * 8);
    *(float4*)&v[4] = *(const float4*)(row + tid * 8 + 4);

    float mx = -1e30f;
#pragma unroll
    for (int i = 0; i < 8; i++) mx = fmaxf(mx, v[i]);
    red[tid] = mx; __syncthreads();
    for (int s = 128; s > 0; s >>= 1) {
        if (tid < s) red[tid] = fmaxf(red[tid], red[tid + s]);
        __syncthreads();
    }
    mx = red[0]; __syncthreads();

    float sum = 0.0f;
#pragma unroll
    for (int i = 0; i < 8; i++) { v[i] = __expf(v[i] - mx); sum += v[i]; }
    red[tid] = sum; __syncthreads();
    for (int s = 128; s > 0; s >>= 1) {
        if (tid < s) red[tid] += red[tid + s];
        __syncthreads();
    }
    const float inv = 1.0f / red[0];
#pragma unroll
    for (int i = 0; i < 8; i++) v[i] *= inv;
    *(float4*)(row + tid * 8)     = *(float4*)&v[0];
    *(float4*)(row + tid * 8 + 4) = *(float4*)&v[4];
}

// ---------------------------------------------------------------------------
// h = x + z ; H = LN(h)*g + b  -> fp32 H + split planes (for bf16x3 SK GEMM)
// ---------------------------------------------------------------------------
__global__ void add_ln_split(const float* __restrict__ X, const float* __restrict__ Z,
                             const float* __restrict__ g, const float* __restrict__ b,
                             float* __restrict__ H, u16* __restrict__ hi, u16* __restrict__ lo)
{
    const long long r = blockIdx.x;
    const int tid = threadIdx.x;
    const int c0  = tid * 4;
    const float* xr = X + r * DMODEL;
    const float* zr = Z + r * DMODEL;
    __shared__ float red[256];

    float4 x4 = *(const float4*)(xr + c0);
    float4 z4 = *(const float4*)(zr + c0);
    float h[4] = { x4.x + z4.x, x4.y + z4.y, x4.z + z4.z, x4.w + z4.w };

    float sum = h[0] + h[1] + h[2] + h[3];
    red[tid] = sum; __syncthreads();
    for (int s = 128; s > 0; s >>= 1) {
        if (tid < s) red[tid] += red[tid + s];
        __syncthreads();
    }
    const float mean = red[0] * (1.0f / DMODEL);
    __syncthreads();

    float vs = 0.0f;
#pragma unroll
    for (int i = 0; i < 4; i++) { const float d = h[i] - mean; vs += d * d; }
    red[tid] = vs; __syncthreads();
    for (int s = 128; s > 0; s >>= 1) {
        if (tid < s) red[tid] += red[tid + s];
        __syncthreads();
    }
    const float inv = rsqrtf(red[0] * (1.0f / DMODEL) + LN_EPS);

    float4 o;
    o.x = (h[0] - mean) * inv * g[c0 + 0] + b[c0 + 0];
    o.y = (h[1] - mean) * inv * g[c0 + 1] + b[c0 + 1];
    o.z = (h[2] - mean) * inv * g[c0 + 2] + b[c0 + 2];
    o.w = (h[3] - mean) * inv * g[c0 + 3] + b[c0 + 3];
    *(float4*)(H + r * DMODEL + c0) = o;

    u32 h01, l01, h23, l23;
    split_pack(o.x, o.y, h01, l01);
    split_pack(o.z, o.w, h23, l23);
    const long long pi = (r * DMODEL + c0) >> 1;
    ((u32*)hi)[pi]     = h01;
    ((u32*)hi)[pi + 1] = h23;
    ((u32*)lo)[pi]     = l01;
    ((u32*)lo)[pi + 1] = l23;
}

// ---------------------------------------------------------------------------
// T[r] = sum of 32 soft-key partials (deterministic fixed-order reduce)
// ---------------------------------------------------------------------------
__global__ void skt_reduce(const float* __restrict__ TP, float* __restrict__ T)
{
    const int r = blockIdx.x * 256 + threadIdx.x;
    const float* p = TP + (long long)r * 32;
    float s = 0.0f;
#pragma unroll
    for (int j = 0; j < 32; j++) s += p[j];
    T[r] = s;
}

// ---------------------------------------------------------------------------
// final_out stage 1: partial over 256-row s-chunk
// ---------------------------------------------------------------------------
__global__ void final_partial(const float* __restrict__ H, const float* __restrict__ w,
                              float* __restrict__ OP)
{
    const int b  = blockIdx.y;
    const int zc = blockIdx.z;
    const int o  = blockIdx.x * 256 + threadIdx.x;
    const float* Hp = H + (long long)b * SEQL * DMODEL
                        + (long long)(zc * 256) * DMODEL + o;
    const float* wb = w + (long long)b * SEQL + zc * 256;

    float a0 = 0.0f, a1 = 0.0f, a2 = 0.0f, a3 = 0.0f;
    for (int s = 0; s < 256; s += 4) {
        a0 += wb[s + 0] * Hp[(long long)(s + 0) * DMODEL];
        a1 += wb[s + 1] * Hp[(long long)(s + 1) * DMODEL];
        a2 += wb[s + 2] * Hp[(long long)(s + 2) * DMODEL];
        a3 += wb[s + 3] * Hp[(long long)(s + 3) * DMODEL];
    }
    OP[(long long)(b * 8 + zc) * DMODEL + o] = (a0 + a1) + (a2 + a3);
}

// final_out stage 2
__global__ void final_reduce(const float* __restrict__ OP, float* __restrict__ out)
{
    const int b = blockIdx.y;
    const int o = blockIdx.x * 256 + threadIdx.x;
    float s = 0.0f;
#pragma unroll
    for (int z = 0; z < 8; z++)
        s += OP[(long long)(b * 8 + z) * DMODEL + o];
    out[b * DMODEL + o] = s;
}

// ---------------------------------------------------------------------------
// Launch
// ---------------------------------------------------------------------------
extern "C" void kernel_launch(void* const* d_in, const int* in_sizes, int n_in,
                              void* d_out, int out_size)
{
    const float* inputs  = (const float*)d_in[0];
    const float* embed_w = (const float*)d_in[1];
    const float* embed_b = (const float*)d_in[2];
    const float* wq_w    = (const float*)d_in[3];
    const float* wq_b    = (const float*)d_in[4];
    const float* wk_w    = (const float*)d_in[5];
    const float* wk_b    = (const float*)d_in[6];
    const float* wv_w    = (const float*)d_in[7];
    const float* wv_b    = (const float*)d_in[8];
    const float* ln_g    = (const float*)d_in[9];
    const float* ln_b    = (const float*)d_in[10];
    const float* skw     = (const float*)d_in[11];
    const float* sq      = (const float*)d_in[12];
    const float* pos     = (const float*)d_in[13];
    float* out = (float*)d_out;

    cudaFuncSetAttribute((const void*)bf16x3_gemm<true,  false>,
                         cudaFuncAttributeMaxDynamicSharedMemorySize, DYN_SMEM_G);
    cudaFuncSetAttribute((const void*)bf16x3_gemm<false, true>,
                         cudaFuncAttributeMaxDynamicSharedMemorySize, DYN_SMEM_G);
    cudaFuncSetAttribute((const void*)bf16s_gemm,
                         cudaFuncAttributeMaxDynamicSharedMemorySize, DYN_SMEM_S);
    cudaFuncSetAttribute((const void*)tf32_gemm,
                         cudaFuncAttributeMaxDynamicSharedMemorySize, DYN_SMEM_T);
    cudaFuncSetAttribute((const void*)tf32_gemm_qkv,
                         cudaFuncAttributeMaxDynamicSharedMemorySize, DYN_SMEM_T);

    float* base = 0;
    cudaGetSymbolAddress((void**)&base, g_scratch);

    u16* INh  = (u16*)(base + O_INS);   u16* INl  = INh  + C_IN;
    u16* EWh  = (u16*)(base + O_EWS);   u16* EWl  = EWh  + C_EW;
    u16* SKWh = (u16*)(base + O_SKWS);  u16* SKWl = SKWh + C_W;
    float* WQT = base + O_WQT;
    float* WKT = base + O_WKT;
    float* WVT = base + O_WVT;
    float* X  = base + O_X;
    float* XT = base + O_XT;
    float* Q  = base + O_Q;
    float* K  = base + O_K;
    u16* VTB  = (u16*)(base + O_VTB);
    float* SC = base + O_SC;
    u16* SCB  = (u16*)(base + O_SCB);
    float* Z  = base + O_Z;
    float* H  = base + O_H;
    u16* Hh   = (u16*)(base + O_HS);    u16* Hl   = Hh + C_MAT;
    float* TP = base + O_TP;
    float* OP = base + O_OP;
    float* T  = base + O_T;

    // 0) operand prep
    split_fp32<<<(int)(C_IN / 4 / 256), 256>>>(inputs,  INh,  INl,  (int)(C_IN / 4));
    split_fp32<<<(int)(C_EW / 4 / 256), 256>>>(embed_w, EWh,  EWl,  (int)(C_EW / 4));
    split_fp32<<<(int)(C_W  / 4 / 256), 256>>>(skw,     SKWh, SKWl, (int)(C_W / 4));
    round3_tf32<<<dim3((int)(C_W / 4 / 256), 3), 256>>>(
        wq_w, wk_w, wv_w, WQT, WKT, WVT, (int)(C_W / 4));

    // 1) embed (bf16x3): X = inputs @ embed_w^T + embed_b + pos_enc; also Xt
    bf16x3_gemm<true, false><<<dim3(DMODEL / 128, NROW / 128, 1), 256, DYN_SMEM_G>>>(
        INh, INl, EWh, EWl, X, XT, 0, 0, DMODEL, D_IN, embed_b, pos);

    // 2) merged QKV (tf32): Q/K tf32-rounded fp32; V -> bf16 transposed
    tf32_gemm_qkv<<<dim3(DMODEL / 128, NROW / 128, 3), 256, DYN_SMEM_T>>>(
        XT, WQT, WKT, WVT, Q, K, VTB, wq_b, wk_b, wv_b);

    // 3) scores = Q @ K^T / 32 (batched, tf32)
    tf32_gemm<<<dim3(SEQL / 128, SEQL / 128, BATCH), 256, DYN_SMEM_T>>>(
        Q, K, SC, SEQL, DMODEL,
        (long long)SEQL * DMODEL, (long long)SEQL * DMODEL, (long long)SEQL * SEQL,
        1.0f / 32.0f);

    // 4) softmax: fp32 logits -> bf16 prob plane
    softmax_bf16<<<NROW, 256>>>(SC, SCB);

    // 5) Z = P @ V  (single-term bf16: half the HMMAs of the tf32 version)
    bf16s_gemm<<<dim3(DMODEL / 128, SEQL / 128, BATCH), 256, DYN_SMEM_S>>>(
        SCB, VTB, Z, DMODEL, SEQL,
        (long long)SEQL * SEQL, (long long)DMODEL * SEQL, (long long)SEQL * DMODEL);

    // 6) H = LN(X + Z)*g + b  (fp32 + split planes for SK)
    add_ln_split<<<NROW, 256>>>(X, Z, ln_g, ln_b, H, Hh, Hl);

    // 7) fused SK GEMM (bf16x3 — unscaled logits need the precision) -> TP
    bf16x3_gemm<false, true><<<dim3(DMODEL / 128, NROW / 128, 1), 256, DYN_SMEM_G>>>(
        Hh, Hl, SKWh, SKWl, 0, 0, TP, sq, DMODEL, DMODEL, 0, 0);

    // 8) T[r] = sum partials; softmax over s per batch
    skt_reduce<<<NROW / 256, 256>>>(TP, T);
    softmax_rows<<<BATCH, 256>>>(T);

    // 9) out[b,o] = sum_s w[b,s] * H[b,s,o]  (two-stage, deterministic)
    final_partial<<<dim3(DMODEL / 256, BATCH, 8), 256>>>(H, T, OP);
    final_reduce<<<dim3(DMODEL / 256, BATCH), 256>>>(OP, out);
}

// round 17
// speedup vs baseline: 2.2134x; 1.2595x over previous
#include <cuda_runtime.h>
#include <cstdint>
#include <math.h>

// ---------------------------------------------------------------------------
// Problem constants
// ---------------------------------------------------------------------------
#define BATCH   8
#define SEQL    2048
#define D_IN    512
#define DMODEL  1024
#define NROW    (BATCH * SEQL)          // 16384
#define LN_EPS  1e-5f

typedef unsigned short u16;
typedef uint32_t u32;

// element counts
static const long long C_IN  = (long long)NROW * D_IN;       // 8388608
static const long long C_EW  = (long long)DMODEL * D_IN;     // 524288
static const long long C_W   = (long long)DMODEL * DMODEL;   // 1048576
static const long long C_MAT = (long long)NROW * DMODEL;     // 16777216
static const long long C_SC  = (long long)BATCH * SEQL * SEQL; // 33554432

// scratch offsets (in floats; u16 arrays take count/2 float slots)
#define O_INS   (0LL)
#define O_EWS   (O_INS  + C_IN)
#define O_SKWS  (O_EWS  + C_EW)
#define O_WQH   (O_SKWS + C_W)          // fp16 weights
#define O_WKH   (O_WQH  + C_W / 2)
#define O_WVH   (O_WKH  + C_W / 2)
#define O_X     (O_WVH  + C_W / 2)      // fp32 X
#define O_X16   (O_X    + C_MAT)        // fp16 X plane
#define O_Q16   (O_X16  + C_MAT / 2)    // fp16 Q
#define O_K16   (O_Q16  + C_MAT / 2)    // fp16 K
#define O_VT16  (O_K16  + C_MAT / 2)    // fp16 V^T (per batch [n][s])
#define O_SC    (O_VT16 + C_MAT / 2)    // fp32 score logits
#define O_P16   (O_SC   + C_SC)         // fp16 softmax probs
#define O_Z     (O_P16  + C_SC / 2)
#define O_H     (O_Z    + C_MAT)
#define O_HS    (O_H    + C_MAT)        // split H planes
#define O_TP    (O_HS   + C_MAT)                 // soft-key partials [16384][32]
#define O_OP    (O_TP   + 16384LL * 32)          // final_out partials [64][1024]
#define O_T     (O_OP   + 65536)
#define O_TOTAL (O_T    + 16384)

__device__ float g_scratch[O_TOTAL];

// ---------------------------------------------------------------------------
// PTX helpers (baseline sm_80+ features only — harness targets plain sm_103)
// ---------------------------------------------------------------------------
__device__ __forceinline__ u32 smem_u32(const void* p) {
    u32 a;
    asm("{ .reg .u64 t; cvta.to.shared.u64 t, %1; cvt.u32.u64 %0, t; }"
        : "=r"(a) : "l"(p));
    return a;
}

__device__ __forceinline__ void cp_async16(u32 dst, const void* src) {
    asm volatile("cp.async.cg.shared.global [%0], [%1], 16;" :: "r"(dst), "l"(src));
}
#define CP_COMMIT() asm volatile("cp.async.commit_group;" ::: "memory")
#define CP_WAIT1()  asm volatile("cp.async.wait_group 1;"  ::: "memory")

// split x0,x1 (fp32) into packed bf16x2 hi and lo parts: x = hi + lo
__device__ __forceinline__ void split_pack(float x0, float x1, u32& hi, u32& lo) {
    asm("cvt.rn.bf16x2.f32 %0, %1, %2;" : "=r"(hi) : "f"(x1), "f"(x0));
    const float h0 = __uint_as_float(hi << 16);
    const float h1 = __uint_as_float(hi & 0xFFFF0000u);
    const float l0 = x0 - h0;
    const float l1 = x1 - h1;
    asm("cvt.rn.bf16x2.f32 %0, %1, %2;" : "=r"(lo) : "f"(l1), "f"(l0));
}

// pack two fp32 into f16x2 (round-to-nearest); low half = x0
__device__ __forceinline__ u32 pack_f16x2(float x0, float x1) {
    u32 r;
    asm("cvt.rn.f16x2.f32 %0, %1, %2;" : "=r"(r) : "f"(x1), "f"(x0));
    return r;
}

// D += A*B  (m16n8k16 bf16, fp32 accum)
__device__ __forceinline__ void mma_bf16(float* d, const u32* a, const u32* b) {
    asm volatile(
        "mma.sync.aligned.m16n8k16.row.col.f32.bf16.bf16.f32 "
        "{%0,%1,%2,%3}, {%4,%5,%6,%7}, {%8,%9}, {%0,%1,%2,%3};"
        : "+f"(d[0]), "+f"(d[1]), "+f"(d[2]), "+f"(d[3])
        : "r"(a[0]), "r"(a[1]), "r"(a[2]), "r"(a[3]), "r"(b[0]), "r"(b[1]));
}

// D += A*B  (m16n8k16 fp16, fp32 accum) — 11-bit mantissa, tf32-equivalent
__device__ __forceinline__ void mma_f16(float* d, const u32* a, const u32* b) {
    asm volatile(
        "mma.sync.aligned.m16n8k16.row.col.f32.f16.f16.f32 "
        "{%0,%1,%2,%3}, {%4,%5,%6,%7}, {%8,%9}, {%0,%1,%2,%3};"
        : "+f"(d[0]), "+f"(d[1]), "+f"(d[2]), "+f"(d[3])
        : "r"(a[0]), "r"(a[1]), "r"(a[2]), "r"(a[3]), "r"(b[0]), "r"(b[1]));
}

__device__ __forceinline__ void ldmat4(u32& r0, u32& r1, u32& r2, u32& r3, u32 addr) {
    asm volatile("ldmatrix.sync.aligned.m8n8.x4.shared.b16 {%0,%1,%2,%3}, [%4];"
                 : "=r"(r0), "=r"(r1), "=r"(r2), "=r"(r3) : "r"(addr));
}

// swizzled byte offset of (row, 16B-chunk ch) in a 128x32 x16b plane (64B rows)
__device__ __forceinline__ u32 sw_off(u32 row, u32 ch) {
    return row * 64u + ((ch ^ ((row >> 1) & 3u)) << 4);
}

// ---------------------------------------------------------------------------
// bf16x3 split GEMM (embed + SK): C = A@B^T (+bias +posenc)
// R7/R10 proven cadence: 3-buffer, one barrier/chunk, load-after-compute.
//   X16OUT: also write fp16 copy of C (embed; feeds fp16 QKV GEMM)
//   SKRED:  fused soft-key epilogue (partials of sum tanh(C)*q), no C written
// ---------------------------------------------------------------------------
#define PLANE_B  (128 * 64)             // 8192
#define STAGE_B  (4 * PLANE_B)          // 32768
#define DYN_SMEM_G (3 * STAGE_B)        // 98304

template <bool X16OUT, bool SKRED>
__global__ __launch_bounds__(256, 2)
void bf16x3_gemm(const u16* __restrict__ Ahi, const u16* __restrict__ Alo,
                 const u16* __restrict__ Bhi, const u16* __restrict__ Blo,
                 float* __restrict__ Cf, u16* __restrict__ C16,
                 float* __restrict__ TP, const float* __restrict__ qvec,
                 int N, int K,
                 const float* __restrict__ bias,
                 const float* __restrict__ posenc)
{
    extern __shared__ char smem[];

    const int tid  = threadIdx.x;
    const int wid  = tid >> 5;
    const int lane = tid & 31;
    const int wm   = wid >> 2;
    const int wn   = wid & 3;
    const int g    = lane >> 2;
    const int t    = lane & 3;
    const int lrow = lane & 15;
    const int lch  = lane >> 4;

    const int m0 = blockIdx.y * 128;
    const int n0 = blockIdx.x * 128;

    const u32 smem_base = smem_u32(smem);

    float acc[4][4][4];
#pragma unroll
    for (int mi = 0; mi < 4; mi++)
#pragma unroll
        for (int ni = 0; ni < 4; ni++)
#pragma unroll
            for (int c = 0; c < 4; c++) acc[mi][ni][c] = 0.0f;

    const int NC = K >> 5;

    const u32 ld_row = (u32)(tid >> 2);
    const u32 ld_ch  = (u32)(tid & 3);

    auto issue_stage = [&](int c, int buf) {
        const int k0 = c * 32;
        const u32 st = smem_base + buf * STAGE_B;
        const u16* srcs[4] = { Ahi, Alo, Bhi, Blo };
#pragma unroll
        for (int p = 0; p < 4; p++) {
            const u16* src = srcs[p];
            const int rbase = (p < 2) ? m0 : n0;
#pragma unroll
            for (int i = 0; i < 2; i++) {
                const u32 row = ld_row + i * 64;
                cp_async16(st + p * PLANE_B + sw_off(row, ld_ch),
                           src + (long long)(rbase + row) * K + k0 + ld_ch * 8);
            }
        }
        CP_COMMIT();
    };

    issue_stage(0, 0);
    issue_stage(1, 1);

    int buf = 0;
    int nbuf = 2;
    for (int c = 0; c < NC; ++c) {
        CP_WAIT1();
        __syncthreads();

        const u32 st = smem_base + buf * STAGE_B;

#pragma unroll
        for (int half = 0; half < 2; half++) {
            const u32 ch = (u32)(half * 2 + lch);

            u32 bh[4][2], bl[4][2];
#pragma unroll
            for (int nj = 0; nj < 2; nj++) {
                const u32 rb = sw_off((u32)(wn * 32 + nj * 16 + lrow), ch);
                u32 r0, r1, r2, r3;
                ldmat4(r0, r1, r2, r3, st + 2 * PLANE_B + rb);
                bh[2*nj][0] = r0; bh[2*nj+1][0] = r1;
                bh[2*nj][1] = r2; bh[2*nj+1][1] = r3;
                ldmat4(r0, r1, r2, r3, st + 3 * PLANE_B + rb);
                bl[2*nj][0] = r0; bl[2*nj+1][0] = r1;
                bl[2*nj][1] = r2; bl[2*nj+1][1] = r3;
            }

#pragma unroll
            for (int mp = 0; mp < 2; mp++) {
                u32 ah[2][4], al[2][4];
#pragma unroll
                for (int q = 0; q < 2; q++) {
                    const int mi = mp * 2 + q;
                    const u32 ra = sw_off((u32)(wm * 64 + mi * 16 + lrow), ch);
                    ldmat4(ah[q][0], ah[q][1], ah[q][2], ah[q][3], st + ra);
                    ldmat4(al[q][0], al[q][1], al[q][2], al[q][3], st + PLANE_B + ra);
                }
#pragma unroll
                for (int q = 0; q < 2; q++)
#pragma unroll
                    for (int ni = 0; ni < 4; ni++)
                        mma_bf16(acc[mp*2+q][ni], ah[q], bh[ni]);
#pragma unroll
                for (int q = 0; q < 2; q++)
#pragma unroll
                    for (int ni = 0; ni < 4; ni++)
                        mma_bf16(acc[mp*2+q][ni], ah[q], bl[ni]);
#pragma unroll
                for (int q = 0; q < 2; q++)
#pragma unroll
                    for (int ni = 0; ni < 4; ni++)
                        mma_bf16(acc[mp*2+q][ni], al[q], bh[ni]);
            }
        }

        if (c + 2 < NC) issue_stage(c + 2, nbuf);
        else            CP_COMMIT();

        buf  = (buf  == 2) ? 0 : buf  + 1;
        nbuf = (nbuf == 2) ? 0 : nbuf + 1;
    }

    // ---- epilogue ----
    if (SKRED) {
#pragma unroll
        for (int mi = 0; mi < 4; mi++) {
            float p0 = 0.0f, p1 = 0.0f;
#pragma unroll
            for (int ni = 0; ni < 4; ni++) {
                const int n = n0 + wn * 32 + ni * 8 + 2 * t;
                const float q0 = qvec[n], q1 = qvec[n + 1];
                p0 += tanhf(acc[mi][ni][0]) * q0 + tanhf(acc[mi][ni][1]) * q1;
                p1 += tanhf(acc[mi][ni][2]) * q0 + tanhf(acc[mi][ni][3]) * q1;
            }
            p0 += __shfl_xor_sync(0xffffffffu, p0, 1);
            p0 += __shfl_xor_sync(0xffffffffu, p0, 2);
            p1 += __shfl_xor_sync(0xffffffffu, p1, 1);
            p1 += __shfl_xor_sync(0xffffffffu, p1, 2);
            if (t == 0) {
                const int m_lo = m0 + wm * 64 + mi * 16 + g;
                const int slot = blockIdx.x * 4 + wn;
                TP[(long long)m_lo * 32 + slot]       = p0;
                TP[(long long)(m_lo + 8) * 32 + slot] = p1;
            }
        }
        return;
    }

#pragma unroll
    for (int mi = 0; mi < 4; mi++) {
        const int m_lo = m0 + wm * 64 + mi * 16 + g;
        const int m_hi = m_lo + 8;
        const float* pe_lo = posenc + (long long)(m_lo & (SEQL - 1)) * N;
        const float* pe_hi = posenc + (long long)(m_hi & (SEQL - 1)) * N;
#pragma unroll
        for (int ni = 0; ni < 4; ni++) {
            const int n = n0 + wn * 32 + ni * 8 + 2 * t;
            const float b0 = bias[n], b1 = bias[n + 1];
            float2 v0, v1;
            v0.x = acc[mi][ni][0] + b0 + pe_lo[n];
            v0.y = acc[mi][ni][1] + b1 + pe_lo[n + 1];
            v1.x = acc[mi][ni][2] + b0 + pe_hi[n];
            v1.y = acc[mi][ni][3] + b1 + pe_hi[n + 1];
            *(float2*)(Cf + (long long)m_lo * N + n) = v0;
            *(float2*)(Cf + (long long)m_hi * N + n) = v1;
            if (X16OUT) {
                *(u32*)(C16 + (long long)m_lo * N + n) = pack_f16x2(v0.x, v0.y);
                *(u32*)(C16 + (long long)m_hi * N + n) = pack_f16x2(v1.x, v1.y);
            }
        }
    }
}

// ---------------------------------------------------------------------------
// single-term fp16 GEMM: A [M][K] fp16, B [N][K] fp16, C fp32 * alpha.
// Same proven cadence; 2 planes per stage, 32 MMAs per K=32 chunk.
// (used for scores and Z)
// ---------------------------------------------------------------------------
#define STAGE_S    (2 * PLANE_B)        // 16384
#define DYN_SMEM_S (3 * STAGE_S)        // 49152

__global__ __launch_bounds__(256, 2)
void h16_gemm(const u16* __restrict__ A, const u16* __restrict__ B,
              float* __restrict__ C, int N, int K,
              long long sA, long long sB, long long sC, float alpha)
{
    extern __shared__ char smem[];

    const int tid  = threadIdx.x;
    const int wid  = tid >> 5;
    const int lane = tid & 31;
    const int wm   = wid >> 2;
    const int wn   = wid & 3;
    const int g    = lane >> 2;
    const int t    = lane & 3;
    const int lrow = lane & 15;
    const int lch  = lane >> 4;

    const int bz = blockIdx.z;
    A += bz * sA; B += bz * sB; C += bz * sC;
    const int m0 = blockIdx.y * 128;
    const int n0 = blockIdx.x * 128;

    const u32 smem_base = smem_u32(smem);

    float acc[4][4][4];
#pragma unroll
    for (int mi = 0; mi < 4; mi++)
#pragma unroll
        for (int ni = 0; ni < 4; ni++)
#pragma unroll
            for (int c = 0; c < 4; c++) acc[mi][ni][c] = 0.0f;

    const int NC = K >> 5;

    const u32 ld_row = (u32)(tid >> 2);
    const u32 ld_ch  = (u32)(tid & 3);

    auto issue_stage = [&](int c, int buf) {
        const int k0 = c * 32;
        const u32 st = smem_base + buf * STAGE_S;
#pragma unroll
        for (int i = 0; i < 2; i++) {
            const u32 row = ld_row + i * 64;
            cp_async16(st + sw_off(row, ld_ch),
                       A + (long long)(m0 + row) * K + k0 + ld_ch * 8);
            cp_async16(st + PLANE_B + sw_off(row, ld_ch),
                       B + (long long)(n0 + row) * K + k0 + ld_ch * 8);
        }
        CP_COMMIT();
    };

    issue_stage(0, 0);
    issue_stage(1, 1);

    int buf = 0;
    int nbuf = 2;
    for (int c = 0; c < NC; ++c) {
        CP_WAIT1();
        __syncthreads();

        const u32 st = smem_base + buf * STAGE_S;

#pragma unroll
        for (int half = 0; half < 2; half++) {
            const u32 ch = (u32)(half * 2 + lch);

            u32 bh[4][2];
#pragma unroll
            for (int nj = 0; nj < 2; nj++) {
                const u32 rb = sw_off((u32)(wn * 32 + nj * 16 + lrow), ch);
                u32 r0, r1, r2, r3;
                ldmat4(r0, r1, r2, r3, st + PLANE_B + rb);
                bh[2*nj][0] = r0; bh[2*nj+1][0] = r1;
                bh[2*nj][1] = r2; bh[2*nj+1][1] = r3;
            }

#pragma unroll
            for (int mp = 0; mp < 2; mp++) {
                u32 ah[2][4];
#pragma unroll
                for (int q = 0; q < 2; q++) {
                    const int mi = mp * 2 + q;
                    const u32 ra = sw_off((u32)(wm * 64 + mi * 16 + lrow), ch);
                    ldmat4(ah[q][0], ah[q][1], ah[q][2], ah[q][3], st + ra);
                }
#pragma unroll
                for (int q = 0; q < 2; q++)
#pragma unroll
                    for (int ni = 0; ni < 4; ni++)
                        mma_f16(acc[mp*2+q][ni], ah[q], bh[ni]);
            }
        }

        if (c + 2 < NC) issue_stage(c + 2, nbuf);
        else            CP_COMMIT();

        buf  = (buf  == 2) ? 0 : buf  + 1;
        nbuf = (nbuf == 2) ? 0 : nbuf + 1;
    }

#pragma unroll
    for (int mi = 0; mi < 4; mi++) {
        const int m_lo = m0 + wm * 64 + mi * 16 + g;
        const int m_hi = m_lo + 8;
#pragma unroll
        for (int ni = 0; ni < 4; ni++) {
            const int n = n0 + wn * 32 + ni * 8 + 2 * t;
            float2 v0, v1;
            v0.x = acc[mi][ni][0] * alpha;
            v0.y = acc[mi][ni][1] * alpha;
            v1.x = acc[mi][ni][2] * alpha;
            v1.y = acc[mi][ni][3] * alpha;
            *(float2*)(C + (long long)m_lo * N + n) = v0;
            *(float2*)(C + (long long)m_hi * N + n) = v1;
        }
    }
}

// ---------------------------------------------------------------------------
// merged QKV fp16 GEMM: grid.z in {0,1,2} selects weight/bias/output.
//   z=0: Q fp16 out   z=1: K fp16 out
//   z=2: V fp16, transposed per batch out[b][n][s]
// A = X fp16 [NROW][DMODEL], weights fp16 [DMODEL][DMODEL].
// ---------------------------------------------------------------------------
__global__ __launch_bounds__(256, 2)
void h16_gemm_qkv(const u16* __restrict__ A,
                  const u16* __restrict__ WQ, const u16* __restrict__ WK,
                  const u16* __restrict__ WV,
                  u16* __restrict__ Q, u16* __restrict__ K,
                  u16* __restrict__ VT,
                  const float* __restrict__ bq, const float* __restrict__ bk,
                  const float* __restrict__ bv)
{
    extern __shared__ char smem[];

    const int tid  = threadIdx.x;
    const int wid  = tid >> 5;
    const int lane = tid & 31;
    const int wm   = wid >> 2;
    const int wn   = wid & 3;
    const int g    = lane >> 2;
    const int t    = lane & 3;
    const int lrow = lane & 15;
    const int lch  = lane >> 4;

    const int z = blockIdx.z;
    const u16* B      = (z == 0) ? WQ : (z == 1) ? WK : WV;
    const float* bias = (z == 0) ? bq : (z == 1) ? bk : bv;

    const int m0 = blockIdx.y * 128;
    const int n0 = blockIdx.x * 128;

    const u32 smem_base = smem_u32(smem);

    float acc[4][4][4];
#pragma unroll
    for (int mi = 0; mi < 4; mi++)
#pragma unroll
        for (int ni = 0; ni < 4; ni++)
#pragma unroll
            for (int c = 0; c < 4; c++) acc[mi][ni][c] = 0.0f;

    const int NC = DMODEL >> 5;

    const u32 ld_row = (u32)(tid >> 2);
    const u32 ld_ch  = (u32)(tid & 3);

    auto issue_stage = [&](int c, int buf) {
        const int k0 = c * 32;
        const u32 st = smem_base + buf * STAGE_S;
#pragma unroll
        for (int i = 0; i < 2; i++) {
            const u32 row = ld_row + i * 64;
            cp_async16(st + sw_off(row, ld_ch),
                       A + (long long)(m0 + row) * DMODEL + k0 + ld_ch * 8);
            cp_async16(st + PLANE_B + sw_off(row, ld_ch),
                       B + (long long)(n0 + row) * DMODEL + k0 + ld_ch * 8);
        }
        CP_COMMIT();
    };

    issue_stage(0, 0);
    issue_stage(1, 1);

    int buf = 0;
    int nbuf = 2;
    for (int c = 0; c < NC; ++c) {
        CP_WAIT1();
        __syncthreads();

        const u32 st = smem_base + buf * STAGE_S;

#pragma unroll
        for (int half = 0; half < 2; half++) {
            const u32 ch = (u32)(half * 2 + lch);

            u32 bh[4][2];
#pragma unroll
            for (int nj = 0; nj < 2; nj++) {
                const u32 rb = sw_off((u32)(wn * 32 + nj * 16 + lrow), ch);
                u32 r0, r1, r2, r3;
                ldmat4(r0, r1, r2, r3, st + PLANE_B + rb);
                bh[2*nj][0] = r0; bh[2*nj+1][0] = r1;
                bh[2*nj][1] = r2; bh[2*nj+1][1] = r3;
            }

#pragma unroll
            for (int mp = 0; mp < 2; mp++) {
                u32 ah[2][4];
#pragma unroll
                for (int q = 0; q < 2; q++) {
                    const int mi = mp * 2 + q;
                    const u32 ra = sw_off((u32)(wm * 64 + mi * 16 + lrow), ch);
                    ldmat4(ah[q][0], ah[q][1], ah[q][2], ah[q][3], st + ra);
                }
#pragma unroll
                for (int q = 0; q < 2; q++)
#pragma unroll
                    for (int ni = 0; ni < 4; ni++)
                        mma_f16(acc[mp*2+q][ni], ah[q], bh[ni]);
            }
        }

        if (c + 2 < NC) issue_stage(c + 2, nbuf);
        else            CP_COMMIT();

        buf  = (buf  == 2) ? 0 : buf  + 1;
        nbuf = (nbuf == 2) ? 0 : nbuf + 1;
    }

#pragma unroll
    for (int mi = 0; mi < 4; mi++) {
        const int m_lo = m0 + wm * 64 + mi * 16 + g;
        const int m_hi = m_lo + 8;
#pragma unroll
        for (int ni = 0; ni < 4; ni++) {
            const int n = n0 + wn * 32 + ni * 8 + 2 * t;
            const float b0 = bias[n], b1 = bias[n + 1];
            const float a0 = acc[mi][ni][0] + b0;
            const float a1 = acc[mi][ni][1] + b1;
            const float a2 = acc[mi][ni][2] + b0;
            const float a3 = acc[mi][ni][3] + b1;
            const u32 h0 = pack_f16x2(a0, a1);
            const u32 h1 = pack_f16x2(a2, a3);
            if (z == 2) {
                // fp16 V^T: out[b][n][s], m = b*SEQL + s; DMODEL*SEQL = 1<<21
                const long long base_lo = ((long long)(m_lo >> 11) << 21) + (m_lo & 2047);
                const long long base_hi = ((long long)(m_hi >> 11) << 21) + (m_hi & 2047);
                VT[base_lo + (long long)n * SEQL]       = (u16)h0;
                VT[base_lo + (long long)(n + 1) * SEQL] = (u16)(h0 >> 16);
                VT[base_hi + (long long)n * SEQL]       = (u16)h1;
                VT[base_hi + (long long)(n + 1) * SEQL] = (u16)(h1 >> 16);
            } else {
                u16* C = (z == 0) ? Q : K;
                *(u32*)(C + (long long)m_lo * DMODEL + n) = h0;
                *(u32*)(C + (long long)m_hi * DMODEL + n) = h1;
            }
        }
    }
}

// ---------------------------------------------------------------------------
// fp32 -> split bf16 hi/lo planes (4 elems per thread)
// ---------------------------------------------------------------------------
__global__ void split_fp32(const float* __restrict__ src,
                           u16* __restrict__ hi, u16* __restrict__ lo, int n4)
{
    const int i = blockIdx.x * blockDim.x + threadIdx.x;
    if (i >= n4) return;
    const float4 v = ((const float4*)src)[i];
    u32 h01, l01, h23, l23;
    split_pack(v.x, v.y, h01, l01);
    split_pack(v.z, v.w, h23, l23);
    ((uint2*)hi)[i] = make_uint2(h01, h23);
    ((uint2*)lo)[i] = make_uint2(l01, l23);
}

// ---------------------------------------------------------------------------
// three fp32 weight mats -> fp16 planes (grid.y selects src/dst)
// ---------------------------------------------------------------------------
__global__ void cvt3_f16(const float* __restrict__ s0, const float* __restrict__ s1,
                         const float* __restrict__ s2, u16* __restrict__ d0,
                         u16* __restrict__ d1, u16* __restrict__ d2, int n4)
{
    const int i = blockIdx.x * blockDim.x + threadIdx.x;
    if (i >= n4) return;
    const float* src = (blockIdx.y == 0) ? s0 : (blockIdx.y == 1) ? s1 : s2;
    u16* dst         = (blockIdx.y == 0) ? d0 : (blockIdx.y == 1) ? d1 : d2;
    const float4 v = ((const float4*)src)[i];
    ((uint2*)dst)[i] = make_uint2(pack_f16x2(v.x, v.y), pack_f16x2(v.z, v.w));
}

// ---------------------------------------------------------------------------
// Row softmax over fp32 logits (2048 cols), writing PACKED fp16 prob plane.
// ---------------------------------------------------------------------------
__global__ void softmax_f16(const float* __restrict__ S, u16* __restrict__ P)
{
    const long long off = (long long)blockIdx.x * 2048;
    const float* row = S + off;
    const int tid = threadIdx.x;
    __shared__ float red[256];

    float v[8];
    *(float4*)&v[0] = *(const float4*)(row + tid * 8);
    *(float4*)&v[4] = *(const float4*)(row + tid * 8 + 4);

    float mx = -1e30f;
#pragma unroll
    for (int i = 0; i < 8; i++) mx = fmaxf(mx, v[i]);
    red[tid] = mx; __syncthreads();
    for (int s = 128; s > 0; s >>= 1) {
        if (tid < s) red[tid] = fmaxf(red[tid], red[tid + s]);
        __syncthreads();
    }
    mx = red[0]; __syncthreads();

    float sum = 0.0f;
#pragma unroll
    for (int i = 0; i < 8; i++) { v[i] = __expf(v[i] - mx); sum += v[i]; }
    red[tid] = sum; __syncthreads();
    for (int s = 128; s > 0; s >>= 1) {
        if (tid < s) red[tid] += red[tid + s];
        __syncthreads();
    }
    const float inv = 1.0f / red[0];

    u32* pp = (u32*)P + (off >> 1) + tid * 4;
#pragma unroll
    for (int j = 0; j < 4; j++)
        pp[j] = pack_f16x2(v[2*j] * inv, v[2*j+1] * inv);
}

// ---------------------------------------------------------------------------
// Plain fp32 row softmax, in place (pooling weights, 8 rows)
// ---------------------------------------------------------------------------
__global__ void softmax_rows(float* __restrict__ S)
{
    float* row = S + (long long)blockIdx.x * 2048;
    const int tid = threadIdx.x;
    __shared__ float red[256];

    float v[8];
    *(float4*)&v[0] = *(const float4*)(row + tid * 8);
    *(float4*)&v[4] = *(const float4*)(row + tid * 8 + 4);

    float mx = -1e30f;
#pragma unroll
    for (int i = 0; i < 8; i++) mx = fmaxf(mx, v[i]);
    red[tid] = mx; __syncthreads();
    for (int s = 128; s > 0; s >>= 1) {
        if (tid < s) red[tid] = fmaxf(red[tid], red[tid + s]);
        __syncthreads();
    }
    mx = red[0]; __syncthreads();

    float sum = 0.0f;
#pragma unroll
    for (int i = 0; i < 8; i++) { v[i] = __expf(v[i] - mx); sum += v[i]; }
    red[tid] = sum; __syncthreads();
    for (int s = 128; s > 0; s >>= 1) {
        if (tid < s) red[tid] += red[tid + s];
        __syncthreads();
    }
    const float inv = 1.0f / red[0];
#pragma unroll
    for (int i = 0; i < 8; i++) v[i] *= inv;
    *(float4*)(row + tid * 8)     = *(float4*)&v[0];
    *(float4*)(row + tid * 8 + 4) = *(float4*)&v[4];
}

// ---------------------------------------------------------------------------
// h = x + z ; H = LN(h)*g + b  -> fp32 H + split planes (for bf16x3 SK GEMM)
// ---------------------------------------------------------------------------
__global__ void add_ln_split(const float* __restrict__ X, const float* __restrict__ Z,
                             const float* __restrict__ g, const float* __restrict__ b,
                             float* __restrict__ H, u16* __restrict__ hi, u16* __restrict__ lo)
{
    const long long r = blockIdx.x;
    const int tid = threadIdx.x;
    const int c0  = tid * 4;
    const float* xr = X + r * DMODEL;
    const float* zr = Z + r * DMODEL;
    __shared__ float red[256];

    float4 x4 = *(const float4*)(xr + c0);
    float4 z4 = *(const float4*)(zr + c0);
    float h[4] = { x4.x + z4.x, x4.y + z4.y, x4.z + z4.z, x4.w + z4.w };

    float sum = h[0] + h[1] + h[2] + h[3];
    red[tid] = sum; __syncthreads();
    for (int s = 128; s > 0; s >>= 1) {
        if (tid < s) red[tid] += red[tid + s];
        __syncthreads();
    }
    const float mean = red[0] * (1.0f / DMODEL);
    __syncthreads();

    float vs = 0.0f;
#pragma unroll
    for (int i = 0; i < 4; i++) { const float d = h[i] - mean; vs += d * d; }
    red[tid] = vs; __syncthreads();
    for (int s = 128; s > 0; s >>= 1) {
        if (tid < s) red[tid] += red[tid + s];
        __syncthreads();
    }
    const float inv = rsqrtf(red[0] * (1.0f / DMODEL) + LN_EPS);

    float4 o;
    o.x = (h[0] - mean) * inv * g[c0 + 0] + b[c0 + 0];
    o.y = (h[1] - mean) * inv * g[c0 + 1] + b[c0 + 1];
    o.z = (h[2] - mean) * inv * g[c0 + 2] + b[c0 + 2];
    o.w = (h[3] - mean) * inv * g[c0 + 3] + b[c0 + 3];
    *(float4*)(H + r * DMODEL + c0) = o;

    u32 h01, l01, h23, l23;
    split_pack(o.x, o.y, h01, l01);
    split_pack(o.z, o.w, h23, l23);
    const long long pi = (r * DMODEL + c0) >> 1;
    ((u32*)hi)[pi]     = h01;
    ((u32*)hi)[pi + 1] = h23;
    ((u32*)lo)[pi]     = l01;
    ((u32*)lo)[pi + 1] = l23;
}

// ---------------------------------------------------------------------------
// T[r] = sum of 32 soft-key partials (deterministic fixed-order reduce)
// ---------------------------------------------------------------------------
__global__ void skt_reduce(const float* __restrict__ TP, float* __restrict__ T)
{
    const int r = blockIdx.x * 256 + threadIdx.x;
    const float* p = TP + (long long)r * 32;
    float s = 0.0f;
#pragma unroll
    for (int j = 0; j < 32; j++) s += p[j];
    T[r] = s;
}

// ---------------------------------------------------------------------------
// final_out stage 1: partial over 256-row s-chunk
// ---------------------------------------------------------------------------
__global__ void final_partial(const float* __restrict__ H, const float* __restrict__ w,
                              float* __restrict__ OP)
{
    const int b  = blockIdx.y;
    const int zc = blockIdx.z;
    const int o  = blockIdx.x * 256 + threadIdx.x;
    const float* Hp = H + (long long)b * SEQL * DMODEL
                        + (long long)(zc * 256) * DMODEL + o;
    const float* wb = w + (long long)b * SEQL + zc * 256;

    float a0 = 0.0f, a1 = 0.0f, a2 = 0.0f, a3 = 0.0f;
    for (int s = 0; s < 256; s += 4) {
        a0 += wb[s + 0] * Hp[(long long)(s + 0) * DMODEL];
        a1 += wb[s + 1] * Hp[(long long)(s + 1) * DMODEL];
        a2 += wb[s + 2] * Hp[(long long)(s + 2) * DMODEL];
        a3 += wb[s + 3] * Hp[(long long)(s + 3) * DMODEL];
    }
    OP[(long long)(b * 8 + zc) * DMODEL + o] = (a0 + a1) + (a2 + a3);
}

// final_out stage 2
__global__ void final_reduce(const float* __restrict__ OP, float* __restrict__ out)
{
    const int b = blockIdx.y;
    const int o = blockIdx.x * 256 + threadIdx.x;
    float s = 0.0f;
#pragma unroll
    for (int z = 0; z < 8; z++)
        s += OP[(long long)(b * 8 + z) * DMODEL + o];
    out[b * DMODEL + o] = s;
}

// ---------------------------------------------------------------------------
// Launch
// ---------------------------------------------------------------------------
extern "C" void kernel_launch(void* const* d_in, const int* in_sizes, int n_in,
                              void* d_out, int out_size)
{
    const float* inputs  = (const float*)d_in[0];
    const float* embed_w = (const float*)d_in[1];
    const float* embed_b = (const float*)d_in[2];
    const float* wq_w    = (const float*)d_in[3];
    const float* wq_b    = (const float*)d_in[4];
    const float* wk_w    = (const float*)d_in[5];
    const float* wk_b    = (const float*)d_in[6];
    const float* wv_w    = (const float*)d_in[7];
    const float* wv_b    = (const float*)d_in[8];
    const float* ln_g    = (const float*)d_in[9];
    const float* ln_b    = (const float*)d_in[10];
    const float* skw     = (const float*)d_in[11];
    const float* sq      = (const float*)d_in[12];
    const float* pos     = (const float*)d_in[13];
    float* out = (float*)d_out;

    cudaFuncSetAttribute((const void*)bf16x3_gemm<true,  false>,
                         cudaFuncAttributeMaxDynamicSharedMemorySize, DYN_SMEM_G);
    cudaFuncSetAttribute((const void*)bf16x3_gemm<false, true>,
                         cudaFuncAttributeMaxDynamicSharedMemorySize, DYN_SMEM_G);
    cudaFuncSetAttribute((const void*)h16_gemm,
                         cudaFuncAttributeMaxDynamicSharedMemorySize, DYN_SMEM_S);
    cudaFuncSetAttribute((const void*)h16_gemm_qkv,
                         cudaFuncAttributeMaxDynamicSharedMemorySize, DYN_SMEM_S);

    float* base = 0;
    cudaGetSymbolAddress((void**)&base, g_scratch);

    u16* INh  = (u16*)(base + O_INS);   u16* INl  = INh  + C_IN;
    u16* EWh  = (u16*)(base + O_EWS);   u16* EWl  = EWh  + C_EW;
    u16* SKWh = (u16*)(base + O_SKWS);  u16* SKWl = SKWh + C_W;
    u16* WQH  = (u16*)(base + O_WQH);
    u16* WKH  = (u16*)(base + O_WKH);
    u16* WVH  = (u16*)(base + O_WVH);
    float* X  = base + O_X;
    u16* X16  = (u16*)(base + O_X16);
    u16* Q16  = (u16*)(base + O_Q16);
    u16* K16  = (u16*)(base + O_K16);
    u16* VT16 = (u16*)(base + O_VT16);
    float* SC = base + O_SC;
    u16* P16  = (u16*)(base + O_P16);
    float* Z  = base + O_Z;
    float* H  = base + O_H;
    u16* Hh   = (u16*)(base + O_HS);    u16* Hl   = Hh + C_MAT;
    float* TP = base + O_TP;
    float* OP = base + O_OP;
    float* T  = base + O_T;

    // 0) operand prep
    split_fp32<<<(int)(C_IN / 4 / 256), 256>>>(inputs,  INh,  INl,  (int)(C_IN / 4));
    split_fp32<<<(int)(C_EW / 4 / 256), 256>>>(embed_w, EWh,  EWl,  (int)(C_EW / 4));
    split_fp32<<<(int)(C_W  / 4 / 256), 256>>>(skw,     SKWh, SKWl, (int)(C_W / 4));
    cvt3_f16<<<dim3((int)(C_W / 4 / 256), 3), 256>>>(
        wq_w, wk_w, wv_w, WQH, WKH, WVH, (int)(C_W / 4));

    // 1) embed (bf16x3): X = inputs @ embed_w^T + embed_b + pos_enc; also X16
    bf16x3_gemm<true, false><<<dim3(DMODEL / 128, NROW / 128, 1), 256, DYN_SMEM_G>>>(
        INh, INl, EWh, EWl, X, X16, 0, 0, DMODEL, D_IN, embed_b, pos);

    // 2) merged QKV (fp16 m16n8k16 — tf32-equivalent mantissa, half the HMMAs)
    h16_gemm_qkv<<<dim3(DMODEL / 128, NROW / 128, 3), 256, DYN_SMEM_S>>>(
        X16, WQH, WKH, WVH, Q16, K16, VT16, wq_b, wk_b, wv_b);

    // 3) scores = Q @ K^T / 32 (batched, fp16)
    h16_gemm<<<dim3(SEQL / 128, SEQL / 128, BATCH), 256, DYN_SMEM_S>>>(
        Q16, K16, SC, SEQL, DMODEL,
        (long long)SEQL * DMODEL, (long long)SEQL * DMODEL, (long long)SEQL * SEQL,
        1.0f / 32.0f);

    // 4) softmax: fp32 logits -> fp16 prob plane
    softmax_f16<<<NROW, 256>>>(SC, P16);

    // 5) Z = P @ V  (fp16)
    h16_gemm<<<dim3(DMODEL / 128, SEQL / 128, BATCH), 256, DYN_SMEM_S>>>(
        P16, VT16, Z, DMODEL, SEQL,
        (long long)SEQL * SEQL, (long long)DMODEL * SEQL, (long long)SEQL * DMODEL,
        1.0f);

    // 6) H = LN(X + Z)*g + b  (fp32 + split planes for SK)
    add_ln_split<<<NROW, 256>>>(X, Z, ln_g, ln_b, H, Hh, Hl);

    // 7) fused SK GEMM (bf16x3 — unscaled logits need the precision) -> TP
    bf16x3_gemm<false, true><<<dim3(DMODEL / 128, NROW / 128, 1), 256, DYN_SMEM_G>>>(
        Hh, Hl, SKWh, SKWl, 0, 0, TP, sq, DMODEL, DMODEL, 0, 0);

    // 8) T[r] = sum partials; softmax over s per batch
    skt_reduce<<<NROW / 256, 256>>>(TP, T);
    softmax_rows<<<BATCH, 256>>>(T);

    // 9) out[b,o] = sum_s w[b,s] * H[b,s,o]  (two-stage, deterministic)
    final_partial<<<dim3(DMODEL / 256, BATCH, 8), 256>>>(H, T, OP);
    final_reduce<<<dim3(DMODEL / 256, BATCH), 256>>>(OP, out);
}